// round 1
// baseline (speedup 1.0000x reference)
#include <cuda_runtime.h>
#include <math.h>

#define BB 4
#define NQ 1024
#define HW 4096
#define CC 1024
#define HH 8
#define DH 128

// ---------------- scratch (device globals; no allocations allowed) ----------
__device__ float g_q[(size_t)BB * NQ * CC];     //  16.8 MB
__device__ float g_k[(size_t)BB * HW * CC];     //  67.1 MB
__device__ float g_v[(size_t)BB * HW * CC];     //  67.1 MB
__device__ float g_attn[(size_t)BB * NQ * CC];  //  16.8 MB

// ---------------------------------------------------------------------------
// Y[m,n] = sum_k X[m,k] * W[n,k] + bias[n]     (NT gemm, K = N = 1024)
// 128x128 tile, BK=16, 256 threads, 8x8 per thread.
// ---------------------------------------------------------------------------
__global__ __launch_bounds__(256) void sgemm_bias_nt(
    const float* __restrict__ X, const float* __restrict__ W,
    const float* __restrict__ bias, float* __restrict__ Y)
{
    const int K = CC, N = CC;
    __shared__ float As[16][128];
    __shared__ float Bs[16][128];

    const int tid = threadIdx.x;
    const int m0 = blockIdx.y * 128;
    const int n0 = blockIdx.x * 128;
    const int tx = tid & 15, ty = tid >> 4;

    float acc[8][8];
#pragma unroll
    for (int i = 0; i < 8; i++)
#pragma unroll
        for (int j = 0; j < 8; j++) acc[i][j] = 0.f;

    for (int k0 = 0; k0 < K; k0 += 16) {
#pragma unroll
        for (int i = 0; i < 2; i++) {
            int idx = tid + i * 256;         // 0..511
            int row = idx >> 2;              // 0..127
            int c4  = (idx & 3) * 4;         // 0,4,8,12
            float4 va = *(const float4*)(X + (size_t)(m0 + row) * K + k0 + c4);
            As[c4 + 0][row] = va.x; As[c4 + 1][row] = va.y;
            As[c4 + 2][row] = va.z; As[c4 + 3][row] = va.w;
            float4 vb = *(const float4*)(W + (size_t)(n0 + row) * K + k0 + c4);
            Bs[c4 + 0][row] = vb.x; Bs[c4 + 1][row] = vb.y;
            Bs[c4 + 2][row] = vb.z; Bs[c4 + 3][row] = vb.w;
        }
        __syncthreads();

#pragma unroll
        for (int kk = 0; kk < 16; kk++) {
            float4 a0 = *(const float4*)&As[kk][ty * 8];
            float4 a1 = *(const float4*)&As[kk][ty * 8 + 4];
            float4 b0 = *(const float4*)&Bs[kk][tx * 8];
            float4 b1 = *(const float4*)&Bs[kk][tx * 8 + 4];
            float a[8] = {a0.x, a0.y, a0.z, a0.w, a1.x, a1.y, a1.z, a1.w};
            float bv[8] = {b0.x, b0.y, b0.z, b0.w, b1.x, b1.y, b1.z, b1.w};
#pragma unroll
            for (int i = 0; i < 8; i++)
#pragma unroll
                for (int j = 0; j < 8; j++)
                    acc[i][j] += a[i] * bv[j];
        }
        __syncthreads();
    }

#pragma unroll
    for (int i = 0; i < 8; i++) {
        float* yr = Y + (size_t)(m0 + ty * 8 + i) * N + n0 + tx * 8;
        float4 r0, r1;
        r0.x = acc[i][0] + bias[n0 + tx * 8 + 0];
        r0.y = acc[i][1] + bias[n0 + tx * 8 + 1];
        r0.z = acc[i][2] + bias[n0 + tx * 8 + 2];
        r0.w = acc[i][3] + bias[n0 + tx * 8 + 3];
        r1.x = acc[i][4] + bias[n0 + tx * 8 + 4];
        r1.y = acc[i][5] + bias[n0 + tx * 8 + 5];
        r1.z = acc[i][6] + bias[n0 + tx * 8 + 6];
        r1.w = acc[i][7] + bias[n0 + tx * 8 + 7];
        *(float4*)(yr)     = r0;
        *(float4*)(yr + 4) = r1;
    }
}

// ---------------------------------------------------------------------------
// Flash attention, fp32, online softmax.
// Block = (q-tile 64 rows) x (head) x (batch). 256 threads (16x16).
// Thread (ty,tx): S rows ty*4..+3, S cols {tx, tx+16, tx+32, tx+48},
//                 O rows ty*4..+3, O cols tx*8..+7.
// ---------------------------------------------------------------------------
#define SQ 132   // Q/K/V smem row stride (128 + 4 pad)
#define SS 68    // mask/P smem row stride (64 + 4 pad)

__global__ __launch_bounds__(256) void flash_attn(
    const float* __restrict__ Qg, const float* __restrict__ Kg,
    const float* __restrict__ Vg, const float* __restrict__ Mg,
    float* __restrict__ Og)
{
    extern __shared__ float sm[];
    float* Qs = sm;                  // 64*132
    float* Ks = Qs + 64 * SQ;        // 64*132
    float* Vs = Ks + 64 * SQ;        // 64*132
    float* SP = Vs + 64 * SQ;        // 64*68  (mask tile, then P tile)

    const int tid = threadIdx.x;
    const int tx = tid & 15, ty = tid >> 4;
    const int q0 = blockIdx.x * 64;
    const int h  = blockIdx.y;
    const int b  = blockIdx.z;

    const int rm = ty * 4;
    const int cn = tx * 8;
    const float scale = 0.08838834764831845f;  // 1/sqrt(128)

    const float* qsrc = Qg + ((size_t)(b * NQ + q0)) * CC + h * DH;
    const float* kbase = Kg + ((size_t)b * HW) * CC + h * DH;
    const float* vbase = Vg + ((size_t)b * HW) * CC + h * DH;
    const float* mbase = Mg + ((size_t)(b * NQ + q0)) * HW;

    // load Q tile (64 x 128)
#pragma unroll
    for (int i = 0; i < 8; i++) {
        int idx = tid + i * 256;       // 0..2047
        int row = idx >> 5;
        int c4  = (idx & 31) * 4;
        *(float4*)&Qs[row * SQ + c4] =
            *(const float4*)(qsrc + (size_t)row * CC + c4);
    }

    float m_[4], l_[4], o[4][8];
#pragma unroll
    for (int i = 0; i < 4; i++) {
        m_[i] = -1e30f; l_[i] = 0.f;
#pragma unroll
        for (int j = 0; j < 8; j++) o[i][j] = 0.f;
    }

    __syncthreads();

    for (int k0 = 0; k0 < HW; k0 += 64) {
        // ---- load K, V (64x128) and mask (64x64) tiles ----
#pragma unroll
        for (int i = 0; i < 8; i++) {
            int idx = tid + i * 256;
            int row = idx >> 5;
            int c4  = (idx & 31) * 4;
            *(float4*)&Ks[row * SQ + c4] =
                *(const float4*)(kbase + (size_t)(k0 + row) * CC + c4);
            *(float4*)&Vs[row * SQ + c4] =
                *(const float4*)(vbase + (size_t)(k0 + row) * CC + c4);
        }
#pragma unroll
        for (int i = 0; i < 4; i++) {
            int idx = tid + i * 256;    // 0..1023
            int row = idx >> 4;
            int c4  = (idx & 15) * 4;
            *(float4*)&SP[row * SS + c4] =
                *(const float4*)(mbase + (size_t)row * HW + k0 + c4);
        }
        __syncthreads();

        // ---- S = (Q*scale) K^T ----
        float s[4][4];
#pragma unroll
        for (int i = 0; i < 4; i++)
#pragma unroll
            for (int j = 0; j < 4; j++) s[i][j] = 0.f;

#pragma unroll 4
        for (int d = 0; d < DH; d += 4) {
            float4 q4[4], k4[4];
#pragma unroll
            for (int i = 0; i < 4; i++)
                q4[i] = *(const float4*)&Qs[(rm + i) * SQ + d];
#pragma unroll
            for (int j = 0; j < 4; j++)
                k4[j] = *(const float4*)&Ks[(tx + 16 * j) * SQ + d];
#pragma unroll
            for (int i = 0; i < 4; i++)
#pragma unroll
                for (int j = 0; j < 4; j++)
                    s[i][j] += q4[i].x * k4[j].x + q4[i].y * k4[j].y +
                               q4[i].z * k4[j].z + q4[i].w * k4[j].w;
        }

        // ---- mask + scale, rowmax ----
        float mrow[4];
#pragma unroll
        for (int i = 0; i < 4; i++) {
            mrow[i] = m_[i];
#pragma unroll
            for (int j = 0; j < 4; j++) {
                float mk = SP[(rm + i) * SS + tx + 16 * j];
                float sv = (mk >= 0.5f) ? s[i][j] * scale : -1e30f;
                s[i][j] = sv;
                mrow[i] = fmaxf(mrow[i], sv);
            }
        }
#pragma unroll
        for (int i = 0; i < 4; i++) {
#pragma unroll
            for (int off = 8; off; off >>= 1)
                mrow[i] = fmaxf(mrow[i], __shfl_xor_sync(0xffffffffu, mrow[i], off));
        }

        // ---- exp, rowsum, rescale ----
        float alpha[4], rs[4];
#pragma unroll
        for (int i = 0; i < 4; i++) {
            alpha[i] = __expf(m_[i] - mrow[i]);
            m_[i] = mrow[i];
            rs[i] = 0.f;
#pragma unroll
            for (int j = 0; j < 4; j++) {
                float p = __expf(s[i][j] - mrow[i]);
                s[i][j] = p;
                rs[i] += p;
            }
        }
#pragma unroll
        for (int i = 0; i < 4; i++) {
#pragma unroll
            for (int off = 8; off; off >>= 1)
                rs[i] += __shfl_xor_sync(0xffffffffu, rs[i], off);
            l_[i] = l_[i] * alpha[i] + rs[i];
        }
#pragma unroll
        for (int i = 0; i < 4; i++)
#pragma unroll
            for (int j = 0; j < 4; j++)
                SP[(rm + i) * SS + tx + 16 * j] = s[i][j];
#pragma unroll
        for (int i = 0; i < 4; i++)
#pragma unroll
            for (int j = 0; j < 8; j++) o[i][j] *= alpha[i];

        __syncthreads();

        // ---- O += P @ V ----
#pragma unroll 4
        for (int k = 0; k < 64; k += 4) {
            float pk[4][4];
#pragma unroll
            for (int i = 0; i < 4; i++) {
                float4 t = *(const float4*)&SP[(rm + i) * SS + k];
                pk[i][0] = t.x; pk[i][1] = t.y; pk[i][2] = t.z; pk[i][3] = t.w;
            }
#pragma unroll
            for (int kk = 0; kk < 4; kk++) {
                float4 va = *(const float4*)&Vs[(k + kk) * SQ + cn];
                float4 vb = *(const float4*)&Vs[(k + kk) * SQ + cn + 4];
#pragma unroll
                for (int i = 0; i < 4; i++) {
                    float p = pk[i][kk];
                    o[i][0] += p * va.x; o[i][1] += p * va.y;
                    o[i][2] += p * va.z; o[i][3] += p * va.w;
                    o[i][4] += p * vb.x; o[i][5] += p * vb.y;
                    o[i][6] += p * vb.z; o[i][7] += p * vb.w;
                }
            }
        }
        __syncthreads();
    }

    // ---- normalize and write ----
    float* obase = Og + ((size_t)(b * NQ + q0)) * CC + h * DH;
#pragma unroll
    for (int i = 0; i < 4; i++) {
        float inv = 1.0f / l_[i];
        float4 r0, r1;
        r0.x = o[i][0] * inv; r0.y = o[i][1] * inv;
        r0.z = o[i][2] * inv; r0.w = o[i][3] * inv;
        r1.x = o[i][4] * inv; r1.y = o[i][5] * inv;
        r1.z = o[i][6] * inv; r1.w = o[i][7] * inv;
        *(float4*)(obase + (size_t)(rm + i) * CC + cn)     = r0;
        *(float4*)(obase + (size_t)(rm + i) * CC + cn + 4) = r1;
    }
}

// ---------------------------------------------------------------------------
extern "C" void kernel_launch(void* const* d_in, const int* in_sizes, int n_in,
                              void* d_out, int out_size)
{
    const float* query  = (const float*)d_in[0];
    const float* memory = (const float*)d_in[1];
    const float* mask   = (const float*)d_in[2];
    const float* Wq = (const float*)d_in[3];
    const float* bq = (const float*)d_in[4];
    const float* Wk = (const float*)d_in[5];
    const float* bk = (const float*)d_in[6];
    const float* Wv = (const float*)d_in[7];
    const float* bv = (const float*)d_in[8];
    const float* Wo = (const float*)d_in[9];
    const float* bo = (const float*)d_in[10];
    float* out = (float*)d_out;

    float *qp, *kp, *vp, *ap;
    cudaGetSymbolAddress((void**)&qp, g_q);
    cudaGetSymbolAddress((void**)&kp, g_k);
    cudaGetSymbolAddress((void**)&vp, g_v);
    cudaGetSymbolAddress((void**)&ap, g_attn);

    dim3 blk(256);

    // projections
    sgemm_bias_nt<<<dim3(CC / 128, (BB * NQ) / 128), blk>>>(query,  Wq, bq, qp);
    sgemm_bias_nt<<<dim3(CC / 128, (BB * HW) / 128), blk>>>(memory, Wk, bk, kp);
    sgemm_bias_nt<<<dim3(CC / 128, (BB * HW) / 128), blk>>>(memory, Wv, bv, vp);

    // attention
    const int smem_bytes = (3 * 64 * SQ + 64 * SS) * (int)sizeof(float); // 118784
    cudaFuncSetAttribute(flash_attn,
                         cudaFuncAttributeMaxDynamicSharedMemorySize, smem_bytes);
    flash_attn<<<dim3(NQ / 64, HH, BB), blk, smem_bytes>>>(qp, kp, vp, mask, ap);

    // output projection
    sgemm_bias_nt<<<dim3(CC / 128, (BB * NQ) / 128), blk>>>(ap, Wo, bo, out);
}

// round 3
// speedup vs baseline: 1.3332x; 1.3332x over previous
#include <cuda_runtime.h>
#include <cuda_bf16.h>
#include <math.h>
#include <stdint.h>

#define BB 4
#define NQ 1024
#define HW 4096
#define CC 1024
#define HH 8
#define DH 128

// ---------------- scratch (device globals; no allocations allowed) ----------
__device__ float g_q[(size_t)BB * NQ * CC];
__device__ float g_k[(size_t)BB * HW * CC];
__device__ float g_v[(size_t)BB * HW * CC];
__device__ float g_attn[(size_t)BB * NQ * CC];

// ============================ helpers =======================================
__device__ __forceinline__ uint32_t smem_u32(const void* p) {
    uint32_t a;
    asm("{ .reg .u64 t; cvta.to.shared.u64 t, %1; cvt.u32.u64 %0, t; }"
        : "=r"(a) : "l"(p));
    return a;
}

__device__ __forceinline__ void ldx4(uint32_t* r, uint32_t addr) {
    asm volatile("ldmatrix.sync.aligned.m8n8.x4.shared.b16 {%0,%1,%2,%3}, [%4];"
                 : "=r"(r[0]), "=r"(r[1]), "=r"(r[2]), "=r"(r[3]) : "r"(addr));
}

__device__ __forceinline__ void mma_bf16(float* c, const uint32_t* a,
                                         uint32_t b0, uint32_t b1) {
    asm volatile(
        "mma.sync.aligned.m16n8k16.row.col.f32.bf16.bf16.f32 "
        "{%0,%1,%2,%3}, {%4,%5,%6,%7}, {%8,%9}, {%0,%1,%2,%3};"
        : "+f"(c[0]), "+f"(c[1]), "+f"(c[2]), "+f"(c[3])
        : "r"(a[0]), "r"(a[1]), "r"(a[2]), "r"(a[3]), "r"(b0), "r"(b1));
}

// split a float4 into packed bf16 hi (2x uint) and lo (2x uint)
__device__ __forceinline__ void split_pack4(float4 v, uint32_t* hi, uint32_t* lo) {
    float h0 = __bfloat162float(__float2bfloat16_rn(v.x));
    float h1 = __bfloat162float(__float2bfloat16_rn(v.y));
    float h2 = __bfloat162float(__float2bfloat16_rn(v.z));
    float h3 = __bfloat162float(__float2bfloat16_rn(v.w));
    __nv_bfloat162 H0 = __floats2bfloat162_rn(h0, h1);
    __nv_bfloat162 H1 = __floats2bfloat162_rn(h2, h3);
    __nv_bfloat162 L0 = __floats2bfloat162_rn(v.x - h0, v.y - h1);
    __nv_bfloat162 L1 = __floats2bfloat162_rn(v.z - h2, v.w - h3);
    hi[0] = *(uint32_t*)&H0; hi[1] = *(uint32_t*)&H1;
    lo[0] = *(uint32_t*)&L0; lo[1] = *(uint32_t*)&L1;
}

// ============================================================================
// Y[m,n] = sum_k X[m,k]*W[n,k] + bias[n] via mma.sync bf16, 3-pass fp32 emu.
// CTA 128x128, BK=16, 8 warps (4 m x 2 n), warp tile 32x64.
// Smem per stage: Ahi/Alo/Bhi/Blo, each 128 rows x 48B (24 bf16, 16 used).
// ============================================================================
#define AST 48
#define VOFF 6144              // 128*48
#define STAGE 24576            // 4*VOFF
#define NCHUNK (CC / 16)       // 64

__global__ __launch_bounds__(256)
void gemm_bf16x3_nt(const float* __restrict__ X, const float* __restrict__ W,
                    const float* __restrict__ bias, float* __restrict__ Y)
{
    extern __shared__ char sm[];
    const uint32_t sb = smem_u32(sm);

    const int tid  = threadIdx.x;
    const int wid  = tid >> 5;
    const int lane = tid & 31;
    const int wm = wid & 3;        // warp row (x32)
    const int wn = wid >> 2;       // warp col (x64)
    const int m0 = blockIdx.y * 128;
    const int n0 = blockIdx.x * 128;

    // loader coords: row = tid>>1 (0..127), half = tid&1 (8 floats each)
    const int lrow = tid >> 1;
    const int lcol = (tid & 1) * 8;
    const uint32_t st_off = (uint32_t)(lrow * AST + (tid & 1) * 16);

    const float* Ag = X + (size_t)(m0 + lrow) * CC + lcol;
    const float* Bg = W + (size_t)(n0 + lrow) * CC + lcol;

    float acc[2][8][4];
#pragma unroll
    for (int i = 0; i < 2; i++)
#pragma unroll
        for (int j = 0; j < 8; j++)
#pragma unroll
            for (int k = 0; k < 4; k++) acc[i][j][k] = 0.f;

    // fragment smem addresses (lane-dependent, stage-relative)
    const uint32_t a_l = sb + (uint32_t)((wm * 32 + (lane & 15)) * AST + (lane >> 4) * 16);
    const uint32_t b_l = sb + 12288u +
        (uint32_t)((wn * 64 + ((lane >> 4) & 1) * 8 + (lane & 7)) * AST +
                   ((lane >> 3) & 1) * 16);

    // ---- prologue: chunk 0 ----
    float4 a0 = *(const float4*)(Ag);
    float4 a1 = *(const float4*)(Ag + 4);
    float4 b0 = *(const float4*)(Bg);
    float4 b1 = *(const float4*)(Bg + 4);
    {
        uint32_t h[4], l[4];
        split_pack4(a0, h, l); split_pack4(a1, h + 2, l + 2);
        *(uint4*)(sm + st_off)        = *(uint4*)h;
        *(uint4*)(sm + VOFF + st_off) = *(uint4*)l;
        split_pack4(b0, h, l); split_pack4(b1, h + 2, l + 2);
        *(uint4*)(sm + 12288 + st_off) = *(uint4*)h;
        *(uint4*)(sm + 18432 + st_off) = *(uint4*)l;
    }
    __syncthreads();

    for (int s = 0; s < NCHUNK; s++) {
        const uint32_t cbase = (uint32_t)((s & 1) * STAGE);

        // prefetch next chunk (gmem -> regs)
        if (s + 1 < NCHUNK) {
            const float* An = Ag + (s + 1) * 16;
            const float* Bn = Bg + (s + 1) * 16;
            a0 = *(const float4*)(An);
            a1 = *(const float4*)(An + 4);
            b0 = *(const float4*)(Bn);
            b1 = *(const float4*)(Bn + 4);
        }

        // ---- compute chunk s ----
        uint32_t ah[2][4], al[2][4];
#pragma unroll
        for (int mt = 0; mt < 2; mt++) {
            ldx4(ah[mt], a_l + cbase + mt * (16 * AST));
            ldx4(al[mt], a_l + cbase + mt * (16 * AST) + VOFF);
        }
#pragma unroll
        for (int np = 0; np < 4; np++) {
            uint32_t bh[4], bl[4];
            ldx4(bh, b_l + cbase + np * (16 * AST));
            ldx4(bl, b_l + cbase + np * (16 * AST) + VOFF);
#pragma unroll
            for (int mt = 0; mt < 2; mt++) {
                mma_bf16(acc[mt][2 * np + 0], ah[mt], bh[0], bh[1]);
                mma_bf16(acc[mt][2 * np + 1], ah[mt], bh[2], bh[3]);
                mma_bf16(acc[mt][2 * np + 0], ah[mt], bl[0], bl[1]);
                mma_bf16(acc[mt][2 * np + 1], ah[mt], bl[2], bl[3]);
                mma_bf16(acc[mt][2 * np + 0], al[mt], bh[0], bh[1]);
                mma_bf16(acc[mt][2 * np + 1], al[mt], bh[2], bh[3]);
            }
        }

        // ---- store next chunk to other buffer ----
        if (s + 1 < NCHUNK) {
            char* nb = sm + ((s + 1) & 1) * STAGE;
            uint32_t h[4], l[4];
            split_pack4(a0, h, l); split_pack4(a1, h + 2, l + 2);
            *(uint4*)(nb + st_off)        = *(uint4*)h;
            *(uint4*)(nb + VOFF + st_off) = *(uint4*)l;
            split_pack4(b0, h, l); split_pack4(b1, h + 2, l + 2);
            *(uint4*)(nb + 12288 + st_off) = *(uint4*)h;
            *(uint4*)(nb + 18432 + st_off) = *(uint4*)l;
        }
        __syncthreads();
    }

    // ---- epilogue: write accum + bias ----
#pragma unroll
    for (int mt = 0; mt < 2; mt++) {
        const int r0 = m0 + wm * 32 + mt * 16 + (lane >> 2);
#pragma unroll
        for (int nt = 0; nt < 8; nt++) {
            const int c = n0 + wn * 64 + nt * 8 + (lane & 3) * 2;
            float2 bv = *(const float2*)(bias + c);
            float2 o;
            o.x = acc[mt][nt][0] + bv.x;
            o.y = acc[mt][nt][1] + bv.y;
            *(float2*)(Y + (size_t)r0 * CC + c) = o;
            o.x = acc[mt][nt][2] + bv.x;
            o.y = acc[mt][nt][3] + bv.y;
            *(float2*)(Y + (size_t)(r0 + 8) * CC + c) = o;
        }
    }
}

// ---------------------------------------------------------------------------
// Flash attention, fp32, online softmax (unchanged).
// ---------------------------------------------------------------------------
#define SQ 132
#define SS 68

__global__ __launch_bounds__(256) void flash_attn(
    const float* __restrict__ Qg, const float* __restrict__ Kg,
    const float* __restrict__ Vg, const float* __restrict__ Mg,
    float* __restrict__ Og)
{
    extern __shared__ float smf[];
    float* Qs = smf;
    float* Ks = Qs + 64 * SQ;
    float* Vs = Ks + 64 * SQ;
    float* SP = Vs + 64 * SQ;

    const int tid = threadIdx.x;
    const int tx = tid & 15, ty = tid >> 4;
    const int q0 = blockIdx.x * 64;
    const int h  = blockIdx.y;
    const int b  = blockIdx.z;

    const int rm = ty * 4;
    const int cn = tx * 8;
    const float scale = 0.08838834764831845f;

    const float* qsrc  = Qg + ((size_t)(b * NQ + q0)) * CC + h * DH;
    const float* kbase = Kg + ((size_t)b * HW) * CC + h * DH;
    const float* vbase = Vg + ((size_t)b * HW) * CC + h * DH;
    const float* mbase = Mg + ((size_t)(b * NQ + q0)) * HW;

#pragma unroll
    for (int i = 0; i < 8; i++) {
        int idx = tid + i * 256;
        int row = idx >> 5;
        int c4  = (idx & 31) * 4;
        *(float4*)&Qs[row * SQ + c4] = *(const float4*)(qsrc + (size_t)row * CC + c4);
    }

    float m_[4], l_[4], o[4][8];
#pragma unroll
    for (int i = 0; i < 4; i++) {
        m_[i] = -1e30f; l_[i] = 0.f;
#pragma unroll
        for (int j = 0; j < 8; j++) o[i][j] = 0.f;
    }

    __syncthreads();

    for (int k0 = 0; k0 < HW; k0 += 64) {
#pragma unroll
        for (int i = 0; i < 8; i++) {
            int idx = tid + i * 256;
            int row = idx >> 5;
            int c4  = (idx & 31) * 4;
            *(float4*)&Ks[row * SQ + c4] = *(const float4*)(kbase + (size_t)(k0 + row) * CC + c4);
            *(float4*)&Vs[row * SQ + c4] = *(const float4*)(vbase + (size_t)(k0 + row) * CC + c4);
        }
#pragma unroll
        for (int i = 0; i < 4; i++) {
            int idx = tid + i * 256;
            int row = idx >> 4;
            int c4  = (idx & 15) * 4;
            *(float4*)&SP[row * SS + c4] = *(const float4*)(mbase + (size_t)row * HW + k0 + c4);
        }
        __syncthreads();

        float s[4][4];
#pragma unroll
        for (int i = 0; i < 4; i++)
#pragma unroll
            for (int j = 0; j < 4; j++) s[i][j] = 0.f;

#pragma unroll 4
        for (int d = 0; d < DH; d += 4) {
            float4 q4[4], k4[4];
#pragma unroll
            for (int i = 0; i < 4; i++) q4[i] = *(const float4*)&Qs[(rm + i) * SQ + d];
#pragma unroll
            for (int j = 0; j < 4; j++) k4[j] = *(const float4*)&Ks[(tx + 16 * j) * SQ + d];
#pragma unroll
            for (int i = 0; i < 4; i++)
#pragma unroll
                for (int j = 0; j < 4; j++)
                    s[i][j] += q4[i].x * k4[j].x + q4[i].y * k4[j].y +
                               q4[i].z * k4[j].z + q4[i].w * k4[j].w;
        }

        float mrow[4];
#pragma unroll
        for (int i = 0; i < 4; i++) {
            mrow[i] = m_[i];
#pragma unroll
            for (int j = 0; j < 4; j++) {
                float mk = SP[(rm + i) * SS + tx + 16 * j];
                float sv = (mk >= 0.5f) ? s[i][j] * scale : -1e30f;
                s[i][j] = sv;
                mrow[i] = fmaxf(mrow[i], sv);
            }
        }
#pragma unroll
        for (int i = 0; i < 4; i++) {
#pragma unroll
            for (int off = 8; off; off >>= 1)
                mrow[i] = fmaxf(mrow[i], __shfl_xor_sync(0xffffffffu, mrow[i], off));
        }

        float alpha[4], rs[4];
#pragma unroll
        for (int i = 0; i < 4; i++) {
            alpha[i] = __expf(m_[i] - mrow[i]);
            m_[i] = mrow[i];
            rs[i] = 0.f;
#pragma unroll
            for (int j = 0; j < 4; j++) {
                float p = __expf(s[i][j] - mrow[i]);
                s[i][j] = p;
                rs[i] += p;
            }
        }
#pragma unroll
        for (int i = 0; i < 4; i++) {
#pragma unroll
            for (int off = 8; off; off >>= 1)
                rs[i] += __shfl_xor_sync(0xffffffffu, rs[i], off);
            l_[i] = l_[i] * alpha[i] + rs[i];
        }
#pragma unroll
        for (int i = 0; i < 4; i++)
#pragma unroll
            for (int j = 0; j < 4; j++)
                SP[(rm + i) * SS + tx + 16 * j] = s[i][j];
#pragma unroll
        for (int i = 0; i < 4; i++)
#pragma unroll
            for (int j = 0; j < 8; j++) o[i][j] *= alpha[i];

        __syncthreads();

#pragma unroll 4
        for (int k = 0; k < 64; k += 4) {
            float pk[4][4];
#pragma unroll
            for (int i = 0; i < 4; i++) {
                float4 t = *(const float4*)&SP[(rm + i) * SS + k];
                pk[i][0] = t.x; pk[i][1] = t.y; pk[i][2] = t.z; pk[i][3] = t.w;
            }
#pragma unroll
            for (int kk = 0; kk < 4; kk++) {
                float4 va = *(const float4*)&Vs[(k + kk) * SQ + cn];
                float4 vb = *(const float4*)&Vs[(k + kk) * SQ + cn + 4];
#pragma unroll
                for (int i = 0; i < 4; i++) {
                    float p = pk[i][kk];
                    o[i][0] += p * va.x; o[i][1] += p * va.y;
                    o[i][2] += p * va.z; o[i][3] += p * va.w;
                    o[i][4] += p * vb.x; o[i][5] += p * vb.y;
                    o[i][6] += p * vb.z; o[i][7] += p * vb.w;
                }
            }
        }
        __syncthreads();
    }

    float* obase = Og + ((size_t)(b * NQ + q0)) * CC + h * DH;
#pragma unroll
    for (int i = 0; i < 4; i++) {
        float inv = 1.0f / l_[i];
        float4 r0, r1;
        r0.x = o[i][0] * inv; r0.y = o[i][1] * inv;
        r0.z = o[i][2] * inv; r0.w = o[i][3] * inv;
        r1.x = o[i][4] * inv; r1.y = o[i][5] * inv;
        r1.z = o[i][6] * inv; r1.w = o[i][7] * inv;
        *(float4*)(obase + (size_t)(rm + i) * CC + cn)     = r0;
        *(float4*)(obase + (size_t)(rm + i) * CC + cn + 4) = r1;
    }
}

// ---------------------------------------------------------------------------
extern "C" void kernel_launch(void* const* d_in, const int* in_sizes, int n_in,
                              void* d_out, int out_size)
{
    const float* query  = (const float*)d_in[0];
    const float* memory = (const float*)d_in[1];
    const float* mask   = (const float*)d_in[2];
    const float* Wq = (const float*)d_in[3];
    const float* bq = (const float*)d_in[4];
    const float* Wk = (const float*)d_in[5];
    const float* bk = (const float*)d_in[6];
    const float* Wv = (const float*)d_in[7];
    const float* bv = (const float*)d_in[8];
    const float* Wo = (const float*)d_in[9];
    const float* bo = (const float*)d_in[10];
    float* out = (float*)d_out;

    float *qp, *kp, *vp, *ap;
    cudaGetSymbolAddress((void**)&qp, g_q);
    cudaGetSymbolAddress((void**)&kp, g_k);
    cudaGetSymbolAddress((void**)&vp, g_v);
    cudaGetSymbolAddress((void**)&ap, g_attn);

    const int gemm_smem = 2 * STAGE;  // 49152
    cudaFuncSetAttribute(gemm_bf16x3_nt,
                         cudaFuncAttributeMaxDynamicSharedMemorySize, gemm_smem);

    dim3 blk(256);

    gemm_bf16x3_nt<<<dim3(CC / 128, (BB * NQ) / 128), blk, gemm_smem>>>(query,  Wq, bq, qp);
    gemm_bf16x3_nt<<<dim3(CC / 128, (BB * HW) / 128), blk, gemm_smem>>>(memory, Wk, bk, kp);
    gemm_bf16x3_nt<<<dim3(CC / 128, (BB * HW) / 128), blk, gemm_smem>>>(memory, Wv, bv, vp);

    const int smem_bytes = (3 * 64 * SQ + 64 * SS) * (int)sizeof(float);
    cudaFuncSetAttribute(flash_attn,
                         cudaFuncAttributeMaxDynamicSharedMemorySize, smem_bytes);
    flash_attn<<<dim3(NQ / 64, HH, BB), blk, smem_bytes>>>(qp, kp, vp, mask, ap);

    gemm_bf16x3_nt<<<dim3(CC / 128, (BB * NQ) / 128), blk, gemm_smem>>>(ap, Wo, bo, out);
}

// round 4
// speedup vs baseline: 2.4161x; 1.8122x over previous
#include <cuda_runtime.h>
#include <cuda_bf16.h>
#include <math.h>
#include <stdint.h>

#define BB 4
#define NQ 1024
#define HW 4096
#define CC 1024
#define HH 8
#define DH 128

// ---------------- scratch (device globals; no allocations allowed) ----------
__device__ float g_q[(size_t)BB * NQ * CC];
__device__ float g_k[(size_t)BB * HW * CC];
__device__ float g_v[(size_t)BB * HW * CC];
__device__ float g_attn[(size_t)BB * NQ * CC];

// ============================ helpers =======================================
__device__ __forceinline__ uint32_t smem_u32(const void* p) {
    uint32_t a;
    asm("{ .reg .u64 t; cvta.to.shared.u64 t, %1; cvt.u32.u64 %0, t; }"
        : "=r"(a) : "l"(p));
    return a;
}

__device__ __forceinline__ void ldx4(uint32_t* r, uint32_t addr) {
    asm volatile("ldmatrix.sync.aligned.m8n8.x4.shared.b16 {%0,%1,%2,%3}, [%4];"
                 : "=r"(r[0]), "=r"(r[1]), "=r"(r[2]), "=r"(r[3]) : "r"(addr));
}

__device__ __forceinline__ void ldx4t(uint32_t* r, uint32_t addr) {
    asm volatile("ldmatrix.sync.aligned.m8n8.x4.trans.shared.b16 {%0,%1,%2,%3}, [%4];"
                 : "=r"(r[0]), "=r"(r[1]), "=r"(r[2]), "=r"(r[3]) : "r"(addr));
}

__device__ __forceinline__ void mma_bf16(float* c, const uint32_t* a,
                                         uint32_t b0, uint32_t b1) {
    asm volatile(
        "mma.sync.aligned.m16n8k16.row.col.f32.bf16.bf16.f32 "
        "{%0,%1,%2,%3}, {%4,%5,%6,%7}, {%8,%9}, {%0,%1,%2,%3};"
        : "+f"(c[0]), "+f"(c[1]), "+f"(c[2]), "+f"(c[3])
        : "r"(a[0]), "r"(a[1]), "r"(a[2]), "r"(a[3]), "r"(b0), "r"(b1));
}

// split a float4 into packed bf16 hi (2x uint) and lo (2x uint)
__device__ __forceinline__ void split_pack4(float4 v, uint32_t* hi, uint32_t* lo) {
    float h0 = __bfloat162float(__float2bfloat16_rn(v.x));
    float h1 = __bfloat162float(__float2bfloat16_rn(v.y));
    float h2 = __bfloat162float(__float2bfloat16_rn(v.z));
    float h3 = __bfloat162float(__float2bfloat16_rn(v.w));
    __nv_bfloat162 H0 = __floats2bfloat162_rn(h0, h1);
    __nv_bfloat162 H1 = __floats2bfloat162_rn(h2, h3);
    __nv_bfloat162 L0 = __floats2bfloat162_rn(v.x - h0, v.y - h1);
    __nv_bfloat162 L1 = __floats2bfloat162_rn(v.z - h2, v.w - h3);
    hi[0] = *(uint32_t*)&H0; hi[1] = *(uint32_t*)&H1;
    lo[0] = *(uint32_t*)&L0; lo[1] = *(uint32_t*)&L1;
}

__device__ __forceinline__ uint32_t pack_hi(float x, float y) {
    __nv_bfloat162 h = __floats2bfloat162_rn(x, y);
    return *(uint32_t*)&h;
}
__device__ __forceinline__ uint32_t pack_lo(float x, float y) {
    float hx = __bfloat162float(__float2bfloat16_rn(x));
    float hy = __bfloat162float(__float2bfloat16_rn(y));
    __nv_bfloat162 l = __floats2bfloat162_rn(x - hx, y - hy);
    return *(uint32_t*)&l;
}

// ============================================================================
// Projection GEMM (unchanged from R3): Y = X @ W^T + bias, bf16 3-pass.
// ============================================================================
#define AST 48
#define VOFF 6144
#define STAGE 24576
#define NCHUNK (CC / 16)

__global__ __launch_bounds__(256)
void gemm_bf16x3_nt(const float* __restrict__ X, const float* __restrict__ W,
                    const float* __restrict__ bias, float* __restrict__ Y)
{
    extern __shared__ char sm[];
    const uint32_t sb = smem_u32(sm);

    const int tid  = threadIdx.x;
    const int wid  = tid >> 5;
    const int lane = tid & 31;
    const int wm = wid & 3;
    const int wn = wid >> 2;
    const int m0 = blockIdx.y * 128;
    const int n0 = blockIdx.x * 128;

    const int lrow = tid >> 1;
    const uint32_t st_off = (uint32_t)(lrow * AST + (tid & 1) * 16);
    const int lcol = (tid & 1) * 8;

    const float* Ag = X + (size_t)(m0 + lrow) * CC + lcol;
    const float* Bg = W + (size_t)(n0 + lrow) * CC + lcol;

    float acc[2][8][4];
#pragma unroll
    for (int i = 0; i < 2; i++)
#pragma unroll
        for (int j = 0; j < 8; j++)
#pragma unroll
            for (int k = 0; k < 4; k++) acc[i][j][k] = 0.f;

    const uint32_t a_l = sb + (uint32_t)((wm * 32 + (lane & 15)) * AST + (lane >> 4) * 16);
    const uint32_t b_l = sb + 12288u +
        (uint32_t)((wn * 64 + ((lane >> 4) & 1) * 8 + (lane & 7)) * AST +
                   ((lane >> 3) & 1) * 16);

    float4 a0 = *(const float4*)(Ag);
    float4 a1 = *(const float4*)(Ag + 4);
    float4 b0 = *(const float4*)(Bg);
    float4 b1 = *(const float4*)(Bg + 4);
    {
        uint32_t h[4], l[4];
        split_pack4(a0, h, l); split_pack4(a1, h + 2, l + 2);
        *(uint4*)(sm + st_off)        = *(uint4*)h;
        *(uint4*)(sm + VOFF + st_off) = *(uint4*)l;
        split_pack4(b0, h, l); split_pack4(b1, h + 2, l + 2);
        *(uint4*)(sm + 12288 + st_off) = *(uint4*)h;
        *(uint4*)(sm + 18432 + st_off) = *(uint4*)l;
    }
    __syncthreads();

    for (int s = 0; s < NCHUNK; s++) {
        const uint32_t cbase = (uint32_t)((s & 1) * STAGE);

        if (s + 1 < NCHUNK) {
            const float* An = Ag + (s + 1) * 16;
            const float* Bn = Bg + (s + 1) * 16;
            a0 = *(const float4*)(An);
            a1 = *(const float4*)(An + 4);
            b0 = *(const float4*)(Bn);
            b1 = *(const float4*)(Bn + 4);
        }

        uint32_t ah[2][4], al[2][4];
#pragma unroll
        for (int mt = 0; mt < 2; mt++) {
            ldx4(ah[mt], a_l + cbase + mt * (16 * AST));
            ldx4(al[mt], a_l + cbase + mt * (16 * AST) + VOFF);
        }
#pragma unroll
        for (int np = 0; np < 4; np++) {
            uint32_t bh[4], bl[4];
            ldx4(bh, b_l + cbase + np * (16 * AST));
            ldx4(bl, b_l + cbase + np * (16 * AST) + VOFF);
#pragma unroll
            for (int mt = 0; mt < 2; mt++) {
                mma_bf16(acc[mt][2 * np + 0], ah[mt], bh[0], bh[1]);
                mma_bf16(acc[mt][2 * np + 1], ah[mt], bh[2], bh[3]);
                mma_bf16(acc[mt][2 * np + 0], ah[mt], bl[0], bl[1]);
                mma_bf16(acc[mt][2 * np + 1], ah[mt], bl[2], bl[3]);
                mma_bf16(acc[mt][2 * np + 0], al[mt], bh[0], bh[1]);
                mma_bf16(acc[mt][2 * np + 1], al[mt], bh[2], bh[3]);
            }
        }

        if (s + 1 < NCHUNK) {
            char* nb = sm + ((s + 1) & 1) * STAGE;
            uint32_t h[4], l[4];
            split_pack4(a0, h, l); split_pack4(a1, h + 2, l + 2);
            *(uint4*)(nb + st_off)        = *(uint4*)h;
            *(uint4*)(nb + VOFF + st_off) = *(uint4*)l;
            split_pack4(b0, h, l); split_pack4(b1, h + 2, l + 2);
            *(uint4*)(nb + 12288 + st_off) = *(uint4*)h;
            *(uint4*)(nb + 18432 + st_off) = *(uint4*)l;
        }
        __syncthreads();
    }

#pragma unroll
    for (int mt = 0; mt < 2; mt++) {
        const int r0 = m0 + wm * 32 + mt * 16 + (lane >> 2);
#pragma unroll
        for (int nt = 0; nt < 8; nt++) {
            const int c = n0 + wn * 64 + nt * 8 + (lane & 3) * 2;
            float2 bv = *(const float2*)(bias + c);
            float2 o;
            o.x = acc[mt][nt][0] + bv.x;
            o.y = acc[mt][nt][1] + bv.y;
            *(float2*)(Y + (size_t)r0 * CC + c) = o;
            o.x = acc[mt][nt][2] + bv.x;
            o.y = acc[mt][nt][3] + bv.y;
            *(float2*)(Y + (size_t)(r0 + 8) * CC + c) = o;
        }
    }
}

// ============================================================================
// Tensor-core flash attention (bf16 3-pass, fp32 softmax in registers).
// Block: q-tile 128 x (head, batch). 8 warps; warp w owns q rows 16w..16w+15.
// KV tile 64. Q kept in smem (hi/lo, pre-scaled). P stays in registers.
// ============================================================================
// smem byte offsets
#define FQH 0
#define FQL 32768
#define FKH 65536
#define FKL 81920
#define FVH 98304
#define FVL 114688
#define FMSK 131072
#define MSKST 68               // mask row stride in floats
#define FLASH_SMEM (131072 + 128 * MSKST * 4)   // 165888

// swizzled byte offset inside a bf16 tile with 256B rows (16 chunks of 16B)
__device__ __forceinline__ uint32_t swz(int row, int chunk) {
    return (uint32_t)(row * 256 + ((chunk ^ (row & 7)) << 4));
}

__global__ __launch_bounds__(256)
void flash_attn_tc(const float* __restrict__ Qg, const float* __restrict__ Kg,
                   const float* __restrict__ Vg, const float* __restrict__ Mg,
                   float* __restrict__ Og)
{
    extern __shared__ char sm[];
    const uint32_t sb = smem_u32(sm);
    float* smf = (float*)sm;

    const int tid  = threadIdx.x;
    const int wid  = tid >> 5;
    const int lane = tid & 31;
    const int q0 = blockIdx.x * 128;
    const int h  = blockIdx.y;
    const int b  = blockIdx.z;

    const float scale = 0.08838834764831845f;  // 1/sqrt(128)

    const float* qsrc  = Qg + ((size_t)(b * NQ + q0)) * CC + h * DH;
    const float* kbase = Kg + ((size_t)b * HW) * CC + h * DH;
    const float* vbase = Vg + ((size_t)b * HW) * CC + h * DH;
    const float* mbase = Mg + ((size_t)(b * NQ + q0)) * HW;

    // ---- load Q (128x128), fold scale, split hi/lo ----
    {
        const int row = tid >> 1;
        const int cb  = (tid & 1) * 8;
#pragma unroll
        for (int c = 0; c < 8; c++) {
            const int ch = cb + c;
            float4 x = *(const float4*)(qsrc + (size_t)row * CC + ch * 8);
            float4 y = *(const float4*)(qsrc + (size_t)row * CC + ch * 8 + 4);
            x.x *= scale; x.y *= scale; x.z *= scale; x.w *= scale;
            y.x *= scale; y.y *= scale; y.z *= scale; y.w *= scale;
            uint32_t hh[4], ll[4];
            split_pack4(x, hh, ll); split_pack4(y, hh + 2, ll + 2);
            *(uint4*)(sm + FQH + swz(row, ch)) = *(uint4*)hh;
            *(uint4*)(sm + FQL + swz(row, ch)) = *(uint4*)ll;
        }
    }

    // per-thread softmax state: rows r0 = 16*wid + (lane>>2), r1 = r0+8
    float m0r = -1e30f, m1r = -1e30f, l0r = 0.f, l1r = 0.f;
    float oc[16][4];
#pragma unroll
    for (int n = 0; n < 16; n++)
#pragma unroll
        for (int j = 0; j < 4; j++) oc[n][j] = 0.f;

    // A-operand (Q) ldmatrix lane geometry
    const int qrow = 16 * wid + (lane & 15);
    const int qc   = lane >> 4;                 // chunk offset 0/1
    // B-operand (K) geometry
    const int krow_in = ((lane >> 4) & 1) * 8 + (lane & 7);
    const int kc      = (lane >> 3) & 1;
    // V trans geometry
    const int vrow_in = (lane & 7) + ((lane >> 3) & 1) * 8;
    const int vc      = lane >> 4;

    // loader coords
    const int kvrow = tid >> 2;          // 0..63
    const int kvcb  = (tid & 3) * 4;     // chunk base
    const int mrow  = tid >> 1;          // 0..127
    const int mcb   = (tid & 1) * 32;    // float col base

    for (int k0 = 0; k0 < HW; k0 += 64) {
        // ---- load K, V (64x128 fp32 -> bf16 hi/lo), mask (128x64 fp32) ----
#pragma unroll
        for (int c = 0; c < 4; c++) {
            const int ch = kvcb + c;
            const float* kp = kbase + (size_t)(k0 + kvrow) * CC + ch * 8;
            float4 x = *(const float4*)(kp);
            float4 y = *(const float4*)(kp + 4);
            uint32_t hh[4], ll[4];
            split_pack4(x, hh, ll); split_pack4(y, hh + 2, ll + 2);
            *(uint4*)(sm + FKH + swz(kvrow, ch)) = *(uint4*)hh;
            *(uint4*)(sm + FKL + swz(kvrow, ch)) = *(uint4*)ll;
            const float* vp = vbase + (size_t)(k0 + kvrow) * CC + ch * 8;
            x = *(const float4*)(vp);
            y = *(const float4*)(vp + 4);
            split_pack4(x, hh, ll); split_pack4(y, hh + 2, ll + 2);
            *(uint4*)(sm + FVH + swz(kvrow, ch)) = *(uint4*)hh;
            *(uint4*)(sm + FVL + swz(kvrow, ch)) = *(uint4*)ll;
        }
#pragma unroll
        for (int j = 0; j < 8; j++) {
            float4 mv = *(const float4*)(mbase + (size_t)mrow * HW + k0 + mcb + j * 4);
            *(float4*)&smf[FMSK / 4 + mrow * MSKST + mcb + j * 4] = mv;
        }
        __syncthreads();

        // ---- S = Q K^T (3-pass bf16), warp tile 16 x 64 ----
        float sc[8][4];
#pragma unroll
        for (int n = 0; n < 8; n++)
#pragma unroll
            for (int j = 0; j < 4; j++) sc[n][j] = 0.f;

#pragma unroll
        for (int kt = 0; kt < 8; kt++) {
            uint32_t qh[4], ql[4];
            const uint32_t qa = sb + swz(qrow, 2 * kt + qc);
            ldx4(qh, FQH ? qa + FQH : qa);   // FQH==0
            ldx4(ql, qa + FQL);
#pragma unroll
            for (int j = 0; j < 4; j++) {
                uint32_t kh[4], kl[4];
                const uint32_t ka = sb + swz(16 * j + krow_in, 2 * kt + kc);
                ldx4(kh, ka + FKH);
                ldx4(kl, ka + FKL);
                mma_bf16(sc[2 * j + 0], qh, kh[0], kh[1]);
                mma_bf16(sc[2 * j + 1], qh, kh[2], kh[3]);
                mma_bf16(sc[2 * j + 0], qh, kl[0], kl[1]);
                mma_bf16(sc[2 * j + 1], qh, kl[2], kl[3]);
                mma_bf16(sc[2 * j + 0], ql, kh[0], kh[1]);
                mma_bf16(sc[2 * j + 1], ql, kh[2], kh[3]);
            }
        }

        // ---- mask + online softmax (in registers) ----
        const int r0l = 16 * wid + (lane >> 2);      // local row 0
        const int mc0 = 2 * (lane & 3);
        float mx0 = m0r, mx1 = m1r;
#pragma unroll
        for (int n = 0; n < 8; n++) {
            const int cw = n * 8 + mc0;
            float2 mk0 = *(const float2*)&smf[FMSK / 4 + r0l * MSKST + cw];
            float2 mk1 = *(const float2*)&smf[FMSK / 4 + (r0l + 8) * MSKST + cw];
            sc[n][0] = (mk0.x >= 0.5f) ? sc[n][0] : -1e30f;
            sc[n][1] = (mk0.y >= 0.5f) ? sc[n][1] : -1e30f;
            sc[n][2] = (mk1.x >= 0.5f) ? sc[n][2] : -1e30f;
            sc[n][3] = (mk1.y >= 0.5f) ? sc[n][3] : -1e30f;
            mx0 = fmaxf(mx0, fmaxf(sc[n][0], sc[n][1]));
            mx1 = fmaxf(mx1, fmaxf(sc[n][2], sc[n][3]));
        }
        mx0 = fmaxf(mx0, __shfl_xor_sync(0xffffffffu, mx0, 1));
        mx0 = fmaxf(mx0, __shfl_xor_sync(0xffffffffu, mx0, 2));
        mx1 = fmaxf(mx1, __shfl_xor_sync(0xffffffffu, mx1, 1));
        mx1 = fmaxf(mx1, __shfl_xor_sync(0xffffffffu, mx1, 2));

        const float alpha0 = __expf(m0r - mx0);
        const float alpha1 = __expf(m1r - mx1);
        m0r = mx0; m1r = mx1;

        float rs0 = 0.f, rs1 = 0.f;
#pragma unroll
        for (int n = 0; n < 8; n++) {
            sc[n][0] = __expf(sc[n][0] - mx0);
            sc[n][1] = __expf(sc[n][1] - mx0);
            sc[n][2] = __expf(sc[n][2] - mx1);
            sc[n][3] = __expf(sc[n][3] - mx1);
            rs0 += sc[n][0] + sc[n][1];
            rs1 += sc[n][2] + sc[n][3];
        }
        rs0 += __shfl_xor_sync(0xffffffffu, rs0, 1);
        rs0 += __shfl_xor_sync(0xffffffffu, rs0, 2);
        rs1 += __shfl_xor_sync(0xffffffffu, rs1, 1);
        rs1 += __shfl_xor_sync(0xffffffffu, rs1, 2);
        l0r = l0r * alpha0 + rs0;
        l1r = l1r * alpha1 + rs1;

        // ---- pack P (hi/lo) into A-fragments; rescale O ----
        uint32_t pah[4][4], pal[4][4];
#pragma unroll
        for (int kt = 0; kt < 4; kt++) {
            pah[kt][0] = pack_hi(sc[2 * kt][0],     sc[2 * kt][1]);
            pah[kt][1] = pack_hi(sc[2 * kt][2],     sc[2 * kt][3]);
            pah[kt][2] = pack_hi(sc[2 * kt + 1][0], sc[2 * kt + 1][1]);
            pah[kt][3] = pack_hi(sc[2 * kt + 1][2], sc[2 * kt + 1][3]);
            pal[kt][0] = pack_lo(sc[2 * kt][0],     sc[2 * kt][1]);
            pal[kt][1] = pack_lo(sc[2 * kt][2],     sc[2 * kt][3]);
            pal[kt][2] = pack_lo(sc[2 * kt + 1][0], sc[2 * kt + 1][1]);
            pal[kt][3] = pack_lo(sc[2 * kt + 1][2], sc[2 * kt + 1][3]);
        }
#pragma unroll
        for (int n = 0; n < 16; n++) {
            oc[n][0] *= alpha0; oc[n][1] *= alpha0;
            oc[n][2] *= alpha1; oc[n][3] *= alpha1;
        }

        // ---- O += P @ V (3-pass), V via ldmatrix.trans ----
#pragma unroll
        for (int kt = 0; kt < 4; kt++) {
#pragma unroll
            for (int np = 0; np < 8; np++) {
                uint32_t vh[4], vl[4];
                const uint32_t va = sb + swz(16 * kt + vrow_in, 2 * np + vc);
                ldx4t(vh, va + FVH);
                ldx4t(vl, va + FVL);
                mma_bf16(oc[2 * np + 0], pah[kt], vh[0], vh[1]);
                mma_bf16(oc[2 * np + 1], pah[kt], vh[2], vh[3]);
                mma_bf16(oc[2 * np + 0], pah[kt], vl[0], vl[1]);
                mma_bf16(oc[2 * np + 1], pah[kt], vl[2], vl[3]);
                mma_bf16(oc[2 * np + 0], pal[kt], vh[0], vh[1]);
                mma_bf16(oc[2 * np + 1], pal[kt], vh[2], vh[3]);
            }
        }
        __syncthreads();
    }

    // ---- normalize and write ----
    const float rl0 = 1.0f / l0r;
    const float rl1 = 1.0f / l1r;
    const int row0 = q0 + 16 * wid + (lane >> 2);
    float* obase = Og + ((size_t)b * NQ) * CC + (size_t)h * DH;
#pragma unroll
    for (int n = 0; n < 16; n++) {
        const int c = n * 8 + 2 * (lane & 3);
        float2 o0, o1;
        o0.x = oc[n][0] * rl0; o0.y = oc[n][1] * rl0;
        o1.x = oc[n][2] * rl1; o1.y = oc[n][3] * rl1;
        *(float2*)(obase + (size_t)row0 * CC + c)       = o0;
        *(float2*)(obase + (size_t)(row0 + 8) * CC + c) = o1;
    }
}

// ---------------------------------------------------------------------------
extern "C" void kernel_launch(void* const* d_in, const int* in_sizes, int n_in,
                              void* d_out, int out_size)
{
    const float* query  = (const float*)d_in[0];
    const float* memory = (const float*)d_in[1];
    const float* mask   = (const float*)d_in[2];
    const float* Wq = (const float*)d_in[3];
    const float* bq = (const float*)d_in[4];
    const float* Wk = (const float*)d_in[5];
    const float* bk = (const float*)d_in[6];
    const float* Wv = (const float*)d_in[7];
    const float* bv = (const float*)d_in[8];
    const float* Wo = (const float*)d_in[9];
    const float* bo = (const float*)d_in[10];
    float* out = (float*)d_out;

    float *qp, *kp, *vp, *ap;
    cudaGetSymbolAddress((void**)&qp, g_q);
    cudaGetSymbolAddress((void**)&kp, g_k);
    cudaGetSymbolAddress((void**)&vp, g_v);
    cudaGetSymbolAddress((void**)&ap, g_attn);

    const int gemm_smem = 2 * STAGE;
    cudaFuncSetAttribute(gemm_bf16x3_nt,
                         cudaFuncAttributeMaxDynamicSharedMemorySize, gemm_smem);

    dim3 blk(256);

    gemm_bf16x3_nt<<<dim3(CC / 128, (BB * NQ) / 128), blk, gemm_smem>>>(query,  Wq, bq, qp);
    gemm_bf16x3_nt<<<dim3(CC / 128, (BB * HW) / 128), blk, gemm_smem>>>(memory, Wk, bk, kp);
    gemm_bf16x3_nt<<<dim3(CC / 128, (BB * HW) / 128), blk, gemm_smem>>>(memory, Wv, bv, vp);

    cudaFuncSetAttribute(flash_attn_tc,
                         cudaFuncAttributeMaxDynamicSharedMemorySize, FLASH_SMEM);
    flash_attn_tc<<<dim3(NQ / 128, HH, BB), blk, FLASH_SMEM>>>(qp, kp, vp, mask, ap);

    gemm_bf16x3_nt<<<dim3(CC / 128, (BB * NQ) / 128), blk, gemm_smem>>>(ap, Wo, bo, out);
}

// round 5
// speedup vs baseline: 2.8405x; 1.1757x over previous
#include <cuda_runtime.h>
#include <cuda_bf16.h>
#include <math.h>
#include <stdint.h>

#define BB 4
#define NQ 1024
#define HW 4096
#define CC 1024
#define HH 8
#define DH 128

typedef __nv_bfloat16 bf16;

// ---------------- scratch (device globals; no allocations allowed) ----------
__device__ bf16 s_qin_h[(size_t)BB * NQ * CC];
__device__ bf16 s_qin_l[(size_t)BB * NQ * CC];
__device__ bf16 s_mem_h[(size_t)BB * HW * CC];
__device__ bf16 s_mem_l[(size_t)BB * HW * CC];
__device__ bf16 s_wq_h[(size_t)CC * CC];
__device__ bf16 s_wq_l[(size_t)CC * CC];
__device__ bf16 s_wk_h[(size_t)CC * CC];
__device__ bf16 s_wk_l[(size_t)CC * CC];
__device__ bf16 s_wv_h[(size_t)CC * CC];
__device__ bf16 s_wv_l[(size_t)CC * CC];
__device__ bf16 s_wo_h[(size_t)CC * CC];
__device__ bf16 s_wo_l[(size_t)CC * CC];
__device__ bf16 s_q_h[(size_t)BB * NQ * CC];   // scaled q projection
__device__ bf16 s_q_l[(size_t)BB * NQ * CC];
__device__ bf16 s_k_h[(size_t)BB * HW * CC];
__device__ bf16 s_k_l[(size_t)BB * HW * CC];
__device__ bf16 s_v_h[(size_t)BB * HW * CC];
__device__ bf16 s_v_l[(size_t)BB * HW * CC];
__device__ bf16 s_a_h[(size_t)BB * NQ * CC];   // attention output
__device__ bf16 s_a_l[(size_t)BB * NQ * CC];

// ============================ helpers =======================================
__device__ __forceinline__ uint32_t smem_u32(const void* p) {
    uint32_t a;
    asm("{ .reg .u64 t; cvta.to.shared.u64 t, %1; cvt.u32.u64 %0, t; }"
        : "=r"(a) : "l"(p));
    return a;
}

__device__ __forceinline__ void ldx4(uint32_t* r, uint32_t addr) {
    asm volatile("ldmatrix.sync.aligned.m8n8.x4.shared.b16 {%0,%1,%2,%3}, [%4];"
                 : "=r"(r[0]), "=r"(r[1]), "=r"(r[2]), "=r"(r[3]) : "r"(addr));
}

__device__ __forceinline__ void ldx4t(uint32_t* r, uint32_t addr) {
    asm volatile("ldmatrix.sync.aligned.m8n8.x4.trans.shared.b16 {%0,%1,%2,%3}, [%4];"
                 : "=r"(r[0]), "=r"(r[1]), "=r"(r[2]), "=r"(r[3]) : "r"(addr));
}

__device__ __forceinline__ void mma_bf16(float* c, const uint32_t* a,
                                         uint32_t b0, uint32_t b1) {
    asm volatile(
        "mma.sync.aligned.m16n8k16.row.col.f32.bf16.bf16.f32 "
        "{%0,%1,%2,%3}, {%4,%5,%6,%7}, {%8,%9}, {%0,%1,%2,%3};"
        : "+f"(c[0]), "+f"(c[1]), "+f"(c[2]), "+f"(c[3])
        : "r"(a[0]), "r"(a[1]), "r"(a[2]), "r"(a[3]), "r"(b0), "r"(b1));
}

__device__ __forceinline__ void cpa16(uint32_t dst, const void* src) {
    asm volatile("cp.async.cg.shared.global [%0], [%1], 16;"
                 :: "r"(dst), "l"(src) : "memory");
}
#define CP_COMMIT() asm volatile("cp.async.commit_group;" ::: "memory")
#define CP_WAIT0()  asm volatile("cp.async.wait_group 0;" ::: "memory")
#define CP_WAIT1()  asm volatile("cp.async.wait_group 1;" ::: "memory")

__device__ __forceinline__ void split_pack4(float4 v, uint32_t* hi, uint32_t* lo) {
    float h0 = __bfloat162float(__float2bfloat16_rn(v.x));
    float h1 = __bfloat162float(__float2bfloat16_rn(v.y));
    float h2 = __bfloat162float(__float2bfloat16_rn(v.z));
    float h3 = __bfloat162float(__float2bfloat16_rn(v.w));
    __nv_bfloat162 H0 = __floats2bfloat162_rn(h0, h1);
    __nv_bfloat162 H1 = __floats2bfloat162_rn(h2, h3);
    __nv_bfloat162 L0 = __floats2bfloat162_rn(v.x - h0, v.y - h1);
    __nv_bfloat162 L1 = __floats2bfloat162_rn(v.z - h2, v.w - h3);
    hi[0] = *(uint32_t*)&H0; hi[1] = *(uint32_t*)&H1;
    lo[0] = *(uint32_t*)&L0; lo[1] = *(uint32_t*)&L1;
}

__device__ __forceinline__ uint32_t pack_hi(float x, float y) {
    __nv_bfloat162 h = __floats2bfloat162_rn(x, y);
    return *(uint32_t*)&h;
}
__device__ __forceinline__ uint32_t pack_lo(float x, float y) {
    float hx = __bfloat162float(__float2bfloat16_rn(x));
    float hy = __bfloat162float(__float2bfloat16_rn(y));
    __nv_bfloat162 l = __floats2bfloat162_rn(x - hx, y - hy);
    return *(uint32_t*)&l;
}

// swizzle for bf16 tiles with 256B rows (128 bf16), 16 chunks of 16B
__device__ __forceinline__ uint32_t swz(int row, int chunk) {
    return (uint32_t)(row * 256 + ((chunk ^ (row & 7)) << 4));
}
// swizzle for bf16 tiles with 128B rows (64 bf16), 8 chunks of 16B
__device__ __forceinline__ uint32_t swz128(int row, int chunk) {
    return (uint32_t)(row * 128 + ((chunk ^ (row & 7)) << 4));
}

// ============================================================================
// split kernel: fp32 -> bf16 hi/lo (grid-stride over float4 units)
// ============================================================================
__global__ __launch_bounds__(256)
void split_f32(const float* __restrict__ x, bf16* __restrict__ hi,
               bf16* __restrict__ lo, int n4)
{
    int i = blockIdx.x * blockDim.x + threadIdx.x;
    if (i < n4) {
        float4 v = ((const float4*)x)[i];
        uint32_t hh[2], ll[2];
        split_pack4(v, hh, ll);
        ((uint2*)hi)[i] = make_uint2(hh[0], hh[1]);
        ((uint2*)lo)[i] = make_uint2(ll[0], ll[1]);
    }
}

// ============================================================================
// GEMM: Y[m,n] = sum_k (Ah+Al)[m,k] * (Bh+Bl)[n,k] + bias[n]   (3-pass bf16)
// CTA 128x128, BK=64, 3-stage cp.async pipeline. 8 warps (4m x 2n).
// Stage layout: Ah(16K) Al(16K) Bh(16K) Bl(16K) = 64KB. Total smem 192KB.
// Epilogue: Yf!=null -> fp32 + bias;  else -> bf16 hi/lo of (acc+bias)*scale.
// ============================================================================
#define GSTG 65536
#define GEMM_SMEM (3 * GSTG)
#define GNS (CC / 64)          // 16 k-stages

__global__ __launch_bounds__(256, 1)
void gemm_pre(const bf16* __restrict__ Ah, const bf16* __restrict__ Al,
              const bf16* __restrict__ Bh, const bf16* __restrict__ Bl,
              const float* __restrict__ bias,
              float* __restrict__ Yf, bf16* __restrict__ Yh,
              bf16* __restrict__ Yl, float scale)
{
    extern __shared__ char sm[];
    const uint32_t sb = smem_u32(sm);

    const int tid  = threadIdx.x;
    const int wid  = tid >> 5;
    const int lane = tid & 31;
    const int wm = wid & 3;
    const int wn = wid >> 2;
    const int m0 = blockIdx.y * 128;
    const int n0 = blockIdx.x * 128;

    // loader: row = tid>>1 (0..127), 4 chunks starting at (tid&1)*4
    const int lrow = tid >> 1;
    const int lcb  = (tid & 1) * 4;

    const bf16* Ahp = Ah + (size_t)(m0 + lrow) * CC;
    const bf16* Alp = Al + (size_t)(m0 + lrow) * CC;
    const bf16* Bhp = Bh + (size_t)(n0 + lrow) * CC;
    const bf16* Blp = Bl + (size_t)(n0 + lrow) * CC;

    float acc[2][8][4];
#pragma unroll
    for (int i = 0; i < 2; i++)
#pragma unroll
        for (int j = 0; j < 8; j++)
#pragma unroll
            for (int k = 0; k < 4; k++) acc[i][j][k] = 0.f;

    const int krow_in = ((lane >> 4) & 1) * 8 + (lane & 7);
    const int kc      = (lane >> 3) & 1;
    const int arow    = wm * 32 + (lane & 15);
    const int ac      = lane >> 4;

    // issue stage s into buffer s%3
    auto issue = [&](int s) {
        const uint32_t stb = sb + (uint32_t)((s % 3) * GSTG);
        const int ko = s * 64;
#pragma unroll
        for (int c = 0; c < 4; c++) {
            const int ch = lcb + c;
            const uint32_t so = swz128(lrow, ch);
            cpa16(stb + so,          Ahp + ko + ch * 8);
            cpa16(stb + 16384 + so,  Alp + ko + ch * 8);
            cpa16(stb + 32768 + so,  Bhp + ko + ch * 8);
            cpa16(stb + 49152 + so,  Blp + ko + ch * 8);
        }
    };

    issue(0); CP_COMMIT();
    issue(1); CP_COMMIT();

    for (int s = 0; s < GNS; s++) {
        CP_WAIT1();
        __syncthreads();
        if (s + 2 < GNS) issue(s + 2);
        CP_COMMIT();

        const uint32_t stb = sb + (uint32_t)((s % 3) * GSTG);
#pragma unroll
        for (int kt = 0; kt < 4; kt++) {
            uint32_t ah_[2][4], al_[2][4];
#pragma unroll
            for (int mt = 0; mt < 2; mt++) {
                const uint32_t aa = stb + swz128(arow + mt * 16, 2 * kt + ac);
                ldx4(ah_[mt], aa);
                ldx4(al_[mt], aa + 16384);
            }
#pragma unroll
            for (int np = 0; np < 4; np++) {
                const uint32_t ba = stb + 32768 +
                    swz128(wn * 64 + np * 16 + krow_in, 2 * kt + kc);
                uint32_t bh_[4], bl_[4];
                ldx4(bh_, ba);
                ldx4(bl_, ba + 16384);
#pragma unroll
                for (int mt = 0; mt < 2; mt++) {
                    mma_bf16(acc[mt][2 * np + 0], ah_[mt], bh_[0], bh_[1]);
                    mma_bf16(acc[mt][2 * np + 1], ah_[mt], bh_[2], bh_[3]);
                    mma_bf16(acc[mt][2 * np + 0], ah_[mt], bl_[0], bl_[1]);
                    mma_bf16(acc[mt][2 * np + 1], ah_[mt], bl_[2], bl_[3]);
                    mma_bf16(acc[mt][2 * np + 0], al_[mt], bh_[0], bh_[1]);
                    mma_bf16(acc[mt][2 * np + 1], al_[mt], bh_[2], bh_[3]);
                }
            }
        }
    }

    // ---- epilogue ----
#pragma unroll
    for (int mt = 0; mt < 2; mt++) {
        const int r0 = m0 + wm * 32 + mt * 16 + (lane >> 2);
#pragma unroll
        for (int nt = 0; nt < 8; nt++) {
            const int c = n0 + wn * 64 + nt * 8 + (lane & 3) * 2;
            float2 bv = *(const float2*)(bias + c);
            float y00 = acc[mt][nt][0] + bv.x;
            float y01 = acc[mt][nt][1] + bv.y;
            float y10 = acc[mt][nt][2] + bv.x;
            float y11 = acc[mt][nt][3] + bv.y;
            if (Yf) {
                *(float2*)(Yf + (size_t)r0 * CC + c)       = make_float2(y00, y01);
                *(float2*)(Yf + (size_t)(r0 + 8) * CC + c) = make_float2(y10, y11);
            } else {
                y00 *= scale; y01 *= scale; y10 *= scale; y11 *= scale;
                *(uint32_t*)(Yh + (size_t)r0 * CC + c)       = pack_hi(y00, y01);
                *(uint32_t*)(Yl + (size_t)r0 * CC + c)       = pack_lo(y00, y01);
                *(uint32_t*)(Yh + (size_t)(r0 + 8) * CC + c) = pack_hi(y10, y11);
                *(uint32_t*)(Yl + (size_t)(r0 + 8) * CC + c) = pack_lo(y10, y11);
            }
        }
    }
}

// ============================================================================
// Flash attention v2: all operands pre-split bf16, cp.async double-buffered,
// Q fragments register-resident. q-tile 128, kv-tile 64, 8 warps.
// Stage: Kh(16K) Kl(16K) Vh(16K) Vl(16K) = 64KB x2; mask 2 x 34816B.
// ============================================================================
#define KVSTG 65536
#define FMSK  131072
#define MSTG  34816
#define FLASH_SMEM (FMSK + 2 * MSTG)    // 200704

__global__ __launch_bounds__(256, 1)
void flash_attn_tc2(const bf16* __restrict__ Qh, const bf16* __restrict__ Ql,
                    const bf16* __restrict__ Kh, const bf16* __restrict__ Kl,
                    const bf16* __restrict__ Vh, const bf16* __restrict__ Vl,
                    const float* __restrict__ Mg,
                    bf16* __restrict__ Oh, bf16* __restrict__ Ol)
{
    extern __shared__ char sm[];
    const uint32_t sb = smem_u32(sm);

    const int tid  = threadIdx.x;
    const int wid  = tid >> 5;
    const int lane = tid & 31;
    const int q0 = blockIdx.x * 128;
    const int h  = blockIdx.y;
    const int b  = blockIdx.z;

    // ---- stage Q (hi/lo) into stage-0 buffer, extract fragments ----
    {
        const int row = tid >> 1;
        const int cb  = (tid & 1) * 8;
        const bf16* qh_src = Qh + (size_t)(b * NQ + q0 + row) * CC + h * DH;
        const bf16* ql_src = Ql + (size_t)(b * NQ + q0 + row) * CC + h * DH;
#pragma unroll
        for (int c = 0; c < 8; c++) {
            const int ch = cb + c;
            cpa16(sb + swz(row, ch),         qh_src + ch * 8);
            cpa16(sb + 32768 + swz(row, ch), ql_src + ch * 8);
        }
        CP_COMMIT();
        CP_WAIT0();
        __syncthreads();
    }

    uint32_t qhf[8][4], qlf[8][4];
    {
        const int qrow = 16 * wid + (lane & 15);
        const int qc   = lane >> 4;
#pragma unroll
        for (int kt = 0; kt < 8; kt++) {
            const uint32_t qa = sb + swz(qrow, 2 * kt + qc);
            ldx4(qhf[kt], qa);
            ldx4(qlf[kt], qa + 32768);
        }
    }
    __syncthreads();

    // fragment geometries
    const int krow_in = ((lane >> 4) & 1) * 8 + (lane & 7);
    const int kc      = (lane >> 3) & 1;
    const int vrow_in = (lane & 7) + ((lane >> 3) & 1) * 8;
    const int vc      = lane >> 4;

    // loader coords
    const int kvrow = tid >> 2;
    const int kvcb  = (tid & 3) * 4;
    const int mrow  = tid >> 1;
    const int mcb   = (tid & 1) * 8;

    const bf16* khb = Kh + (size_t)(b * HW + kvrow) * CC + h * DH;
    const bf16* klb = Kl + (size_t)(b * HW + kvrow) * CC + h * DH;
    const bf16* vhb = Vh + (size_t)(b * HW + kvrow) * CC + h * DH;
    const bf16* vlb = Vl + (size_t)(b * HW + kvrow) * CC + h * DH;
    const float* mb = Mg + (size_t)(b * NQ + q0 + mrow) * HW;

    auto issue = [&](int i) {
        const uint32_t stb = sb + (uint32_t)((i & 1) * KVSTG);
        const size_t koff = (size_t)(i * 64) * CC;
#pragma unroll
        for (int c = 0; c < 4; c++) {
            const int ch = kvcb + c;
            const uint32_t so = swz(kvrow, ch);
            cpa16(stb + so,         khb + koff + ch * 8);
            cpa16(stb + 16384 + so, klb + koff + ch * 8);
            cpa16(stb + 32768 + so, vhb + koff + ch * 8);
            cpa16(stb + 49152 + so, vlb + koff + ch * 8);
        }
        const uint32_t mstb = sb + FMSK + (uint32_t)((i & 1) * MSTG);
#pragma unroll
        for (int j = 0; j < 8; j++) {
            const int ch = mcb + j;
            cpa16(mstb + (uint32_t)(mrow * 272 + ch * 16), mb + i * 64 + ch * 4);
        }
    };

    // softmax state + O accumulators
    float m0r = -1e30f, m1r = -1e30f, l0r = 0.f, l1r = 0.f;
    float oc[16][4];
#pragma unroll
    for (int n = 0; n < 16; n++)
#pragma unroll
        for (int j = 0; j < 4; j++) oc[n][j] = 0.f;

    issue(0); CP_COMMIT();

    const int r0l = 16 * wid + (lane >> 2);
    const int mc0 = 2 * (lane & 3);

    for (int i = 0; i < HW / 64; i++) {
        CP_WAIT0();
        __syncthreads();
        if (i + 1 < HW / 64) issue(i + 1);
        CP_COMMIT();

        const uint32_t stb = sb + (uint32_t)((i & 1) * KVSTG);
        const float* mskf = (const float*)(sm + FMSK + (i & 1) * MSTG);

        // ---- S = Q K^T (3-pass) ----
        float sc[8][4];
#pragma unroll
        for (int n = 0; n < 8; n++)
#pragma unroll
            for (int j = 0; j < 4; j++) sc[n][j] = 0.f;

#pragma unroll
        for (int kt = 0; kt < 8; kt++) {
#pragma unroll
            for (int j = 0; j < 4; j++) {
                uint32_t kh_[4], kl_[4];
                const uint32_t ka = stb + swz(16 * j + krow_in, 2 * kt + kc);
                ldx4(kh_, ka);
                ldx4(kl_, ka + 16384);
                mma_bf16(sc[2 * j + 0], qhf[kt], kh_[0], kh_[1]);
                mma_bf16(sc[2 * j + 1], qhf[kt], kh_[2], kh_[3]);
                mma_bf16(sc[2 * j + 0], qhf[kt], kl_[0], kl_[1]);
                mma_bf16(sc[2 * j + 1], qhf[kt], kl_[2], kl_[3]);
                mma_bf16(sc[2 * j + 0], qlf[kt], kh_[0], kh_[1]);
                mma_bf16(sc[2 * j + 1], qlf[kt], kh_[2], kh_[3]);
            }
        }

        // ---- mask + online softmax ----
        float mx0 = m0r, mx1 = m1r;
#pragma unroll
        for (int n = 0; n < 8; n++) {
            const int cw = n * 8 + mc0;
            float2 mk0 = *(const float2*)&mskf[r0l * 68 + cw];
            float2 mk1 = *(const float2*)&mskf[(r0l + 8) * 68 + cw];
            sc[n][0] = (mk0.x >= 0.5f) ? sc[n][0] : -1e30f;
            sc[n][1] = (mk0.y >= 0.5f) ? sc[n][1] : -1e30f;
            sc[n][2] = (mk1.x >= 0.5f) ? sc[n][2] : -1e30f;
            sc[n][3] = (mk1.y >= 0.5f) ? sc[n][3] : -1e30f;
            mx0 = fmaxf(mx0, fmaxf(sc[n][0], sc[n][1]));
            mx1 = fmaxf(mx1, fmaxf(sc[n][2], sc[n][3]));
        }
        mx0 = fmaxf(mx0, __shfl_xor_sync(0xffffffffu, mx0, 1));
        mx0 = fmaxf(mx0, __shfl_xor_sync(0xffffffffu, mx0, 2));
        mx1 = fmaxf(mx1, __shfl_xor_sync(0xffffffffu, mx1, 1));
        mx1 = fmaxf(mx1, __shfl_xor_sync(0xffffffffu, mx1, 2));

        const float alpha0 = __expf(m0r - mx0);
        const float alpha1 = __expf(m1r - mx1);
        m0r = mx0; m1r = mx1;

        float rs0 = 0.f, rs1 = 0.f;
#pragma unroll
        for (int n = 0; n < 8; n++) {
            sc[n][0] = __expf(sc[n][0] - mx0);
            sc[n][1] = __expf(sc[n][1] - mx0);
            sc[n][2] = __expf(sc[n][2] - mx1);
            sc[n][3] = __expf(sc[n][3] - mx1);
            rs0 += sc[n][0] + sc[n][1];
            rs1 += sc[n][2] + sc[n][3];
        }
        rs0 += __shfl_xor_sync(0xffffffffu, rs0, 1);
        rs0 += __shfl_xor_sync(0xffffffffu, rs0, 2);
        rs1 += __shfl_xor_sync(0xffffffffu, rs1, 1);
        rs1 += __shfl_xor_sync(0xffffffffu, rs1, 2);
        l0r = l0r * alpha0 + rs0;
        l1r = l1r * alpha1 + rs1;

        // ---- pack P hi/lo into A-fragments; rescale O ----
        uint32_t pah[4][4], pal[4][4];
#pragma unroll
        for (int kt = 0; kt < 4; kt++) {
            pah[kt][0] = pack_hi(sc[2 * kt][0],     sc[2 * kt][1]);
            pah[kt][1] = pack_hi(sc[2 * kt][2],     sc[2 * kt][3]);
            pah[kt][2] = pack_hi(sc[2 * kt + 1][0], sc[2 * kt + 1][1]);
            pah[kt][3] = pack_hi(sc[2 * kt + 1][2], sc[2 * kt + 1][3]);
            pal[kt][0] = pack_lo(sc[2 * kt][0],     sc[2 * kt][1]);
            pal[kt][1] = pack_lo(sc[2 * kt][2],     sc[2 * kt][3]);
            pal[kt][2] = pack_lo(sc[2 * kt + 1][0], sc[2 * kt + 1][1]);
            pal[kt][3] = pack_lo(sc[2 * kt + 1][2], sc[2 * kt + 1][3]);
        }
#pragma unroll
        for (int n = 0; n < 16; n++) {
            oc[n][0] *= alpha0; oc[n][1] *= alpha0;
            oc[n][2] *= alpha1; oc[n][3] *= alpha1;
        }

        // ---- O += P @ V (3-pass) ----
#pragma unroll
        for (int kt = 0; kt < 4; kt++) {
#pragma unroll
            for (int np = 0; np < 8; np++) {
                uint32_t vh_[4], vl_[4];
                const uint32_t va = stb + swz(16 * kt + vrow_in, 2 * np + vc);
                ldx4t(vh_, va + 32768);
                ldx4t(vl_, va + 49152);
                mma_bf16(oc[2 * np + 0], pah[kt], vh_[0], vh_[1]);
                mma_bf16(oc[2 * np + 1], pah[kt], vh_[2], vh_[3]);
                mma_bf16(oc[2 * np + 0], pah[kt], vl_[0], vl_[1]);
                mma_bf16(oc[2 * np + 1], pah[kt], vl_[2], vl_[3]);
                mma_bf16(oc[2 * np + 0], pal[kt], vh_[0], vh_[1]);
                mma_bf16(oc[2 * np + 1], pal[kt], vh_[2], vh_[3]);
            }
        }
    }

    // ---- normalize, split hi/lo, write ----
    const float rl0 = 1.0f / l0r;
    const float rl1 = 1.0f / l1r;
    const size_t rbase0 = (size_t)(b * NQ + q0 + r0l) * CC + h * DH;
    const size_t rbase1 = rbase0 + (size_t)8 * CC;
#pragma unroll
    for (int n = 0; n < 16; n++) {
        const int c = n * 8 + mc0;
        float y00 = oc[n][0] * rl0, y01 = oc[n][1] * rl0;
        float y10 = oc[n][2] * rl1, y11 = oc[n][3] * rl1;
        *(uint32_t*)(Oh + rbase0 + c) = pack_hi(y00, y01);
        *(uint32_t*)(Ol + rbase0 + c) = pack_lo(y00, y01);
        *(uint32_t*)(Oh + rbase1 + c) = pack_hi(y10, y11);
        *(uint32_t*)(Ol + rbase1 + c) = pack_lo(y10, y11);
    }
}

// ---------------------------------------------------------------------------
extern "C" void kernel_launch(void* const* d_in, const int* in_sizes, int n_in,
                              void* d_out, int out_size)
{
    const float* query  = (const float*)d_in[0];
    const float* memory = (const float*)d_in[1];
    const float* mask   = (const float*)d_in[2];
    const float* Wq = (const float*)d_in[3];
    const float* bq = (const float*)d_in[4];
    const float* Wk = (const float*)d_in[5];
    const float* bk = (const float*)d_in[6];
    const float* Wv = (const float*)d_in[7];
    const float* bv = (const float*)d_in[8];
    const float* Wo = (const float*)d_in[9];
    const float* bo = (const float*)d_in[10];
    float* out = (float*)d_out;

    bf16 *qin_h, *qin_l, *mem_h, *mem_l;
    bf16 *wq_h, *wq_l, *wk_h, *wk_l, *wv_h, *wv_l, *wo_h, *wo_l;
    bf16 *q_h, *q_l, *k_h, *k_l, *v_h, *v_l, *a_h, *a_l;
    cudaGetSymbolAddress((void**)&qin_h, s_qin_h);
    cudaGetSymbolAddress((void**)&qin_l, s_qin_l);
    cudaGetSymbolAddress((void**)&mem_h, s_mem_h);
    cudaGetSymbolAddress((void**)&mem_l, s_mem_l);
    cudaGetSymbolAddress((void**)&wq_h, s_wq_h);
    cudaGetSymbolAddress((void**)&wq_l, s_wq_l);
    cudaGetSymbolAddress((void**)&wk_h, s_wk_h);
    cudaGetSymbolAddress((void**)&wk_l, s_wk_l);
    cudaGetSymbolAddress((void**)&wv_h, s_wv_h);
    cudaGetSymbolAddress((void**)&wv_l, s_wv_l);
    cudaGetSymbolAddress((void**)&wo_h, s_wo_h);
    cudaGetSymbolAddress((void**)&wo_l, s_wo_l);
    cudaGetSymbolAddress((void**)&q_h, s_q_h);
    cudaGetSymbolAddress((void**)&q_l, s_q_l);
    cudaGetSymbolAddress((void**)&k_h, s_k_h);
    cudaGetSymbolAddress((void**)&k_l, s_k_l);
    cudaGetSymbolAddress((void**)&v_h, s_v_h);
    cudaGetSymbolAddress((void**)&v_l, s_v_l);
    cudaGetSymbolAddress((void**)&a_h, s_a_h);
    cudaGetSymbolAddress((void**)&a_l, s_a_l);

    cudaFuncSetAttribute(gemm_pre,
                         cudaFuncAttributeMaxDynamicSharedMemorySize, GEMM_SMEM);
    cudaFuncSetAttribute(flash_attn_tc2,
                         cudaFuncAttributeMaxDynamicSharedMemorySize, FLASH_SMEM);

    dim3 blk(256);
    const float scale = 0.08838834764831845f;   // 1/sqrt(128)

    // ---- splits ----
    {
        int n4 = BB * NQ * CC / 4;
        split_f32<<<(n4 + 255) / 256, blk>>>(query, qin_h, qin_l, n4);
        n4 = BB * HW * CC / 4;
        split_f32<<<(n4 + 255) / 256, blk>>>(memory, mem_h, mem_l, n4);
        n4 = CC * CC / 4;
        split_f32<<<(n4 + 255) / 256, blk>>>(Wq, wq_h, wq_l, n4);
        split_f32<<<(n4 + 255) / 256, blk>>>(Wk, wk_h, wk_l, n4);
        split_f32<<<(n4 + 255) / 256, blk>>>(Wv, wv_h, wv_l, n4);
        split_f32<<<(n4 + 255) / 256, blk>>>(Wo, wo_h, wo_l, n4);
    }

    // ---- projections ----
    gemm_pre<<<dim3(CC / 128, (BB * NQ) / 128), blk, GEMM_SMEM>>>(
        qin_h, qin_l, wq_h, wq_l, bq, nullptr, q_h, q_l, scale);
    gemm_pre<<<dim3(CC / 128, (BB * HW) / 128), blk, GEMM_SMEM>>>(
        mem_h, mem_l, wk_h, wk_l, bk, nullptr, k_h, k_l, 1.0f);
    gemm_pre<<<dim3(CC / 128, (BB * HW) / 128), blk, GEMM_SMEM>>>(
        mem_h, mem_l, wv_h, wv_l, bv, nullptr, v_h, v_l, 1.0f);

    // ---- attention ----
    flash_attn_tc2<<<dim3(NQ / 128, HH, BB), blk, FLASH_SMEM>>>(
        q_h, q_l, k_h, k_l, v_h, v_l, mask, a_h, a_l);

    // ---- output projection ----
    gemm_pre<<<dim3(CC / 128, (BB * NQ) / 128), blk, GEMM_SMEM>>>(
        a_h, a_l, wo_h, wo_l, bo, out, nullptr, nullptr, 1.0f);
}

// round 6
// speedup vs baseline: 3.9079x; 1.3758x over previous
#include <cuda_runtime.h>
#include <cuda_fp16.h>
#include <math.h>
#include <stdint.h>

#define BB 4
#define NQ 1024
#define HW 4096
#define CC 1024
#define HH 8
#define DH 128

typedef __half f16;

// ---------------- scratch (device globals; no allocations allowed) ----------
__device__ f16 s_qin_h[(size_t)BB * NQ * CC];
__device__ f16 s_qin_l[(size_t)BB * NQ * CC];
__device__ f16 s_mem_h[(size_t)BB * HW * CC];
__device__ f16 s_mem_l[(size_t)BB * HW * CC];
__device__ f16 s_wq_h[(size_t)CC * CC];
__device__ f16 s_wk_h[(size_t)CC * CC];
__device__ f16 s_wv_h[(size_t)CC * CC];
__device__ f16 s_wo_h[(size_t)CC * CC];
__device__ f16 s_q_h[(size_t)BB * NQ * CC];   // scaled q projection hi/lo
__device__ f16 s_q_l[(size_t)BB * NQ * CC];
__device__ f16 s_k_h[(size_t)BB * HW * CC];   // k projection (single fp16)
__device__ f16 s_v_h[(size_t)BB * HW * CC];   // v projection (single fp16)
__device__ f16 s_a_h[(size_t)BB * NQ * CC];   // attention output hi/lo
__device__ f16 s_a_l[(size_t)BB * NQ * CC];

// ============================ helpers =======================================
__device__ __forceinline__ uint32_t smem_u32(const void* p) {
    uint32_t a;
    asm("{ .reg .u64 t; cvta.to.shared.u64 t, %1; cvt.u32.u64 %0, t; }"
        : "=r"(a) : "l"(p));
    return a;
}

__device__ __forceinline__ void ldx4(uint32_t* r, uint32_t addr) {
    asm volatile("ldmatrix.sync.aligned.m8n8.x4.shared.b16 {%0,%1,%2,%3}, [%4];"
                 : "=r"(r[0]), "=r"(r[1]), "=r"(r[2]), "=r"(r[3]) : "r"(addr));
}

__device__ __forceinline__ void ldx4t(uint32_t* r, uint32_t addr) {
    asm volatile("ldmatrix.sync.aligned.m8n8.x4.trans.shared.b16 {%0,%1,%2,%3}, [%4];"
                 : "=r"(r[0]), "=r"(r[1]), "=r"(r[2]), "=r"(r[3]) : "r"(addr));
}

__device__ __forceinline__ void mma_f16(float* c, const uint32_t* a,
                                        uint32_t b0, uint32_t b1) {
    asm volatile(
        "mma.sync.aligned.m16n8k16.row.col.f32.f16.f16.f32 "
        "{%0,%1,%2,%3}, {%4,%5,%6,%7}, {%8,%9}, {%0,%1,%2,%3};"
        : "+f"(c[0]), "+f"(c[1]), "+f"(c[2]), "+f"(c[3])
        : "r"(a[0]), "r"(a[1]), "r"(a[2]), "r"(a[3]), "r"(b0), "r"(b1));
}

__device__ __forceinline__ void cpa16(uint32_t dst, const void* src) {
    asm volatile("cp.async.cg.shared.global [%0], [%1], 16;"
                 :: "r"(dst), "l"(src) : "memory");
}
#define CP_COMMIT() asm volatile("cp.async.commit_group;" ::: "memory")
#define CP_WAIT0()  asm volatile("cp.async.wait_group 0;" ::: "memory")
#define CP_WAIT1()  asm volatile("cp.async.wait_group 1;" ::: "memory")

// split float4 into fp16 hi (uint2) and fp16 lo (uint2)
__device__ __forceinline__ void split_pack4h(float4 v, uint32_t* hi, uint32_t* lo) {
    __half2 H0 = __floats2half2_rn(v.x, v.y);
    __half2 H1 = __floats2half2_rn(v.z, v.w);
    float h0 = __half2float(__low2half(H0)),  h1 = __half2float(__high2half(H0));
    float h2 = __half2float(__low2half(H1)),  h3 = __half2float(__high2half(H1));
    __half2 L0 = __floats2half2_rn(v.x - h0, v.y - h1);
    __half2 L1 = __floats2half2_rn(v.z - h2, v.w - h3);
    hi[0] = *(uint32_t*)&H0; hi[1] = *(uint32_t*)&H1;
    lo[0] = *(uint32_t*)&L0; lo[1] = *(uint32_t*)&L1;
}

__device__ __forceinline__ uint32_t packh_hi(float x, float y) {
    __half2 h = __floats2half2_rn(x, y);
    return *(uint32_t*)&h;
}
__device__ __forceinline__ uint32_t packh_lo(float x, float y) {
    float hx = __half2float(__float2half_rn(x));
    float hy = __half2float(__float2half_rn(y));
    __half2 l = __floats2half2_rn(x - hx, y - hy);
    return *(uint32_t*)&l;
}

// swizzles: 256B rows (128 f16) and 128B rows (64 f16)
__device__ __forceinline__ uint32_t swz(int row, int chunk) {
    return (uint32_t)(row * 256 + ((chunk ^ (row & 7)) << 4));
}
__device__ __forceinline__ uint32_t swz128(int row, int chunk) {
    return (uint32_t)(row * 128 + ((chunk ^ (row & 7)) << 4));
}

// ============================================================================
// split kernels
// ============================================================================
__global__ __launch_bounds__(256)
void split2_f16(const float* __restrict__ x, f16* __restrict__ hi,
                f16* __restrict__ lo, int n4)
{
    int i = blockIdx.x * blockDim.x + threadIdx.x;
    if (i < n4) {
        float4 v = ((const float4*)x)[i];
        uint32_t hh[2], ll[2];
        split_pack4h(v, hh, ll);
        ((uint2*)hi)[i] = make_uint2(hh[0], hh[1]);
        ((uint2*)lo)[i] = make_uint2(ll[0], ll[1]);
    }
}

__global__ __launch_bounds__(256)
void round_f16(const float* __restrict__ x, f16* __restrict__ hi, int n4)
{
    int i = blockIdx.x * blockDim.x + threadIdx.x;
    if (i < n4) {
        float4 v = ((const float4*)x)[i];
        __half2 H0 = __floats2half2_rn(v.x, v.y);
        __half2 H1 = __floats2half2_rn(v.z, v.w);
        ((uint2*)hi)[i] = make_uint2(*(uint32_t*)&H0, *(uint32_t*)&H1);
    }
}

// ============================================================================
// GEMM: Y[m,n] = sum_k (Ah+Al)[m,k] * Bh[n,k] + bias[n]   (fp16 2-pass)
// CTA 128x128, BK=64, 3-stage cp.async. 8 warps (4m x 2n).
// Stage: Ah(16K) Al(16K) Bh(16K) = 48KB; 3 stages = 144KB.
// Epilogue: Yf -> fp32+bias;  else -> f16 hi (+lo if Yl) of (acc+bias)*scale.
// ============================================================================
#define GSTG 49152
#define GEMM_SMEM (3 * GSTG)
#define GNS (CC / 64)

__global__ __launch_bounds__(256, 1)
void gemm_pre(const f16* __restrict__ Ah, const f16* __restrict__ Al,
              const f16* __restrict__ Bh, const float* __restrict__ bias,
              float* __restrict__ Yf, f16* __restrict__ Yh,
              f16* __restrict__ Yl, float scale)
{
    extern __shared__ char sm[];
    const uint32_t sb = smem_u32(sm);

    const int tid  = threadIdx.x;
    const int wid  = tid >> 5;
    const int lane = tid & 31;
    const int wm = wid & 3;
    const int wn = wid >> 2;
    const int m0 = blockIdx.y * 128;
    const int n0 = blockIdx.x * 128;

    const int lrow = tid >> 1;
    const int lcb  = (tid & 1) * 4;

    const f16* Ahp = Ah + (size_t)(m0 + lrow) * CC;
    const f16* Alp = Al + (size_t)(m0 + lrow) * CC;
    const f16* Bhp = Bh + (size_t)(n0 + lrow) * CC;

    float acc[2][8][4];
#pragma unroll
    for (int i = 0; i < 2; i++)
#pragma unroll
        for (int j = 0; j < 8; j++)
#pragma unroll
            for (int k = 0; k < 4; k++) acc[i][j][k] = 0.f;

    const int krow_in = ((lane >> 4) & 1) * 8 + (lane & 7);
    const int kc      = (lane >> 3) & 1;
    const int arow    = wm * 32 + (lane & 15);
    const int ac      = lane >> 4;

    auto issue = [&](int s) {
        const uint32_t stb = sb + (uint32_t)((s % 3) * GSTG);
        const int ko = s * 64;
#pragma unroll
        for (int c = 0; c < 4; c++) {
            const int ch = lcb + c;
            const uint32_t so = swz128(lrow, ch);
            cpa16(stb + so,          Ahp + ko + ch * 8);
            cpa16(stb + 16384 + so,  Alp + ko + ch * 8);
            cpa16(stb + 32768 + so,  Bhp + ko + ch * 8);
        }
    };

    issue(0); CP_COMMIT();
    issue(1); CP_COMMIT();

    for (int s = 0; s < GNS; s++) {
        CP_WAIT1();
        __syncthreads();
        if (s + 2 < GNS) issue(s + 2);
        CP_COMMIT();

        const uint32_t stb = sb + (uint32_t)((s % 3) * GSTG);
#pragma unroll
        for (int kt = 0; kt < 4; kt++) {
            uint32_t ah_[2][4], al_[2][4];
#pragma unroll
            for (int mt = 0; mt < 2; mt++) {
                const uint32_t aa = stb + swz128(arow + mt * 16, 2 * kt + ac);
                ldx4(ah_[mt], aa);
                ldx4(al_[mt], aa + 16384);
            }
#pragma unroll
            for (int np = 0; np < 4; np++) {
                const uint32_t ba = stb + 32768 +
                    swz128(wn * 64 + np * 16 + krow_in, 2 * kt + kc);
                uint32_t bh_[4];
                ldx4(bh_, ba);
#pragma unroll
                for (int mt = 0; mt < 2; mt++) {
                    mma_f16(acc[mt][2 * np + 0], ah_[mt], bh_[0], bh_[1]);
                    mma_f16(acc[mt][2 * np + 1], ah_[mt], bh_[2], bh_[3]);
                    mma_f16(acc[mt][2 * np + 0], al_[mt], bh_[0], bh_[1]);
                    mma_f16(acc[mt][2 * np + 1], al_[mt], bh_[2], bh_[3]);
                }
            }
        }
    }

    // ---- epilogue ----
#pragma unroll
    for (int mt = 0; mt < 2; mt++) {
        const int r0 = m0 + wm * 32 + mt * 16 + (lane >> 2);
#pragma unroll
        for (int nt = 0; nt < 8; nt++) {
            const int c = n0 + wn * 64 + nt * 8 + (lane & 3) * 2;
            float2 bv = *(const float2*)(bias + c);
            float y00 = acc[mt][nt][0] + bv.x;
            float y01 = acc[mt][nt][1] + bv.y;
            float y10 = acc[mt][nt][2] + bv.x;
            float y11 = acc[mt][nt][3] + bv.y;
            if (Yf) {
                *(float2*)(Yf + (size_t)r0 * CC + c)       = make_float2(y00, y01);
                *(float2*)(Yf + (size_t)(r0 + 8) * CC + c) = make_float2(y10, y11);
            } else {
                y00 *= scale; y01 *= scale; y10 *= scale; y11 *= scale;
                *(uint32_t*)(Yh + (size_t)r0 * CC + c)       = packh_hi(y00, y01);
                *(uint32_t*)(Yh + (size_t)(r0 + 8) * CC + c) = packh_hi(y10, y11);
                if (Yl) {
                    *(uint32_t*)(Yl + (size_t)r0 * CC + c)       = packh_lo(y00, y01);
                    *(uint32_t*)(Yl + (size_t)(r0 + 8) * CC + c) = packh_lo(y10, y11);
                }
            }
        }
    }
}

// ============================================================================
// Flash attention (fp16 2-pass): Q hi/lo register-resident, K/V single fp16,
// cp.async double-buffered. q-tile 128, kv-tile 64, 8 warps.
// Stage: Kh(16K) Vh(16K) = 32KB x2; mask 2 x 34816B.
// ============================================================================
#define KVSTG 32768
#define FMSK  65536
#define MSTG  34816
#define FLASH_SMEM (FMSK + 2 * MSTG)    // 135168

__global__ __launch_bounds__(256, 1)
void flash_attn_tc3(const f16* __restrict__ Qh, const f16* __restrict__ Ql,
                    const f16* __restrict__ Kh, const f16* __restrict__ Vh,
                    const float* __restrict__ Mg,
                    f16* __restrict__ Oh, f16* __restrict__ Ol)
{
    extern __shared__ char sm[];
    const uint32_t sb = smem_u32(sm);

    const int tid  = threadIdx.x;
    const int wid  = tid >> 5;
    const int lane = tid & 31;
    const int q0 = blockIdx.x * 128;
    const int h  = blockIdx.y;
    const int b  = blockIdx.z;

    // ---- stage Q (hi/lo) into the two KV buffers, extract fragments ----
    {
        const int row = tid >> 1;
        const int cb  = (tid & 1) * 8;
        const f16* qh_src = Qh + (size_t)(b * NQ + q0 + row) * CC + h * DH;
        const f16* ql_src = Ql + (size_t)(b * NQ + q0 + row) * CC + h * DH;
#pragma unroll
        for (int c = 0; c < 8; c++) {
            const int ch = cb + c;
            cpa16(sb + swz(row, ch),         qh_src + ch * 8);
            cpa16(sb + 32768 + swz(row, ch), ql_src + ch * 8);
        }
        CP_COMMIT();
        CP_WAIT0();
        __syncthreads();
    }

    uint32_t qhf[8][4], qlf[8][4];
    {
        const int qrow = 16 * wid + (lane & 15);
        const int qc   = lane >> 4;
#pragma unroll
        for (int kt = 0; kt < 8; kt++) {
            const uint32_t qa = sb + swz(qrow, 2 * kt + qc);
            ldx4(qhf[kt], qa);
            ldx4(qlf[kt], qa + 32768);
        }
    }
    __syncthreads();

    const int krow_in = ((lane >> 4) & 1) * 8 + (lane & 7);
    const int kc      = (lane >> 3) & 1;
    const int vrow_in = (lane & 7) + ((lane >> 3) & 1) * 8;
    const int vc      = lane >> 4;

    const int kvrow = tid >> 2;
    const int kvcb  = (tid & 3) * 4;
    const int mrow  = tid >> 1;
    const int mcb   = (tid & 1) * 8;

    const f16* khb = Kh + (size_t)(b * HW + kvrow) * CC + h * DH;
    const f16* vhb = Vh + (size_t)(b * HW + kvrow) * CC + h * DH;
    const float* mb = Mg + (size_t)(b * NQ + q0 + mrow) * HW;

    auto issue = [&](int i) {
        const uint32_t stb = sb + (uint32_t)((i & 1) * KVSTG);
        const size_t koff = (size_t)(i * 64) * CC;
#pragma unroll
        for (int c = 0; c < 4; c++) {
            const int ch = kvcb + c;
            const uint32_t so = swz(kvrow, ch);
            cpa16(stb + so,         khb + koff + ch * 8);
            cpa16(stb + 16384 + so, vhb + koff + ch * 8);
        }
        const uint32_t mstb = sb + FMSK + (uint32_t)((i & 1) * MSTG);
#pragma unroll
        for (int j = 0; j < 8; j++) {
            const int ch = mcb + j;
            cpa16(mstb + (uint32_t)(mrow * 272 + ch * 16), mb + i * 64 + ch * 4);
        }
    };

    float m0r = -1e30f, m1r = -1e30f, l0r = 0.f, l1r = 0.f;
    float oc[16][4];
#pragma unroll
    for (int n = 0; n < 16; n++)
#pragma unroll
        for (int j = 0; j < 4; j++) oc[n][j] = 0.f;

    issue(0); CP_COMMIT();

    const int r0l = 16 * wid + (lane >> 2);
    const int mc0 = 2 * (lane & 3);

    for (int i = 0; i < HW / 64; i++) {
        CP_WAIT0();
        __syncthreads();
        if (i + 1 < HW / 64) issue(i + 1);
        CP_COMMIT();

        const uint32_t stb = sb + (uint32_t)((i & 1) * KVSTG);
        const float* mskf = (const float*)(sm + FMSK + (i & 1) * MSTG);

        // ---- S = Q K^T (fp16 2-pass) ----
        float sc[8][4];
#pragma unroll
        for (int n = 0; n < 8; n++)
#pragma unroll
            for (int j = 0; j < 4; j++) sc[n][j] = 0.f;

#pragma unroll
        for (int kt = 0; kt < 8; kt++) {
#pragma unroll
            for (int j = 0; j < 4; j++) {
                uint32_t kh_[4];
                const uint32_t ka = stb + swz(16 * j + krow_in, 2 * kt + kc);
                ldx4(kh_, ka);
                mma_f16(sc[2 * j + 0], qhf[kt], kh_[0], kh_[1]);
                mma_f16(sc[2 * j + 1], qhf[kt], kh_[2], kh_[3]);
                mma_f16(sc[2 * j + 0], qlf[kt], kh_[0], kh_[1]);
                mma_f16(sc[2 * j + 1], qlf[kt], kh_[2], kh_[3]);
            }
        }

        // ---- mask + online softmax ----
        float mx0 = m0r, mx1 = m1r;
#pragma unroll
        for (int n = 0; n < 8; n++) {
            const int cw = n * 8 + mc0;
            float2 mk0 = *(const float2*)&mskf[r0l * 68 + cw];
            float2 mk1 = *(const float2*)&mskf[(r0l + 8) * 68 + cw];
            sc[n][0] = (mk0.x >= 0.5f) ? sc[n][0] : -1e30f;
            sc[n][1] = (mk0.y >= 0.5f) ? sc[n][1] : -1e30f;
            sc[n][2] = (mk1.x >= 0.5f) ? sc[n][2] : -1e30f;
            sc[n][3] = (mk1.y >= 0.5f) ? sc[n][3] : -1e30f;
            mx0 = fmaxf(mx0, fmaxf(sc[n][0], sc[n][1]));
            mx1 = fmaxf(mx1, fmaxf(sc[n][2], sc[n][3]));
        }
        mx0 = fmaxf(mx0, __shfl_xor_sync(0xffffffffu, mx0, 1));
        mx0 = fmaxf(mx0, __shfl_xor_sync(0xffffffffu, mx0, 2));
        mx1 = fmaxf(mx1, __shfl_xor_sync(0xffffffffu, mx1, 1));
        mx1 = fmaxf(mx1, __shfl_xor_sync(0xffffffffu, mx1, 2));

        const float alpha0 = __expf(m0r - mx0);
        const float alpha1 = __expf(m1r - mx1);
        m0r = mx0; m1r = mx1;

        float rs0 = 0.f, rs1 = 0.f;
#pragma unroll
        for (int n = 0; n < 8; n++) {
            sc[n][0] = __expf(sc[n][0] - mx0);
            sc[n][1] = __expf(sc[n][1] - mx0);
            sc[n][2] = __expf(sc[n][2] - mx1);
            sc[n][3] = __expf(sc[n][3] - mx1);
            rs0 += sc[n][0] + sc[n][1];
            rs1 += sc[n][2] + sc[n][3];
        }
        rs0 += __shfl_xor_sync(0xffffffffu, rs0, 1);
        rs0 += __shfl_xor_sync(0xffffffffu, rs0, 2);
        rs1 += __shfl_xor_sync(0xffffffffu, rs1, 1);
        rs1 += __shfl_xor_sync(0xffffffffu, rs1, 2);
        l0r = l0r * alpha0 + rs0;
        l1r = l1r * alpha1 + rs1;

        // ---- pack P hi/lo; rescale O ----
        uint32_t pah[4][4], pal[4][4];
#pragma unroll
        for (int kt = 0; kt < 4; kt++) {
            pah[kt][0] = packh_hi(sc[2 * kt][0],     sc[2 * kt][1]);
            pah[kt][1] = packh_hi(sc[2 * kt][2],     sc[2 * kt][3]);
            pah[kt][2] = packh_hi(sc[2 * kt + 1][0], sc[2 * kt + 1][1]);
            pah[kt][3] = packh_hi(sc[2 * kt + 1][2], sc[2 * kt + 1][3]);
            pal[kt][0] = packh_lo(sc[2 * kt][0],     sc[2 * kt][1]);
            pal[kt][1] = packh_lo(sc[2 * kt][2],     sc[2 * kt][3]);
            pal[kt][2] = packh_lo(sc[2 * kt + 1][0], sc[2 * kt + 1][1]);
            pal[kt][3] = packh_lo(sc[2 * kt + 1][2], sc[2 * kt + 1][3]);
        }
#pragma unroll
        for (int n = 0; n < 16; n++) {
            oc[n][0] *= alpha0; oc[n][1] *= alpha0;
            oc[n][2] *= alpha1; oc[n][3] *= alpha1;
        }

        // ---- O += P @ V (fp16 2-pass) ----
#pragma unroll
        for (int kt = 0; kt < 4; kt++) {
#pragma unroll
            for (int np = 0; np < 8; np++) {
                uint32_t vh_[4];
                const uint32_t va = stb + 16384 + swz(16 * kt + vrow_in, 2 * np + vc);
                ldx4t(vh_, va);
                mma_f16(oc[2 * np + 0], pah[kt], vh_[0], vh_[1]);
                mma_f16(oc[2 * np + 1], pah[kt], vh_[2], vh_[3]);
                mma_f16(oc[2 * np + 0], pal[kt], vh_[0], vh_[1]);
                mma_f16(oc[2 * np + 1], pal[kt], vh_[2], vh_[3]);
            }
        }
    }

    // ---- normalize, split hi/lo, write ----
    const float rl0 = 1.0f / l0r;
    const float rl1 = 1.0f / l1r;
    const size_t rbase0 = (size_t)(b * NQ + q0 + r0l) * CC + h * DH;
    const size_t rbase1 = rbase0 + (size_t)8 * CC;
#pragma unroll
    for (int n = 0; n < 16; n++) {
        const int c = n * 8 + mc0;
        float y00 = oc[n][0] * rl0, y01 = oc[n][1] * rl0;
        float y10 = oc[n][2] * rl1, y11 = oc[n][3] * rl1;
        *(uint32_t*)(Oh + rbase0 + c) = packh_hi(y00, y01);
        *(uint32_t*)(Ol + rbase0 + c) = packh_lo(y00, y01);
        *(uint32_t*)(Oh + rbase1 + c) = packh_hi(y10, y11);
        *(uint32_t*)(Ol + rbase1 + c) = packh_lo(y10, y11);
    }
}

// ---------------------------------------------------------------------------
extern "C" void kernel_launch(void* const* d_in, const int* in_sizes, int n_in,
                              void* d_out, int out_size)
{
    const float* query  = (const float*)d_in[0];
    const float* memory = (const float*)d_in[1];
    const float* mask   = (const float*)d_in[2];
    const float* Wq = (const float*)d_in[3];
    const float* bq = (const float*)d_in[4];
    const float* Wk = (const float*)d_in[5];
    const float* bk = (const float*)d_in[6];
    const float* Wv = (const float*)d_in[7];
    const float* bv = (const float*)d_in[8];
    const float* Wo = (const float*)d_in[9];
    const float* bo = (const float*)d_in[10];
    float* out = (float*)d_out;

    f16 *qin_h, *qin_l, *mem_h, *mem_l;
    f16 *wq_h, *wk_h, *wv_h, *wo_h;
    f16 *q_h, *q_l, *k_h, *v_h, *a_h, *a_l;
    cudaGetSymbolAddress((void**)&qin_h, s_qin_h);
    cudaGetSymbolAddress((void**)&qin_l, s_qin_l);
    cudaGetSymbolAddress((void**)&mem_h, s_mem_h);
    cudaGetSymbolAddress((void**)&mem_l, s_mem_l);
    cudaGetSymbolAddress((void**)&wq_h, s_wq_h);
    cudaGetSymbolAddress((void**)&wk_h, s_wk_h);
    cudaGetSymbolAddress((void**)&wv_h, s_wv_h);
    cudaGetSymbolAddress((void**)&wo_h, s_wo_h);
    cudaGetSymbolAddress((void**)&q_h, s_q_h);
    cudaGetSymbolAddress((void**)&q_l, s_q_l);
    cudaGetSymbolAddress((void**)&k_h, s_k_h);
    cudaGetSymbolAddress((void**)&v_h, s_v_h);
    cudaGetSymbolAddress((void**)&a_h, s_a_h);
    cudaGetSymbolAddress((void**)&a_l, s_a_l);

    cudaFuncSetAttribute(gemm_pre,
                         cudaFuncAttributeMaxDynamicSharedMemorySize, GEMM_SMEM);
    cudaFuncSetAttribute(flash_attn_tc3,
                         cudaFuncAttributeMaxDynamicSharedMemorySize, FLASH_SMEM);

    dim3 blk(256);
    const float scale = 0.08838834764831845f;   // 1/sqrt(128)

    // ---- splits ----
    {
        int n4 = BB * NQ * CC / 4;
        split2_f16<<<(n4 + 255) / 256, blk>>>(query, qin_h, qin_l, n4);
        n4 = BB * HW * CC / 4;
        split2_f16<<<(n4 + 255) / 256, blk>>>(memory, mem_h, mem_l, n4);
        n4 = CC * CC / 4;
        round_f16<<<(n4 + 255) / 256, blk>>>(Wq, wq_h, n4);
        round_f16<<<(n4 + 255) / 256, blk>>>(Wk, wk_h, n4);
        round_f16<<<(n4 + 255) / 256, blk>>>(Wv, wv_h, n4);
        round_f16<<<(n4 + 255) / 256, blk>>>(Wo, wo_h, n4);
    }

    // ---- projections ----
    gemm_pre<<<dim3(CC / 128, (BB * NQ) / 128), blk, GEMM_SMEM>>>(
        qin_h, qin_l, wq_h, bq, nullptr, q_h, q_l, scale);
    gemm_pre<<<dim3(CC / 128, (BB * HW) / 128), blk, GEMM_SMEM>>>(
        mem_h, mem_l, wk_h, bk, nullptr, k_h, nullptr, 1.0f);
    gemm_pre<<<dim3(CC / 128, (BB * HW) / 128), blk, GEMM_SMEM>>>(
        mem_h, mem_l, wv_h, bv, nullptr, v_h, nullptr, 1.0f);

    // ---- attention ----
    flash_attn_tc3<<<dim3(NQ / 128, HH, BB), blk, FLASH_SMEM>>>(
        q_h, q_l, k_h, v_h, mask, a_h, a_l);

    // ---- output projection ----
    gemm_pre<<<dim3(CC / 128, (BB * NQ) / 128), blk, GEMM_SMEM>>>(
        a_h, a_l, wo_h, bo, out, nullptr, nullptr, 1.0f);
}

// round 7
// speedup vs baseline: 4.1661x; 1.0661x over previous
#include <cuda_runtime.h>
#include <cuda_fp16.h>
#include <math.h>
#include <stdint.h>

#define BB 4
#define NQ 1024
#define HW 4096
#define CC 1024
#define HH 8
#define DH 128

typedef __half f16;

// ---------------- scratch (device globals; no allocations allowed) ----------
__device__ f16 s_qin_h[(size_t)BB * NQ * CC];
__device__ f16 s_qin_l[(size_t)BB * NQ * CC];
__device__ f16 s_mem_h[(size_t)BB * HW * CC];
__device__ f16 s_mem_l[(size_t)BB * HW * CC];
__device__ f16 s_wq_h[(size_t)CC * CC];
__device__ f16 s_wk_h[(size_t)CC * CC];
__device__ f16 s_wv_h[(size_t)CC * CC];
__device__ f16 s_wo_h[(size_t)CC * CC];
__device__ f16 s_q_h[(size_t)BB * NQ * CC];   // scaled q projection (fp16 hi only)
__device__ f16 s_k_h[(size_t)BB * HW * CC];   // k projection (single fp16)
__device__ f16 s_v_h[(size_t)BB * HW * CC];   // v projection (single fp16)
__device__ f16 s_a_h[(size_t)BB * NQ * CC];   // attention output hi/lo
__device__ f16 s_a_l[(size_t)BB * NQ * CC];

// ============================ helpers =======================================
__device__ __forceinline__ uint32_t smem_u32(const void* p) {
    uint32_t a;
    asm("{ .reg .u64 t; cvta.to.shared.u64 t, %1; cvt.u32.u64 %0, t; }"
        : "=r"(a) : "l"(p));
    return a;
}

__device__ __forceinline__ void ldx4(uint32_t* r, uint32_t addr) {
    asm volatile("ldmatrix.sync.aligned.m8n8.x4.shared.b16 {%0,%1,%2,%3}, [%4];"
                 : "=r"(r[0]), "=r"(r[1]), "=r"(r[2]), "=r"(r[3]) : "r"(addr));
}

__device__ __forceinline__ void ldx4t(uint32_t* r, uint32_t addr) {
    asm volatile("ldmatrix.sync.aligned.m8n8.x4.trans.shared.b16 {%0,%1,%2,%3}, [%4];"
                 : "=r"(r[0]), "=r"(r[1]), "=r"(r[2]), "=r"(r[3]) : "r"(addr));
}

__device__ __forceinline__ void mma_f16(float* c, const uint32_t* a,
                                        uint32_t b0, uint32_t b1) {
    asm volatile(
        "mma.sync.aligned.m16n8k16.row.col.f32.f16.f16.f32 "
        "{%0,%1,%2,%3}, {%4,%5,%6,%7}, {%8,%9}, {%0,%1,%2,%3};"
        : "+f"(c[0]), "+f"(c[1]), "+f"(c[2]), "+f"(c[3])
        : "r"(a[0]), "r"(a[1]), "r"(a[2]), "r"(a[3]), "r"(b0), "r"(b1));
}

__device__ __forceinline__ void cpa16(uint32_t dst, const void* src) {
    asm volatile("cp.async.cg.shared.global [%0], [%1], 16;"
                 :: "r"(dst), "l"(src) : "memory");
}
#define CP_COMMIT() asm volatile("cp.async.commit_group;" ::: "memory")
#define CP_WAIT0()  asm volatile("cp.async.wait_group 0;" ::: "memory")
#define CP_WAIT1()  asm volatile("cp.async.wait_group 1;" ::: "memory")

__device__ __forceinline__ void split_pack4h(float4 v, uint32_t* hi, uint32_t* lo) {
    __half2 H0 = __floats2half2_rn(v.x, v.y);
    __half2 H1 = __floats2half2_rn(v.z, v.w);
    float h0 = __half2float(__low2half(H0)),  h1 = __half2float(__high2half(H0));
    float h2 = __half2float(__low2half(H1)),  h3 = __half2float(__high2half(H1));
    __half2 L0 = __floats2half2_rn(v.x - h0, v.y - h1);
    __half2 L1 = __floats2half2_rn(v.z - h2, v.w - h3);
    hi[0] = *(uint32_t*)&H0; hi[1] = *(uint32_t*)&H1;
    lo[0] = *(uint32_t*)&L0; lo[1] = *(uint32_t*)&L1;
}

__device__ __forceinline__ uint32_t packh_hi(float x, float y) {
    __half2 h = __floats2half2_rn(x, y);
    return *(uint32_t*)&h;
}
__device__ __forceinline__ uint32_t packh_lo(float x, float y) {
    float hx = __half2float(__float2half_rn(x));
    float hy = __half2float(__float2half_rn(y));
    __half2 l = __floats2half2_rn(x - hx, y - hy);
    return *(uint32_t*)&l;
}

__device__ __forceinline__ uint32_t swz(int row, int chunk) {
    return (uint32_t)(row * 256 + ((chunk ^ (row & 7)) << 4));
}
__device__ __forceinline__ uint32_t swz128(int row, int chunk) {
    return (uint32_t)(row * 128 + ((chunk ^ (row & 7)) << 4));
}

// ============================================================================
// split kernels
// ============================================================================
__global__ __launch_bounds__(256)
void split2_f16(const float* __restrict__ x, f16* __restrict__ hi,
                f16* __restrict__ lo, int n4)
{
    int i = blockIdx.x * blockDim.x + threadIdx.x;
    if (i < n4) {
        float4 v = ((const float4*)x)[i];
        uint32_t hh[2], ll[2];
        split_pack4h(v, hh, ll);
        ((uint2*)hi)[i] = make_uint2(hh[0], hh[1]);
        ((uint2*)lo)[i] = make_uint2(ll[0], ll[1]);
    }
}

__global__ __launch_bounds__(256)
void round_f16(const float* __restrict__ x, f16* __restrict__ hi, int n4)
{
    int i = blockIdx.x * blockDim.x + threadIdx.x;
    if (i < n4) {
        float4 v = ((const float4*)x)[i];
        __half2 H0 = __floats2half2_rn(v.x, v.y);
        __half2 H1 = __floats2half2_rn(v.z, v.w);
        ((uint2*)hi)[i] = make_uint2(*(uint32_t*)&H0, *(uint32_t*)&H1);
    }
}

// ============================================================================
// GEMM: Y[m,n] = sum_k (Ah+Al)[m,k] * Bh[n,k] + bias[n]   (fp16 2-pass)
// CTA 128x128, BK=64, 3-stage cp.async. 8 warps (4m x 2n).
// MMA schedule: per np, all-hi over both m-tiles first, then all-lo
// (accumulator reuse distance 4 instead of 2).
// ============================================================================
#define GSTG 49152
#define GEMM_SMEM (3 * GSTG)
#define GNS (CC / 64)

__global__ __launch_bounds__(256, 1)
void gemm_pre(const f16* __restrict__ Ah, const f16* __restrict__ Al,
              const f16* __restrict__ Bh, const float* __restrict__ bias,
              float* __restrict__ Yf, f16* __restrict__ Yh,
              f16* __restrict__ Yl, float scale)
{
    extern __shared__ char sm[];
    const uint32_t sb = smem_u32(sm);

    const int tid  = threadIdx.x;
    const int wid  = tid >> 5;
    const int lane = tid & 31;
    const int wm = wid & 3;
    const int wn = wid >> 2;
    const int m0 = blockIdx.y * 128;
    const int n0 = blockIdx.x * 128;

    const int lrow = tid >> 1;
    const int lcb  = (tid & 1) * 4;

    const f16* Ahp = Ah + (size_t)(m0 + lrow) * CC;
    const f16* Alp = Al + (size_t)(m0 + lrow) * CC;
    const f16* Bhp = Bh + (size_t)(n0 + lrow) * CC;

    float acc[2][8][4];
#pragma unroll
    for (int i = 0; i < 2; i++)
#pragma unroll
        for (int j = 0; j < 8; j++)
#pragma unroll
            for (int k = 0; k < 4; k++) acc[i][j][k] = 0.f;

    const int krow_in = ((lane >> 4) & 1) * 8 + (lane & 7);
    const int kc      = (lane >> 3) & 1;
    const int arow    = wm * 32 + (lane & 15);
    const int ac      = lane >> 4;

    auto issue = [&](int s) {
        const uint32_t stb = sb + (uint32_t)((s % 3) * GSTG);
        const int ko = s * 64;
#pragma unroll
        for (int c = 0; c < 4; c++) {
            const int ch = lcb + c;
            const uint32_t so = swz128(lrow, ch);
            cpa16(stb + so,          Ahp + ko + ch * 8);
            cpa16(stb + 16384 + so,  Alp + ko + ch * 8);
            cpa16(stb + 32768 + so,  Bhp + ko + ch * 8);
        }
    };

    issue(0); CP_COMMIT();
    issue(1); CP_COMMIT();

    for (int s = 0; s < GNS; s++) {
        CP_WAIT1();
        __syncthreads();
        if (s + 2 < GNS) issue(s + 2);
        CP_COMMIT();

        const uint32_t stb = sb + (uint32_t)((s % 3) * GSTG);
#pragma unroll
        for (int kt = 0; kt < 4; kt++) {
            uint32_t ah_[2][4], al_[2][4];
#pragma unroll
            for (int mt = 0; mt < 2; mt++) {
                const uint32_t aa = stb + swz128(arow + mt * 16, 2 * kt + ac);
                ldx4(ah_[mt], aa);
                ldx4(al_[mt], aa + 16384);
            }
#pragma unroll
            for (int np = 0; np < 4; np++) {
                const uint32_t ba = stb + 32768 +
                    swz128(wn * 64 + np * 16 + krow_in, 2 * kt + kc);
                uint32_t bh_[4];
                ldx4(bh_, ba);
                // hi pass: 4 distinct accumulators
#pragma unroll
                for (int mt = 0; mt < 2; mt++) {
                    mma_f16(acc[mt][2 * np + 0], ah_[mt], bh_[0], bh_[1]);
                    mma_f16(acc[mt][2 * np + 1], ah_[mt], bh_[2], bh_[3]);
                }
                // lo pass
#pragma unroll
                for (int mt = 0; mt < 2; mt++) {
                    mma_f16(acc[mt][2 * np + 0], al_[mt], bh_[0], bh_[1]);
                    mma_f16(acc[mt][2 * np + 1], al_[mt], bh_[2], bh_[3]);
                }
            }
        }
    }

    // ---- epilogue ----
#pragma unroll
    for (int mt = 0; mt < 2; mt++) {
        const int r0 = m0 + wm * 32 + mt * 16 + (lane >> 2);
#pragma unroll
        for (int nt = 0; nt < 8; nt++) {
            const int c = n0 + wn * 64 + nt * 8 + (lane & 3) * 2;
            float2 bv = *(const float2*)(bias + c);
            float y00 = acc[mt][nt][0] + bv.x;
            float y01 = acc[mt][nt][1] + bv.y;
            float y10 = acc[mt][nt][2] + bv.x;
            float y11 = acc[mt][nt][3] + bv.y;
            if (Yf) {
                *(float2*)(Yf + (size_t)r0 * CC + c)       = make_float2(y00, y01);
                *(float2*)(Yf + (size_t)(r0 + 8) * CC + c) = make_float2(y10, y11);
            } else {
                y00 *= scale; y01 *= scale; y10 *= scale; y11 *= scale;
                *(uint32_t*)(Yh + (size_t)r0 * CC + c)       = packh_hi(y00, y01);
                *(uint32_t*)(Yh + (size_t)(r0 + 8) * CC + c) = packh_hi(y10, y11);
                if (Yl) {
                    *(uint32_t*)(Yl + (size_t)r0 * CC + c)       = packh_lo(y00, y01);
                    *(uint32_t*)(Yl + (size_t)(r0 + 8) * CC + c) = packh_lo(y10, y11);
                }
            }
        }
    }
}

// ============================================================================
// Flash attention: QK^T single-pass fp16 (Q hi only, register-resident),
// PV 2-pass (P hi/lo in registers), K/V single fp16, cp.async double-buffered.
// q-tile 128, kv-tile 64, 8 warps.
// ============================================================================
#define KVSTG 32768
#define FMSK  65536
#define MSTG  34816
#define FLASH_SMEM (FMSK + 2 * MSTG)    // 135168

__global__ __launch_bounds__(256, 1)
void flash_attn_tc3(const f16* __restrict__ Qh,
                    const f16* __restrict__ Kh, const f16* __restrict__ Vh,
                    const float* __restrict__ Mg,
                    f16* __restrict__ Oh, f16* __restrict__ Ol)
{
    extern __shared__ char sm[];
    const uint32_t sb = smem_u32(sm);

    const int tid  = threadIdx.x;
    const int wid  = tid >> 5;
    const int lane = tid & 31;
    const int q0 = blockIdx.x * 128;
    const int h  = blockIdx.y;
    const int b  = blockIdx.z;

    // ---- stage Q (hi) into buffer 0, extract fragments ----
    {
        const int row = tid >> 1;
        const int cb  = (tid & 1) * 8;
        const f16* qh_src = Qh + (size_t)(b * NQ + q0 + row) * CC + h * DH;
#pragma unroll
        for (int c = 0; c < 8; c++) {
            const int ch = cb + c;
            cpa16(sb + swz(row, ch), qh_src + ch * 8);
        }
        CP_COMMIT();
        CP_WAIT0();
        __syncthreads();
    }

    uint32_t qhf[8][4];
    {
        const int qrow = 16 * wid + (lane & 15);
        const int qc   = lane >> 4;
#pragma unroll
        for (int kt = 0; kt < 8; kt++) {
            ldx4(qhf[kt], sb + swz(qrow, 2 * kt + qc));
        }
    }
    __syncthreads();

    const int krow_in = ((lane >> 4) & 1) * 8 + (lane & 7);
    const int kc      = (lane >> 3) & 1;
    const int vrow_in = (lane & 7) + ((lane >> 3) & 1) * 8;
    const int vc      = lane >> 4;

    const int kvrow = tid >> 2;
    const int kvcb  = (tid & 3) * 4;
    const int mrow  = tid >> 1;
    const int mcb   = (tid & 1) * 8;

    const f16* khb = Kh + (size_t)(b * HW + kvrow) * CC + h * DH;
    const f16* vhb = Vh + (size_t)(b * HW + kvrow) * CC + h * DH;
    const float* mb = Mg + (size_t)(b * NQ + q0 + mrow) * HW;

    auto issue = [&](int i) {
        const uint32_t stb = sb + (uint32_t)((i & 1) * KVSTG);
        const size_t koff = (size_t)(i * 64) * CC;
#pragma unroll
        for (int c = 0; c < 4; c++) {
            const int ch = kvcb + c;
            const uint32_t so = swz(kvrow, ch);
            cpa16(stb + so,         khb + koff + ch * 8);
            cpa16(stb + 16384 + so, vhb + koff + ch * 8);
        }
        const uint32_t mstb = sb + FMSK + (uint32_t)((i & 1) * MSTG);
#pragma unroll
        for (int j = 0; j < 8; j++) {
            const int ch = mcb + j;
            cpa16(mstb + (uint32_t)(mrow * 272 + ch * 16), mb + i * 64 + ch * 4);
        }
    };

    float m0r = -1e30f, m1r = -1e30f, l0r = 0.f, l1r = 0.f;
    float oc[16][4];
#pragma unroll
    for (int n = 0; n < 16; n++)
#pragma unroll
        for (int j = 0; j < 4; j++) oc[n][j] = 0.f;

    issue(0); CP_COMMIT();

    const int r0l = 16 * wid + (lane >> 2);
    const int mc0 = 2 * (lane & 3);

    for (int i = 0; i < HW / 64; i++) {
        CP_WAIT0();
        __syncthreads();
        if (i + 1 < HW / 64) issue(i + 1);
        CP_COMMIT();

        const uint32_t stb = sb + (uint32_t)((i & 1) * KVSTG);
        const float* mskf = (const float*)(sm + FMSK + (i & 1) * MSTG);

        // ---- S = Q K^T (fp16 single pass, reuse distance 8) ----
        float sc[8][4];
#pragma unroll
        for (int n = 0; n < 8; n++)
#pragma unroll
            for (int j = 0; j < 4; j++) sc[n][j] = 0.f;

#pragma unroll
        for (int kt = 0; kt < 8; kt++) {
#pragma unroll
            for (int j = 0; j < 4; j++) {
                uint32_t kh_[4];
                ldx4(kh_, stb + swz(16 * j + krow_in, 2 * kt + kc));
                mma_f16(sc[2 * j + 0], qhf[kt], kh_[0], kh_[1]);
                mma_f16(sc[2 * j + 1], qhf[kt], kh_[2], kh_[3]);
            }
        }

        // ---- mask + online softmax ----
        float mx0 = m0r, mx1 = m1r;
#pragma unroll
        for (int n = 0; n < 8; n++) {
            const int cw = n * 8 + mc0;
            float2 mk0 = *(const float2*)&mskf[r0l * 68 + cw];
            float2 mk1 = *(const float2*)&mskf[(r0l + 8) * 68 + cw];
            sc[n][0] = (mk0.x >= 0.5f) ? sc[n][0] : -1e30f;
            sc[n][1] = (mk0.y >= 0.5f) ? sc[n][1] : -1e30f;
            sc[n][2] = (mk1.x >= 0.5f) ? sc[n][2] : -1e30f;
            sc[n][3] = (mk1.y >= 0.5f) ? sc[n][3] : -1e30f;
            mx0 = fmaxf(mx0, fmaxf(sc[n][0], sc[n][1]));
            mx1 = fmaxf(mx1, fmaxf(sc[n][2], sc[n][3]));
        }
        mx0 = fmaxf(mx0, __shfl_xor_sync(0xffffffffu, mx0, 1));
        mx0 = fmaxf(mx0, __shfl_xor_sync(0xffffffffu, mx0, 2));
        mx1 = fmaxf(mx1, __shfl_xor_sync(0xffffffffu, mx1, 1));
        mx1 = fmaxf(mx1, __shfl_xor_sync(0xffffffffu, mx1, 2));

        const float alpha0 = __expf(m0r - mx0);
        const float alpha1 = __expf(m1r - mx1);
        m0r = mx0; m1r = mx1;

        float rs0 = 0.f, rs1 = 0.f;
#pragma unroll
        for (int n = 0; n < 8; n++) {
            sc[n][0] = __expf(sc[n][0] - mx0);
            sc[n][1] = __expf(sc[n][1] - mx0);
            sc[n][2] = __expf(sc[n][2] - mx1);
            sc[n][3] = __expf(sc[n][3] - mx1);
            rs0 += sc[n][0] + sc[n][1];
            rs1 += sc[n][2] + sc[n][3];
        }
        rs0 += __shfl_xor_sync(0xffffffffu, rs0, 1);
        rs0 += __shfl_xor_sync(0xffffffffu, rs0, 2);
        rs1 += __shfl_xor_sync(0xffffffffu, rs1, 1);
        rs1 += __shfl_xor_sync(0xffffffffu, rs1, 2);
        l0r = l0r * alpha0 + rs0;
        l1r = l1r * alpha1 + rs1;

        // ---- pack P hi/lo; rescale O ----
        uint32_t pah[4][4], pal[4][4];
#pragma unroll
        for (int kt = 0; kt < 4; kt++) {
            pah[kt][0] = packh_hi(sc[2 * kt][0],     sc[2 * kt][1]);
            pah[kt][1] = packh_hi(sc[2 * kt][2],     sc[2 * kt][3]);
            pah[kt][2] = packh_hi(sc[2 * kt + 1][0], sc[2 * kt + 1][1]);
            pah[kt][3] = packh_hi(sc[2 * kt + 1][2], sc[2 * kt + 1][3]);
            pal[kt][0] = packh_lo(sc[2 * kt][0],     sc[2 * kt][1]);
            pal[kt][1] = packh_lo(sc[2 * kt][2],     sc[2 * kt][3]);
            pal[kt][2] = packh_lo(sc[2 * kt + 1][0], sc[2 * kt + 1][1]);
            pal[kt][3] = packh_lo(sc[2 * kt + 1][2], sc[2 * kt + 1][3]);
        }
#pragma unroll
        for (int n = 0; n < 16; n++) {
            oc[n][0] *= alpha0; oc[n][1] *= alpha0;
            oc[n][2] *= alpha1; oc[n][3] *= alpha1;
        }

        // ---- O += P @ V (2-pass, np processed in pairs: reuse distance 4) --
#pragma unroll
        for (int kt = 0; kt < 4; kt++) {
#pragma unroll
            for (int npp = 0; npp < 8; npp += 2) {
                uint32_t v0_[4], v1_[4];
                ldx4t(v0_, stb + 16384 + swz(16 * kt + vrow_in, 2 * npp + vc));
                ldx4t(v1_, stb + 16384 + swz(16 * kt + vrow_in, 2 * npp + 2 + vc));
                mma_f16(oc[2 * npp + 0], pah[kt], v0_[0], v0_[1]);
                mma_f16(oc[2 * npp + 1], pah[kt], v0_[2], v0_[3]);
                mma_f16(oc[2 * npp + 2], pah[kt], v1_[0], v1_[1]);
                mma_f16(oc[2 * npp + 3], pah[kt], v1_[2], v1_[3]);
                mma_f16(oc[2 * npp + 0], pal[kt], v0_[0], v0_[1]);
                mma_f16(oc[2 * npp + 1], pal[kt], v0_[2], v0_[3]);
                mma_f16(oc[2 * npp + 2], pal[kt], v1_[0], v1_[1]);
                mma_f16(oc[2 * npp + 3], pal[kt], v1_[2], v1_[3]);
            }
        }
    }

    // ---- normalize, split hi/lo, write ----
    const float rl0 = 1.0f / l0r;
    const float rl1 = 1.0f / l1r;
    const size_t rbase0 = (size_t)(b * NQ + q0 + r0l) * CC + h * DH;
    const size_t rbase1 = rbase0 + (size_t)8 * CC;
#pragma unroll
    for (int n = 0; n < 16; n++) {
        const int c = n * 8 + mc0;
        float y00 = oc[n][0] * rl0, y01 = oc[n][1] * rl0;
        float y10 = oc[n][2] * rl1, y11 = oc[n][3] * rl1;
        *(uint32_t*)(Oh + rbase0 + c) = packh_hi(y00, y01);
        *(uint32_t*)(Ol + rbase0 + c) = packh_lo(y00, y01);
        *(uint32_t*)(Oh + rbase1 + c) = packh_hi(y10, y11);
        *(uint32_t*)(Ol + rbase1 + c) = packh_lo(y10, y11);
    }
}

// ---------------------------------------------------------------------------
extern "C" void kernel_launch(void* const* d_in, const int* in_sizes, int n_in,
                              void* d_out, int out_size)
{
    const float* query  = (const float*)d_in[0];
    const float* memory = (const float*)d_in[1];
    const float* mask   = (const float*)d_in[2];
    const float* Wq = (const float*)d_in[3];
    const float* bq = (const float*)d_in[4];
    const float* Wk = (const float*)d_in[5];
    const float* bk = (const float*)d_in[6];
    const float* Wv = (const float*)d_in[7];
    const float* bv = (const float*)d_in[8];
    const float* Wo = (const float*)d_in[9];
    const float* bo = (const float*)d_in[10];
    float* out = (float*)d_out;

    f16 *qin_h, *qin_l, *mem_h, *mem_l;
    f16 *wq_h, *wk_h, *wv_h, *wo_h;
    f16 *q_h, *k_h, *v_h, *a_h, *a_l;
    cudaGetSymbolAddress((void**)&qin_h, s_qin_h);
    cudaGetSymbolAddress((void**)&qin_l, s_qin_l);
    cudaGetSymbolAddress((void**)&mem_h, s_mem_h);
    cudaGetSymbolAddress((void**)&mem_l, s_mem_l);
    cudaGetSymbolAddress((void**)&wq_h, s_wq_h);
    cudaGetSymbolAddress((void**)&wk_h, s_wk_h);
    cudaGetSymbolAddress((void**)&wv_h, s_wv_h);
    cudaGetSymbolAddress((void**)&wo_h, s_wo_h);
    cudaGetSymbolAddress((void**)&q_h, s_q_h);
    cudaGetSymbolAddress((void**)&k_h, s_k_h);
    cudaGetSymbolAddress((void**)&v_h, s_v_h);
    cudaGetSymbolAddress((void**)&a_h, s_a_h);
    cudaGetSymbolAddress((void**)&a_l, s_a_l);

    cudaFuncSetAttribute(gemm_pre,
                         cudaFuncAttributeMaxDynamicSharedMemorySize, GEMM_SMEM);
    cudaFuncSetAttribute(flash_attn_tc3,
                         cudaFuncAttributeMaxDynamicSharedMemorySize, FLASH_SMEM);

    dim3 blk(256);
    const float scale = 0.08838834764831845f;   // 1/sqrt(128)

    // ---- splits ----
    {
        int n4 = BB * NQ * CC / 4;
        split2_f16<<<(n4 + 255) / 256, blk>>>(query, qin_h, qin_l, n4);
        n4 = BB * HW * CC / 4;
        split2_f16<<<(n4 + 255) / 256, blk>>>(memory, mem_h, mem_l, n4);
        n4 = CC * CC / 4;
        round_f16<<<(n4 + 255) / 256, blk>>>(Wq, wq_h, n4);
        round_f16<<<(n4 + 255) / 256, blk>>>(Wk, wk_h, n4);
        round_f16<<<(n4 + 255) / 256, blk>>>(Wv, wv_h, n4);
        round_f16<<<(n4 + 255) / 256, blk>>>(Wo, wo_h, n4);
    }

    // ---- projections ----
    gemm_pre<<<dim3(CC / 128, (BB * NQ) / 128), blk, GEMM_SMEM>>>(
        qin_h, qin_l, wq_h, bq, nullptr, q_h, nullptr, scale);
    gemm_pre<<<dim3(CC / 128, (BB * HW) / 128), blk, GEMM_SMEM>>>(
        mem_h, mem_l, wk_h, bk, nullptr, k_h, nullptr, 1.0f);
    gemm_pre<<<dim3(CC / 128, (BB * HW) / 128), blk, GEMM_SMEM>>>(
        mem_h, mem_l, wv_h, bv, nullptr, v_h, nullptr, 1.0f);

    // ---- attention ----
    flash_attn_tc3<<<dim3(NQ / 128, HH, BB), blk, FLASH_SMEM>>>(
        q_h, k_h, v_h, mask, a_h, a_l);

    // ---- output projection ----
    gemm_pre<<<dim3(CC / 128, (BB * NQ) / 128), blk, GEMM_SMEM>>>(
        a_h, a_l, wo_h, bo, out, nullptr, nullptr, 1.0f);
}

// round 8
// speedup vs baseline: 5.8337x; 1.4003x over previous
#include <cuda_runtime.h>
#include <cuda_fp16.h>
#include <math.h>
#include <stdint.h>

#define BB 4
#define NQ 1024
#define HW 4096
#define CC 1024
#define HH 8
#define DH 128

typedef __half f16;

// ---------------- scratch (device globals; no allocations allowed) ----------
__device__ f16 s_qin_h[(size_t)BB * NQ * CC];
__device__ f16 s_mem_h[(size_t)BB * HW * CC];
__device__ f16 s_wq_h[(size_t)CC * CC];
__device__ f16 s_wk_h[(size_t)CC * CC];
__device__ f16 s_wv_h[(size_t)CC * CC];
__device__ f16 s_wo_h[(size_t)CC * CC];
__device__ f16 s_q_h[(size_t)BB * NQ * CC];   // scaled q projection (fp16)
__device__ f16 s_k_h[(size_t)BB * HW * CC];   // k projection (fp16)
__device__ f16 s_v_h[(size_t)BB * HW * CC];   // v projection (fp16)
__device__ f16 s_a_h[(size_t)BB * NQ * CC];   // attention output (fp16)

// ============================ helpers =======================================
__device__ __forceinline__ uint32_t smem_u32(const void* p) {
    uint32_t a;
    asm("{ .reg .u64 t; cvta.to.shared.u64 t, %1; cvt.u32.u64 %0, t; }"
        : "=r"(a) : "l"(p));
    return a;
}

__device__ __forceinline__ void ldx4(uint32_t* r, uint32_t addr) {
    asm volatile("ldmatrix.sync.aligned.m8n8.x4.shared.b16 {%0,%1,%2,%3}, [%4];"
                 : "=r"(r[0]), "=r"(r[1]), "=r"(r[2]), "=r"(r[3]) : "r"(addr));
}

__device__ __forceinline__ void ldx4t(uint32_t* r, uint32_t addr) {
    asm volatile("ldmatrix.sync.aligned.m8n8.x4.trans.shared.b16 {%0,%1,%2,%3}, [%4];"
                 : "=r"(r[0]), "=r"(r[1]), "=r"(r[2]), "=r"(r[3]) : "r"(addr));
}

__device__ __forceinline__ void mma_f16(float* c, const uint32_t* a,
                                        uint32_t b0, uint32_t b1) {
    asm volatile(
        "mma.sync.aligned.m16n8k16.row.col.f32.f16.f16.f32 "
        "{%0,%1,%2,%3}, {%4,%5,%6,%7}, {%8,%9}, {%0,%1,%2,%3};"
        : "+f"(c[0]), "+f"(c[1]), "+f"(c[2]), "+f"(c[3])
        : "r"(a[0]), "r"(a[1]), "r"(a[2]), "r"(a[3]), "r"(b0), "r"(b1));
}

__device__ __forceinline__ void cpa16(uint32_t dst, const void* src) {
    asm volatile("cp.async.cg.shared.global [%0], [%1], 16;"
                 :: "r"(dst), "l"(src) : "memory");
}
#define CP_COMMIT() asm volatile("cp.async.commit_group;" ::: "memory")
#define CP_WAIT0()  asm volatile("cp.async.wait_group 0;" ::: "memory")
#define CP_WAIT1()  asm volatile("cp.async.wait_group 1;" ::: "memory")

__device__ __forceinline__ uint32_t packh_hi(float x, float y) {
    __half2 h = __floats2half2_rn(x, y);
    return *(uint32_t*)&h;
}

__device__ __forceinline__ uint32_t swz(int row, int chunk) {
    return (uint32_t)(row * 256 + ((chunk ^ (row & 7)) << 4));
}
__device__ __forceinline__ uint32_t swz128(int row, int chunk) {
    return (uint32_t)(row * 128 + ((chunk ^ (row & 7)) << 4));
}

// ============================================================================
// round kernel: fp32 -> fp16
// ============================================================================
__global__ __launch_bounds__(256)
void round_f16(const float* __restrict__ x, f16* __restrict__ hi, int n4)
{
    int i = blockIdx.x * blockDim.x + threadIdx.x;
    if (i < n4) {
        float4 v = ((const float4*)x)[i];
        __half2 H0 = __floats2half2_rn(v.x, v.y);
        __half2 H1 = __floats2half2_rn(v.z, v.w);
        ((uint2*)hi)[i] = make_uint2(*(uint32_t*)&H0, *(uint32_t*)&H1);
    }
}

// ============================================================================
// GEMM: Y[m,n] = sum_k A[m,k]*B[n,k] + bias[n]   (single-pass fp16)
// CTA 128x128, BK=64, 3-stage cp.async. 8 warps (4m x 2n).
// Stage: A(16K) B(16K) = 32KB; 3 stages = 96KB.
// Epilogue: Yf -> fp32+bias;  else -> fp16 of (acc+bias)*scale.
// ============================================================================
#define GSTG 32768
#define GEMM_SMEM (3 * GSTG)
#define GNS (CC / 64)

__global__ __launch_bounds__(256, 1)
void gemm_f16(const f16* __restrict__ A, const f16* __restrict__ B,
              const float* __restrict__ bias,
              float* __restrict__ Yf, f16* __restrict__ Yh, float scale)
{
    extern __shared__ char sm[];
    const uint32_t sb = smem_u32(sm);

    const int tid  = threadIdx.x;
    const int wid  = tid >> 5;
    const int lane = tid & 31;
    const int wm = wid & 3;
    const int wn = wid >> 2;
    const int m0 = blockIdx.y * 128;
    const int n0 = blockIdx.x * 128;

    const int lrow = tid >> 1;
    const int lcb  = (tid & 1) * 4;

    const f16* Ap = A + (size_t)(m0 + lrow) * CC;
    const f16* Bp = B + (size_t)(n0 + lrow) * CC;

    float acc[2][8][4];
#pragma unroll
    for (int i = 0; i < 2; i++)
#pragma unroll
        for (int j = 0; j < 8; j++)
#pragma unroll
            for (int k = 0; k < 4; k++) acc[i][j][k] = 0.f;

    const int krow_in = ((lane >> 4) & 1) * 8 + (lane & 7);
    const int kc      = (lane >> 3) & 1;
    const int arow    = wm * 32 + (lane & 15);
    const int ac      = lane >> 4;

    auto issue = [&](int s) {
        const uint32_t stb = sb + (uint32_t)((s % 3) * GSTG);
        const int ko = s * 64;
#pragma unroll
        for (int c = 0; c < 4; c++) {
            const int ch = lcb + c;
            const uint32_t so = swz128(lrow, ch);
            cpa16(stb + so,         Ap + ko + ch * 8);
            cpa16(stb + 16384 + so, Bp + ko + ch * 8);
        }
    };

    issue(0); CP_COMMIT();
    issue(1); CP_COMMIT();

    for (int s = 0; s < GNS; s++) {
        CP_WAIT1();
        __syncthreads();
        if (s + 2 < GNS) issue(s + 2);
        CP_COMMIT();

        const uint32_t stb = sb + (uint32_t)((s % 3) * GSTG);
#pragma unroll
        for (int kt = 0; kt < 4; kt++) {
            uint32_t a_[2][4];
#pragma unroll
            for (int mt = 0; mt < 2; mt++)
                ldx4(a_[mt], stb + swz128(arow + mt * 16, 2 * kt + ac));
#pragma unroll
            for (int np = 0; np < 4; np++) {
                uint32_t b_[4];
                ldx4(b_, stb + 16384 +
                         swz128(wn * 64 + np * 16 + krow_in, 2 * kt + kc));
#pragma unroll
                for (int mt = 0; mt < 2; mt++) {
                    mma_f16(acc[mt][2 * np + 0], a_[mt], b_[0], b_[1]);
                    mma_f16(acc[mt][2 * np + 1], a_[mt], b_[2], b_[3]);
                }
            }
        }
    }

    // ---- epilogue ----
#pragma unroll
    for (int mt = 0; mt < 2; mt++) {
        const int r0 = m0 + wm * 32 + mt * 16 + (lane >> 2);
#pragma unroll
        for (int nt = 0; nt < 8; nt++) {
            const int c = n0 + wn * 64 + nt * 8 + (lane & 3) * 2;
            float2 bv = *(const float2*)(bias + c);
            float y00 = acc[mt][nt][0] + bv.x;
            float y01 = acc[mt][nt][1] + bv.y;
            float y10 = acc[mt][nt][2] + bv.x;
            float y11 = acc[mt][nt][3] + bv.y;
            if (Yf) {
                *(float2*)(Yf + (size_t)r0 * CC + c)       = make_float2(y00, y01);
                *(float2*)(Yf + (size_t)(r0 + 8) * CC + c) = make_float2(y10, y11);
            } else {
                y00 *= scale; y01 *= scale; y10 *= scale; y11 *= scale;
                *(uint32_t*)(Yh + (size_t)r0 * CC + c)       = packh_hi(y00, y01);
                *(uint32_t*)(Yh + (size_t)(r0 + 8) * CC + c) = packh_hi(y10, y11);
            }
        }
    }
}

// ============================================================================
// Flash attention, single-pass fp16 throughout. Q fragments register-resident,
// cp.async double-buffered K/V/mask. q-tile 128, kv-tile 64, 8 warps.
// ============================================================================
#define KVSTG 32768
#define FMSK  65536
#define MSTG  34816
#define FLASH_SMEM (FMSK + 2 * MSTG)    // 135168

__global__ __launch_bounds__(256, 1)
void flash_attn_tc4(const f16* __restrict__ Qh,
                    const f16* __restrict__ Kh, const f16* __restrict__ Vh,
                    const float* __restrict__ Mg, f16* __restrict__ Oh)
{
    extern __shared__ char sm[];
    const uint32_t sb = smem_u32(sm);

    const int tid  = threadIdx.x;
    const int wid  = tid >> 5;
    const int lane = tid & 31;
    const int q0 = blockIdx.x * 128;
    const int h  = blockIdx.y;
    const int b  = blockIdx.z;

    // ---- stage Q into low 32KB, extract fragments ----
    {
        const int row = tid >> 1;
        const int cb  = (tid & 1) * 8;
        const f16* qsrc = Qh + (size_t)(b * NQ + q0 + row) * CC + h * DH;
#pragma unroll
        for (int c = 0; c < 8; c++) {
            const int ch = cb + c;
            cpa16(sb + swz(row, ch), qsrc + ch * 8);
        }
        CP_COMMIT();
        CP_WAIT0();
        __syncthreads();
    }

    uint32_t qhf[8][4];
    {
        const int qrow = 16 * wid + (lane & 15);
        const int qc   = lane >> 4;
#pragma unroll
        for (int kt = 0; kt < 8; kt++)
            ldx4(qhf[kt], sb + swz(qrow, 2 * kt + qc));
    }
    __syncthreads();

    const int krow_in = ((lane >> 4) & 1) * 8 + (lane & 7);
    const int kc      = (lane >> 3) & 1;
    const int vrow_in = (lane & 7) + ((lane >> 3) & 1) * 8;
    const int vc      = lane >> 4;

    const int kvrow = tid >> 2;
    const int kvcb  = (tid & 3) * 4;
    const int mrow  = tid >> 1;
    const int mcb   = (tid & 1) * 8;

    const f16* khb = Kh + (size_t)(b * HW + kvrow) * CC + h * DH;
    const f16* vhb = Vh + (size_t)(b * HW + kvrow) * CC + h * DH;
    const float* mb = Mg + (size_t)(b * NQ + q0 + mrow) * HW;

    auto issue = [&](int i) {
        const uint32_t stb = sb + (uint32_t)((i & 1) * KVSTG);
        const size_t koff = (size_t)(i * 64) * CC;
#pragma unroll
        for (int c = 0; c < 4; c++) {
            const int ch = kvcb + c;
            const uint32_t so = swz(kvrow, ch);
            cpa16(stb + so,         khb + koff + ch * 8);
            cpa16(stb + 16384 + so, vhb + koff + ch * 8);
        }
        const uint32_t mstb = sb + FMSK + (uint32_t)((i & 1) * MSTG);
#pragma unroll
        for (int j = 0; j < 8; j++) {
            const int ch = mcb + j;
            cpa16(mstb + (uint32_t)(mrow * 272 + ch * 16), mb + i * 64 + ch * 4);
        }
    };

    float m0r = -1e30f, m1r = -1e30f, l0r = 0.f, l1r = 0.f;
    float oc[16][4];
#pragma unroll
    for (int n = 0; n < 16; n++)
#pragma unroll
        for (int j = 0; j < 4; j++) oc[n][j] = 0.f;

    issue(0); CP_COMMIT();

    const int r0l = 16 * wid + (lane >> 2);
    const int mc0 = 2 * (lane & 3);

    for (int i = 0; i < HW / 64; i++) {
        CP_WAIT0();
        __syncthreads();
        if (i + 1 < HW / 64) issue(i + 1);
        CP_COMMIT();

        const uint32_t stb = sb + (uint32_t)((i & 1) * KVSTG);
        const float* mskf = (const float*)(sm + FMSK + (i & 1) * MSTG);

        // ---- S = Q K^T ----
        float sc[8][4];
#pragma unroll
        for (int n = 0; n < 8; n++)
#pragma unroll
            for (int j = 0; j < 4; j++) sc[n][j] = 0.f;

#pragma unroll
        for (int kt = 0; kt < 8; kt++) {
#pragma unroll
            for (int j = 0; j < 4; j++) {
                uint32_t kh_[4];
                ldx4(kh_, stb + swz(16 * j + krow_in, 2 * kt + kc));
                mma_f16(sc[2 * j + 0], qhf[kt], kh_[0], kh_[1]);
                mma_f16(sc[2 * j + 1], qhf[kt], kh_[2], kh_[3]);
            }
        }

        // ---- mask + online softmax ----
        float mx0 = m0r, mx1 = m1r;
#pragma unroll
        for (int n = 0; n < 8; n++) {
            const int cw = n * 8 + mc0;
            float2 mk0 = *(const float2*)&mskf[r0l * 68 + cw];
            float2 mk1 = *(const float2*)&mskf[(r0l + 8) * 68 + cw];
            sc[n][0] = (mk0.x >= 0.5f) ? sc[n][0] : -1e30f;
            sc[n][1] = (mk0.y >= 0.5f) ? sc[n][1] : -1e30f;
            sc[n][2] = (mk1.x >= 0.5f) ? sc[n][2] : -1e30f;
            sc[n][3] = (mk1.y >= 0.5f) ? sc[n][3] : -1e30f;
            mx0 = fmaxf(mx0, fmaxf(sc[n][0], sc[n][1]));
            mx1 = fmaxf(mx1, fmaxf(sc[n][2], sc[n][3]));
        }
        mx0 = fmaxf(mx0, __shfl_xor_sync(0xffffffffu, mx0, 1));
        mx0 = fmaxf(mx0, __shfl_xor_sync(0xffffffffu, mx0, 2));
        mx1 = fmaxf(mx1, __shfl_xor_sync(0xffffffffu, mx1, 1));
        mx1 = fmaxf(mx1, __shfl_xor_sync(0xffffffffu, mx1, 2));

        const float alpha0 = __expf(m0r - mx0);
        const float alpha1 = __expf(m1r - mx1);
        m0r = mx0; m1r = mx1;

        float rs0 = 0.f, rs1 = 0.f;
#pragma unroll
        for (int n = 0; n < 8; n++) {
            sc[n][0] = __expf(sc[n][0] - mx0);
            sc[n][1] = __expf(sc[n][1] - mx0);
            sc[n][2] = __expf(sc[n][2] - mx1);
            sc[n][3] = __expf(sc[n][3] - mx1);
            rs0 += sc[n][0] + sc[n][1];
            rs1 += sc[n][2] + sc[n][3];
        }
        rs0 += __shfl_xor_sync(0xffffffffu, rs0, 1);
        rs0 += __shfl_xor_sync(0xffffffffu, rs0, 2);
        rs1 += __shfl_xor_sync(0xffffffffu, rs1, 1);
        rs1 += __shfl_xor_sync(0xffffffffu, rs1, 2);
        l0r = l0r * alpha0 + rs0;
        l1r = l1r * alpha1 + rs1;

        // ---- pack P (hi only); rescale O ----
        uint32_t pah[4][4];
#pragma unroll
        for (int kt = 0; kt < 4; kt++) {
            pah[kt][0] = packh_hi(sc[2 * kt][0],     sc[2 * kt][1]);
            pah[kt][1] = packh_hi(sc[2 * kt][2],     sc[2 * kt][3]);
            pah[kt][2] = packh_hi(sc[2 * kt + 1][0], sc[2 * kt + 1][1]);
            pah[kt][3] = packh_hi(sc[2 * kt + 1][2], sc[2 * kt + 1][3]);
        }
#pragma unroll
        for (int n = 0; n < 16; n++) {
            oc[n][0] *= alpha0; oc[n][1] *= alpha0;
            oc[n][2] *= alpha1; oc[n][3] *= alpha1;
        }

        // ---- O += P @ V ----
#pragma unroll
        for (int kt = 0; kt < 4; kt++) {
#pragma unroll
            for (int np = 0; np < 8; np++) {
                uint32_t v_[4];
                ldx4t(v_, stb + 16384 + swz(16 * kt + vrow_in, 2 * np + vc));
                mma_f16(oc[2 * np + 0], pah[kt], v_[0], v_[1]);
                mma_f16(oc[2 * np + 1], pah[kt], v_[2], v_[3]);
            }
        }
    }

    // ---- normalize, write fp16 ----
    const float rl0 = 1.0f / l0r;
    const float rl1 = 1.0f / l1r;
    const size_t rbase0 = (size_t)(b * NQ + q0 + r0l) * CC + h * DH;
    const size_t rbase1 = rbase0 + (size_t)8 * CC;
#pragma unroll
    for (int n = 0; n < 16; n++) {
        const int c = n * 8 + mc0;
        *(uint32_t*)(Oh + rbase0 + c) = packh_hi(oc[n][0] * rl0, oc[n][1] * rl0);
        *(uint32_t*)(Oh + rbase1 + c) = packh_hi(oc[n][2] * rl1, oc[n][3] * rl1);
    }
}

// ---------------------------------------------------------------------------
extern "C" void kernel_launch(void* const* d_in, const int* in_sizes, int n_in,
                              void* d_out, int out_size)
{
    const float* query  = (const float*)d_in[0];
    const float* memory = (const float*)d_in[1];
    const float* mask   = (const float*)d_in[2];
    const float* Wq = (const float*)d_in[3];
    const float* bq = (const float*)d_in[4];
    const float* Wk = (const float*)d_in[5];
    const float* bk = (const float*)d_in[6];
    const float* Wv = (const float*)d_in[7];
    const float* bv = (const float*)d_in[8];
    const float* Wo = (const float*)d_in[9];
    const float* bo = (const float*)d_in[10];
    float* out = (float*)d_out;

    f16 *qin_h, *mem_h, *wq_h, *wk_h, *wv_h, *wo_h;
    f16 *q_h, *k_h, *v_h, *a_h;
    cudaGetSymbolAddress((void**)&qin_h, s_qin_h);
    cudaGetSymbolAddress((void**)&mem_h, s_mem_h);
    cudaGetSymbolAddress((void**)&wq_h, s_wq_h);
    cudaGetSymbolAddress((void**)&wk_h, s_wk_h);
    cudaGetSymbolAddress((void**)&wv_h, s_wv_h);
    cudaGetSymbolAddress((void**)&wo_h, s_wo_h);
    cudaGetSymbolAddress((void**)&q_h, s_q_h);
    cudaGetSymbolAddress((void**)&k_h, s_k_h);
    cudaGetSymbolAddress((void**)&v_h, s_v_h);
    cudaGetSymbolAddress((void**)&a_h, s_a_h);

    cudaFuncSetAttribute(gemm_f16,
                         cudaFuncAttributeMaxDynamicSharedMemorySize, GEMM_SMEM);
    cudaFuncSetAttribute(flash_attn_tc4,
                         cudaFuncAttributeMaxDynamicSharedMemorySize, FLASH_SMEM);

    dim3 blk(256);
    const float scale = 0.08838834764831845f;   // 1/sqrt(128)

    // ---- rounds ----
    {
        int n4 = BB * NQ * CC / 4;
        round_f16<<<(n4 + 255) / 256, blk>>>(query, qin_h, n4);
        n4 = BB * HW * CC / 4;
        round_f16<<<(n4 + 255) / 256, blk>>>(memory, mem_h, n4);
        n4 = CC * CC / 4;
        round_f16<<<(n4 + 255) / 256, blk>>>(Wq, wq_h, n4);
        round_f16<<<(n4 + 255) / 256, blk>>>(Wk, wk_h, n4);
        round_f16<<<(n4 + 255) / 256, blk>>>(Wv, wv_h, n4);
        round_f16<<<(n4 + 255) / 256, blk>>>(Wo, wo_h, n4);
    }

    // ---- projections (single-pass fp16) ----
    gemm_f16<<<dim3(CC / 128, (BB * NQ) / 128), blk, GEMM_SMEM>>>(
        qin_h, wq_h, bq, nullptr, q_h, scale);
    gemm_f16<<<dim3(CC / 128, (BB * HW) / 128), blk, GEMM_SMEM>>>(
        mem_h, wk_h, bk, nullptr, k_h, 1.0f);
    gemm_f16<<<dim3(CC / 128, (BB * HW) / 128), blk, GEMM_SMEM>>>(
        mem_h, wv_h, bv, nullptr, v_h, 1.0f);

    // ---- attention ----
    flash_attn_tc4<<<dim3(NQ / 128, HH, BB), blk, FLASH_SMEM>>>(
        q_h, k_h, v_h, mask, a_h);

    // ---- output projection (fp32 out) ----
    gemm_f16<<<dim3(CC / 128, (BB * NQ) / 128), blk, GEMM_SMEM>>>(
        a_h, wo_h, bo, out, nullptr, 1.0f);
}

// round 9
// speedup vs baseline: 6.7293x; 1.1535x over previous
#include <cuda_runtime.h>
#include <cuda_fp16.h>
#include <math.h>
#include <stdint.h>

#define BB 4
#define NQ 1024
#define HW 4096
#define CC 1024
#define HH 8
#define DH 128

typedef __half f16;

// ---------------- scratch (device globals; no allocations allowed) ----------
__device__ f16 s_qin_h[(size_t)BB * NQ * CC];
__device__ f16 s_mem_h[(size_t)BB * HW * CC];
__device__ f16 s_wq_h[(size_t)CC * CC];
__device__ f16 s_wk_h[(size_t)CC * CC];
__device__ f16 s_wv_h[(size_t)CC * CC];
__device__ f16 s_wo_h[(size_t)CC * CC];
__device__ f16 s_q_h[(size_t)BB * NQ * CC];   // scaled q projection (fp16)
__device__ f16 s_k_h[(size_t)BB * HW * CC];   // k projection (fp16)
__device__ f16 s_v_h[(size_t)BB * HW * CC];   // v projection (fp16)
__device__ f16 s_a_h[(size_t)BB * NQ * CC];   // attention output (fp16)
__device__ uint32_t s_mbits[(size_t)BB * NQ * HW / 32];   // mask bitmap (2MB)

// ============================ helpers =======================================
__device__ __forceinline__ uint32_t smem_u32(const void* p) {
    uint32_t a;
    asm("{ .reg .u64 t; cvta.to.shared.u64 t, %1; cvt.u32.u64 %0, t; }"
        : "=r"(a) : "l"(p));
    return a;
}

__device__ __forceinline__ void ldx4(uint32_t* r, uint32_t addr) {
    asm volatile("ldmatrix.sync.aligned.m8n8.x4.shared.b16 {%0,%1,%2,%3}, [%4];"
                 : "=r"(r[0]), "=r"(r[1]), "=r"(r[2]), "=r"(r[3]) : "r"(addr));
}

__device__ __forceinline__ void ldx4t(uint32_t* r, uint32_t addr) {
    asm volatile("ldmatrix.sync.aligned.m8n8.x4.trans.shared.b16 {%0,%1,%2,%3}, [%4];"
                 : "=r"(r[0]), "=r"(r[1]), "=r"(r[2]), "=r"(r[3]) : "r"(addr));
}

__device__ __forceinline__ void mma_f16(float* c, const uint32_t* a,
                                        uint32_t b0, uint32_t b1) {
    asm volatile(
        "mma.sync.aligned.m16n8k16.row.col.f32.f16.f16.f32 "
        "{%0,%1,%2,%3}, {%4,%5,%6,%7}, {%8,%9}, {%0,%1,%2,%3};"
        : "+f"(c[0]), "+f"(c[1]), "+f"(c[2]), "+f"(c[3])
        : "r"(a[0]), "r"(a[1]), "r"(a[2]), "r"(a[3]), "r"(b0), "r"(b1));
}

__device__ __forceinline__ void cpa16(uint32_t dst, const void* src) {
    asm volatile("cp.async.cg.shared.global [%0], [%1], 16;"
                 :: "r"(dst), "l"(src) : "memory");
}
#define CP_COMMIT() asm volatile("cp.async.commit_group;" ::: "memory")
#define CP_WAIT0()  asm volatile("cp.async.wait_group 0;" ::: "memory")
#define CP_WAIT1()  asm volatile("cp.async.wait_group 1;" ::: "memory")

__device__ __forceinline__ uint32_t packh_hi(float x, float y) {
    __half2 h = __floats2half2_rn(x, y);
    return *(uint32_t*)&h;
}

// raw base-2 exponential (single MUFU op)
__device__ __forceinline__ float ex2f(float x) {
    float y;
    asm("ex2.approx.ftz.f32 %0, %1;" : "=f"(y) : "f"(x));
    return y;
}

__device__ __forceinline__ uint32_t swz(int row, int chunk) {
    return (uint32_t)(row * 256 + ((chunk ^ (row & 7)) << 4));
}
__device__ __forceinline__ uint32_t swz128(int row, int chunk) {
    return (uint32_t)(row * 128 + ((chunk ^ (row & 7)) << 4));
}

// ============================================================================
// prep kernels
// ============================================================================
__global__ __launch_bounds__(256)
void round_f16(const float* __restrict__ x, f16* __restrict__ hi, int n4)
{
    int i = blockIdx.x * blockDim.x + threadIdx.x;
    if (i < n4) {
        float4 v = ((const float4*)x)[i];
        __half2 H0 = __floats2half2_rn(v.x, v.y);
        __half2 H1 = __floats2half2_rn(v.z, v.w);
        ((uint2*)hi)[i] = make_uint2(*(uint32_t*)&H0, *(uint32_t*)&H1);
    }
}

// mask fp32 -> bitmap: bit l of word w = (mask[w*32+l] >= 0.5)
__global__ __launch_bounds__(256)
void mask_bits(const float* __restrict__ m, uint32_t* __restrict__ out, int nwords)
{
    int w = blockIdx.x * (blockDim.x >> 5) + (threadIdx.x >> 5);
    int lane = threadIdx.x & 31;
    if (w < nwords) {
        float v = m[(size_t)w * 32 + lane];
        uint32_t bits = __ballot_sync(0xffffffffu, v >= 0.5f);
        if (lane == 0) out[w] = bits;
    }
}

// ============================================================================
// GEMM: Y[m,n] = sum_k A[m,k]*B[n,k] + bias[n]   (single-pass fp16)
// CTA 128x128, BK=64, 3-stage cp.async. 8 warps (4m x 2n).
// ============================================================================
#define GSTG 32768
#define GEMM_SMEM (3 * GSTG)
#define GNS (CC / 64)

__global__ __launch_bounds__(256, 1)
void gemm_f16(const f16* __restrict__ A, const f16* __restrict__ B,
              const float* __restrict__ bias,
              float* __restrict__ Yf, f16* __restrict__ Yh, float scale)
{
    extern __shared__ char sm[];
    const uint32_t sb = smem_u32(sm);

    const int tid  = threadIdx.x;
    const int wid  = tid >> 5;
    const int lane = tid & 31;
    const int wm = wid & 3;
    const int wn = wid >> 2;
    const int m0 = blockIdx.y * 128;
    const int n0 = blockIdx.x * 128;

    const int lrow = tid >> 1;
    const int lcb  = (tid & 1) * 4;

    const f16* Ap = A + (size_t)(m0 + lrow) * CC;
    const f16* Bp = B + (size_t)(n0 + lrow) * CC;

    float acc[2][8][4];
#pragma unroll
    for (int i = 0; i < 2; i++)
#pragma unroll
        for (int j = 0; j < 8; j++)
#pragma unroll
            for (int k = 0; k < 4; k++) acc[i][j][k] = 0.f;

    const int krow_in = ((lane >> 4) & 1) * 8 + (lane & 7);
    const int kc      = (lane >> 3) & 1;
    const int arow    = wm * 32 + (lane & 15);
    const int ac      = lane >> 4;

    auto issue = [&](int s) {
        const uint32_t stb = sb + (uint32_t)((s % 3) * GSTG);
        const int ko = s * 64;
#pragma unroll
        for (int c = 0; c < 4; c++) {
            const int ch = lcb + c;
            const uint32_t so = swz128(lrow, ch);
            cpa16(stb + so,         Ap + ko + ch * 8);
            cpa16(stb + 16384 + so, Bp + ko + ch * 8);
        }
    };

    issue(0); CP_COMMIT();
    issue(1); CP_COMMIT();

    for (int s = 0; s < GNS; s++) {
        CP_WAIT1();
        __syncthreads();
        if (s + 2 < GNS) issue(s + 2);
        CP_COMMIT();

        const uint32_t stb = sb + (uint32_t)((s % 3) * GSTG);
#pragma unroll
        for (int kt = 0; kt < 4; kt++) {
            uint32_t a_[2][4];
#pragma unroll
            for (int mt = 0; mt < 2; mt++)
                ldx4(a_[mt], stb + swz128(arow + mt * 16, 2 * kt + ac));
#pragma unroll
            for (int np = 0; np < 4; np++) {
                uint32_t b_[4];
                ldx4(b_, stb + 16384 +
                         swz128(wn * 64 + np * 16 + krow_in, 2 * kt + kc));
#pragma unroll
                for (int mt = 0; mt < 2; mt++) {
                    mma_f16(acc[mt][2 * np + 0], a_[mt], b_[0], b_[1]);
                    mma_f16(acc[mt][2 * np + 1], a_[mt], b_[2], b_[3]);
                }
            }
        }
    }

    // ---- epilogue ----
#pragma unroll
    for (int mt = 0; mt < 2; mt++) {
        const int r0 = m0 + wm * 32 + mt * 16 + (lane >> 2);
#pragma unroll
        for (int nt = 0; nt < 8; nt++) {
            const int c = n0 + wn * 64 + nt * 8 + (lane & 3) * 2;
            float2 bv = *(const float2*)(bias + c);
            float y00 = acc[mt][nt][0] + bv.x;
            float y01 = acc[mt][nt][1] + bv.y;
            float y10 = acc[mt][nt][2] + bv.x;
            float y11 = acc[mt][nt][3] + bv.y;
            if (Yf) {
                *(float2*)(Yf + (size_t)r0 * CC + c)       = make_float2(y00, y01);
                *(float2*)(Yf + (size_t)(r0 + 8) * CC + c) = make_float2(y10, y11);
            } else {
                y00 *= scale; y01 *= scale; y10 *= scale; y11 *= scale;
                *(uint32_t*)(Yh + (size_t)r0 * CC + c)       = packh_hi(y00, y01);
                *(uint32_t*)(Yh + (size_t)(r0 + 8) * CC + c) = packh_hi(y10, y11);
            }
        }
    }
}

// ============================================================================
// Flash attention: single-pass fp16, base-2 softmax, bitmask mask,
// 3-stage cp.async KV pipeline. q-tile 128, kv-tile 64, 8 warps.
// Q (scaled by 1/sqrt(dh)*log2e at projection) register-resident.
// Stage: K(16K) V(16K) = 32KB; 3 stages = 96KB.
// ============================================================================
#define KVSTG 32768
#define FLASH_SMEM (3 * KVSTG)    // 98304
#define NKV (HW / 64)             // 64

__global__ __launch_bounds__(256, 1)
void flash_attn_tc5(const f16* __restrict__ Qh,
                    const f16* __restrict__ Kh, const f16* __restrict__ Vh,
                    const uint32_t* __restrict__ Mb, f16* __restrict__ Oh)
{
    extern __shared__ char sm[];
    const uint32_t sb = smem_u32(sm);

    const int tid  = threadIdx.x;
    const int wid  = tid >> 5;
    const int lane = tid & 31;
    const int q0 = blockIdx.x * 128;
    const int h  = blockIdx.y;
    const int b  = blockIdx.z;

    // ---- stage Q into stage-0 buffer, extract fragments ----
    {
        const int row = tid >> 1;
        const int cb  = (tid & 1) * 8;
        const f16* qsrc = Qh + (size_t)(b * NQ + q0 + row) * CC + h * DH;
#pragma unroll
        for (int c = 0; c < 8; c++) {
            const int ch = cb + c;
            cpa16(sb + swz(row, ch), qsrc + ch * 8);
        }
        CP_COMMIT();
        CP_WAIT0();
        __syncthreads();
    }

    uint32_t qhf[8][4];
    {
        const int qrow = 16 * wid + (lane & 15);
        const int qc   = lane >> 4;
#pragma unroll
        for (int kt = 0; kt < 8; kt++)
            ldx4(qhf[kt], sb + swz(qrow, 2 * kt + qc));
    }
    __syncthreads();

    const int krow_in = ((lane >> 4) & 1) * 8 + (lane & 7);
    const int kc      = (lane >> 3) & 1;
    const int vrow_in = (lane & 7) + ((lane >> 3) & 1) * 8;
    const int vc      = lane >> 4;

    const int kvrow = tid >> 2;
    const int kvcb  = (tid & 3) * 4;

    const f16* khb = Kh + (size_t)(b * HW + kvrow) * CC + h * DH;
    const f16* vhb = Vh + (size_t)(b * HW + kvrow) * CC + h * DH;

    const int r0l = 16 * wid + (lane >> 2);
    const int mc0 = 2 * (lane & 3);
    const uint32_t* mrow0 = Mb + (size_t)(b * NQ + q0 + r0l) * (HW / 32);
    const uint32_t* mrow1 = mrow0 + (size_t)8 * (HW / 32);

    auto issue = [&](int i) {
        const uint32_t stb = sb + (uint32_t)((i % 3) * KVSTG);
        const size_t koff = (size_t)(i * 64) * CC;
#pragma unroll
        for (int c = 0; c < 4; c++) {
            const int ch = kvcb + c;
            const uint32_t so = swz(kvrow, ch);
            cpa16(stb + so,         khb + koff + ch * 8);
            cpa16(stb + 16384 + so, vhb + koff + ch * 8);
        }
    };

    float m0r = -1e30f, m1r = -1e30f, l0r = 0.f, l1r = 0.f;
    float oc[16][4];
#pragma unroll
    for (int n = 0; n < 16; n++)
#pragma unroll
        for (int j = 0; j < 4; j++) oc[n][j] = 0.f;

    issue(0); CP_COMMIT();
    issue(1); CP_COMMIT();

    for (int i = 0; i < NKV; i++) {
        CP_WAIT1();
        __syncthreads();
        if (i + 2 < NKV) issue(i + 2);
        CP_COMMIT();

        const uint32_t stb = sb + (uint32_t)((i % 3) * KVSTG);

        // mask bit words for this thread's two rows, this kv tile
        const uint2 w0 = *(const uint2*)(mrow0 + i * 2);
        const uint2 w1 = *(const uint2*)(mrow1 + i * 2);

        // ---- S = Q K^T ----
        float sc[8][4];
#pragma unroll
        for (int n = 0; n < 8; n++)
#pragma unroll
            for (int j = 0; j < 4; j++) sc[n][j] = 0.f;

#pragma unroll
        for (int kt = 0; kt < 8; kt++) {
#pragma unroll
            for (int j = 0; j < 4; j++) {
                uint32_t kh_[4];
                ldx4(kh_, stb + swz(16 * j + krow_in, 2 * kt + kc));
                mma_f16(sc[2 * j + 0], qhf[kt], kh_[0], kh_[1]);
                mma_f16(sc[2 * j + 1], qhf[kt], kh_[2], kh_[3]);
            }
        }

        // ---- mask (bit test) + online softmax (base-2) ----
        float mx0 = m0r, mx1 = m1r;
#pragma unroll
        for (int n = 0; n < 8; n++) {
            const uint32_t wa = (n < 4) ? w0.x : w0.y;
            const uint32_t wb = (n < 4) ? w1.x : w1.y;
            const int pos = (n & 3) * 8 + mc0;
            sc[n][0] = ((wa >> pos) & 1u)       ? sc[n][0] : -1e30f;
            sc[n][1] = ((wa >> (pos + 1)) & 1u) ? sc[n][1] : -1e30f;
            sc[n][2] = ((wb >> pos) & 1u)       ? sc[n][2] : -1e30f;
            sc[n][3] = ((wb >> (pos + 1)) & 1u) ? sc[n][3] : -1e30f;
            mx0 = fmaxf(mx0, fmaxf(sc[n][0], sc[n][1]));
            mx1 = fmaxf(mx1, fmaxf(sc[n][2], sc[n][3]));
        }
        mx0 = fmaxf(mx0, __shfl_xor_sync(0xffffffffu, mx0, 1));
        mx0 = fmaxf(mx0, __shfl_xor_sync(0xffffffffu, mx0, 2));
        mx1 = fmaxf(mx1, __shfl_xor_sync(0xffffffffu, mx1, 1));
        mx1 = fmaxf(mx1, __shfl_xor_sync(0xffffffffu, mx1, 2));

        const float alpha0 = ex2f(m0r - mx0);
        const float alpha1 = ex2f(m1r - mx1);
        m0r = mx0; m1r = mx1;

        float rs0 = 0.f, rs1 = 0.f;
#pragma unroll
        for (int n = 0; n < 8; n++) {
            sc[n][0] = ex2f(sc[n][0] - mx0);
            sc[n][1] = ex2f(sc[n][1] - mx0);
            sc[n][2] = ex2f(sc[n][2] - mx1);
            sc[n][3] = ex2f(sc[n][3] - mx1);
            rs0 += sc[n][0] + sc[n][1];
            rs1 += sc[n][2] + sc[n][3];
        }
        rs0 += __shfl_xor_sync(0xffffffffu, rs0, 1);
        rs0 += __shfl_xor_sync(0xffffffffu, rs0, 2);
        rs1 += __shfl_xor_sync(0xffffffffu, rs1, 1);
        rs1 += __shfl_xor_sync(0xffffffffu, rs1, 2);
        l0r = l0r * alpha0 + rs0;
        l1r = l1r * alpha1 + rs1;

        // ---- pack P; rescale O ----
        uint32_t pah[4][4];
#pragma unroll
        for (int kt = 0; kt < 4; kt++) {
            pah[kt][0] = packh_hi(sc[2 * kt][0],     sc[2 * kt][1]);
            pah[kt][1] = packh_hi(sc[2 * kt][2],     sc[2 * kt][3]);
            pah[kt][2] = packh_hi(sc[2 * kt + 1][0], sc[2 * kt + 1][1]);
            pah[kt][3] = packh_hi(sc[2 * kt + 1][2], sc[2 * kt + 1][3]);
        }
#pragma unroll
        for (int n = 0; n < 16; n++) {
            oc[n][0] *= alpha0; oc[n][1] *= alpha0;
            oc[n][2] *= alpha1; oc[n][3] *= alpha1;
        }

        // ---- O += P @ V ----
#pragma unroll
        for (int kt = 0; kt < 4; kt++) {
#pragma unroll
            for (int np = 0; np < 8; np++) {
                uint32_t v_[4];
                ldx4t(v_, stb + 16384 + swz(16 * kt + vrow_in, 2 * np + vc));
                mma_f16(oc[2 * np + 0], pah[kt], v_[0], v_[1]);
                mma_f16(oc[2 * np + 1], pah[kt], v_[2], v_[3]);
            }
        }
    }

    // ---- normalize, write fp16 ----
    const float rl0 = 1.0f / l0r;
    const float rl1 = 1.0f / l1r;
    const size_t rbase0 = (size_t)(b * NQ + q0 + r0l) * CC + h * DH;
    const size_t rbase1 = rbase0 + (size_t)8 * CC;
#pragma unroll
    for (int n = 0; n < 16; n++) {
        const int c = n * 8 + mc0;
        *(uint32_t*)(Oh + rbase0 + c) = packh_hi(oc[n][0] * rl0, oc[n][1] * rl0);
        *(uint32_t*)(Oh + rbase1 + c) = packh_hi(oc[n][2] * rl1, oc[n][3] * rl1);
    }
}

// ---------------------------------------------------------------------------
extern "C" void kernel_launch(void* const* d_in, const int* in_sizes, int n_in,
                              void* d_out, int out_size)
{
    const float* query  = (const float*)d_in[0];
    const float* memory = (const float*)d_in[1];
    const float* mask   = (const float*)d_in[2];
    const float* Wq = (const float*)d_in[3];
    const float* bq = (const float*)d_in[4];
    const float* Wk = (const float*)d_in[5];
    const float* bk = (const float*)d_in[6];
    const float* Wv = (const float*)d_in[7];
    const float* bv = (const float*)d_in[8];
    const float* Wo = (const float*)d_in[9];
    const float* bo = (const float*)d_in[10];
    float* out = (float*)d_out;

    f16 *qin_h, *mem_h, *wq_h, *wk_h, *wv_h, *wo_h;
    f16 *q_h, *k_h, *v_h, *a_h;
    uint32_t* mb;
    cudaGetSymbolAddress((void**)&qin_h, s_qin_h);
    cudaGetSymbolAddress((void**)&mem_h, s_mem_h);
    cudaGetSymbolAddress((void**)&wq_h, s_wq_h);
    cudaGetSymbolAddress((void**)&wk_h, s_wk_h);
    cudaGetSymbolAddress((void**)&wv_h, s_wv_h);
    cudaGetSymbolAddress((void**)&wo_h, s_wo_h);
    cudaGetSymbolAddress((void**)&q_h, s_q_h);
    cudaGetSymbolAddress((void**)&k_h, s_k_h);
    cudaGetSymbolAddress((void**)&v_h, s_v_h);
    cudaGetSymbolAddress((void**)&a_h, s_a_h);
    cudaGetSymbolAddress((void**)&mb, s_mbits);

    cudaFuncSetAttribute(gemm_f16,
                         cudaFuncAttributeMaxDynamicSharedMemorySize, GEMM_SMEM);
    cudaFuncSetAttribute(flash_attn_tc5,
                         cudaFuncAttributeMaxDynamicSharedMemorySize, FLASH_SMEM);

    dim3 blk(256);
    // 1/sqrt(dh) * log2(e): base-2 softmax with scale folded into Q
    const float scale = 0.08838834764831845f * 1.4426950408889634f;

    // ---- prep: rounds + mask bitmap ----
    {
        int n4 = BB * NQ * CC / 4;
        round_f16<<<(n4 + 255) / 256, blk>>>(query, qin_h, n4);
        n4 = BB * HW * CC / 4;
        round_f16<<<(n4 + 255) / 256, blk>>>(memory, mem_h, n4);
        n4 = CC * CC / 4;
        round_f16<<<(n4 + 255) / 256, blk>>>(Wq, wq_h, n4);
        round_f16<<<(n4 + 255) / 256, blk>>>(Wk, wk_h, n4);
        round_f16<<<(n4 + 255) / 256, blk>>>(Wv, wv_h, n4);
        round_f16<<<(n4 + 255) / 256, blk>>>(Wo, wo_h, n4);
        const int nwords = BB * NQ * HW / 32;       // 524288
        mask_bits<<<nwords / 8, blk>>>(mask, mb, nwords);
    }

    // ---- projections (single-pass fp16) ----
    gemm_f16<<<dim3(CC / 128, (BB * NQ) / 128), blk, GEMM_SMEM>>>(
        qin_h, wq_h, bq, nullptr, q_h, scale);
    gemm_f16<<<dim3(CC / 128, (BB * HW) / 128), blk, GEMM_SMEM>>>(
        mem_h, wk_h, bk, nullptr, k_h, 1.0f);
    gemm_f16<<<dim3(CC / 128, (BB * HW) / 128), blk, GEMM_SMEM>>>(
        mem_h, wv_h, bv, nullptr, v_h, 1.0f);

    // ---- attention ----
    flash_attn_tc5<<<dim3(NQ / 128, HH, BB), blk, FLASH_SMEM>>>(
        q_h, k_h, v_h, mb, a_h);

    // ---- output projection (fp32 out) ----
    gemm_f16<<<dim3(CC / 128, (BB * NQ) / 128), blk, GEMM_SMEM>>>(
        a_h, wo_h, bo, out, nullptr, 1.0f);
}

// round 10
// speedup vs baseline: 7.1007x; 1.0552x over previous
#include <cuda_runtime.h>
#include <cuda_fp16.h>
#include <math.h>
#include <stdint.h>

#define BB 4
#define NQ 1024
#define HW 4096
#define CC 1024
#define HH 8
#define DH 128

typedef __half f16;

// ---------------- scratch (device globals; no allocations allowed) ----------
__device__ f16 s_qin_h[(size_t)BB * NQ * CC];
__device__ f16 s_mem_h[(size_t)BB * HW * CC];
__device__ f16 s_wq_h[(size_t)CC * CC];
__device__ f16 s_wk_h[(size_t)CC * CC];
__device__ f16 s_wv_h[(size_t)CC * CC];
__device__ f16 s_wo_h[(size_t)CC * CC];
__device__ f16 s_q_h[(size_t)BB * NQ * CC];
__device__ f16 s_k_h[(size_t)BB * HW * CC];
__device__ f16 s_v_h[(size_t)BB * HW * CC];
__device__ f16 s_a_h[(size_t)BB * NQ * CC];
__device__ uint32_t s_mbits[(size_t)BB * NQ * HW / 32];

// ============================ helpers =======================================
__device__ __forceinline__ uint32_t smem_u32(const void* p) {
    uint32_t a;
    asm("{ .reg .u64 t; cvta.to.shared.u64 t, %1; cvt.u32.u64 %0, t; }"
        : "=r"(a) : "l"(p));
    return a;
}

__device__ __forceinline__ void ldx4(uint32_t* r, uint32_t addr) {
    asm volatile("ldmatrix.sync.aligned.m8n8.x4.shared.b16 {%0,%1,%2,%3}, [%4];"
                 : "=r"(r[0]), "=r"(r[1]), "=r"(r[2]), "=r"(r[3]) : "r"(addr));
}

__device__ __forceinline__ void ldx4t(uint32_t* r, uint32_t addr) {
    asm volatile("ldmatrix.sync.aligned.m8n8.x4.trans.shared.b16 {%0,%1,%2,%3}, [%4];"
                 : "=r"(r[0]), "=r"(r[1]), "=r"(r[2]), "=r"(r[3]) : "r"(addr));
}

__device__ __forceinline__ void mma_f16(float* c, const uint32_t* a,
                                        uint32_t b0, uint32_t b1) {
    asm volatile(
        "mma.sync.aligned.m16n8k16.row.col.f32.f16.f16.f32 "
        "{%0,%1,%2,%3}, {%4,%5,%6,%7}, {%8,%9}, {%0,%1,%2,%3};"
        : "+f"(c[0]), "+f"(c[1]), "+f"(c[2]), "+f"(c[3])
        : "r"(a[0]), "r"(a[1]), "r"(a[2]), "r"(a[3]), "r"(b0), "r"(b1));
}

__device__ __forceinline__ void cpa16(uint32_t dst, const void* src) {
    asm volatile("cp.async.cg.shared.global [%0], [%1], 16;"
                 :: "r"(dst), "l"(src) : "memory");
}
#define CP_COMMIT() asm volatile("cp.async.commit_group;" ::: "memory")
#define CP_WAIT0()  asm volatile("cp.async.wait_group 0;" ::: "memory")
#define CP_WAIT1()  asm volatile("cp.async.wait_group 1;" ::: "memory")
#define CP_WAIT2()  asm volatile("cp.async.wait_group 2;" ::: "memory")

__device__ __forceinline__ uint32_t packh_hi(float x, float y) {
    __half2 h = __floats2half2_rn(x, y);
    return *(uint32_t*)&h;
}

__device__ __forceinline__ float ex2f(float x) {
    float y;
    asm("ex2.approx.ftz.f32 %0, %1;" : "=f"(y) : "f"(x));
    return y;
}

__device__ __forceinline__ uint32_t swz(int row, int chunk) {
    return (uint32_t)(row * 256 + ((chunk ^ (row & 7)) << 4));
}
__device__ __forceinline__ uint32_t swz128(int row, int chunk) {
    return (uint32_t)(row * 128 + ((chunk ^ (row & 7)) << 4));
}

// ============================================================================
// prep kernels
// ============================================================================
__global__ __launch_bounds__(256)
void round_f16(const float* __restrict__ x, f16* __restrict__ hi, int n4)
{
    int i = blockIdx.x * blockDim.x + threadIdx.x;
    if (i < n4) {
        float4 v = ((const float4*)x)[i];
        __half2 H0 = __floats2half2_rn(v.x, v.y);
        __half2 H1 = __floats2half2_rn(v.z, v.w);
        ((uint2*)hi)[i] = make_uint2(*(uint32_t*)&H0, *(uint32_t*)&H1);
    }
}

// 4 weight tensors in one launch (blockIdx.y selects)
__global__ __launch_bounds__(256)
void round4_f16(const float* __restrict__ x0, f16* __restrict__ y0,
                const float* __restrict__ x1, f16* __restrict__ y1,
                const float* __restrict__ x2, f16* __restrict__ y2,
                const float* __restrict__ x3, f16* __restrict__ y3, int n4)
{
    int i = blockIdx.x * blockDim.x + threadIdx.x;
    if (i >= n4) return;
    const float* x = (blockIdx.y == 0) ? x0 : (blockIdx.y == 1) ? x1
                   : (blockIdx.y == 2) ? x2 : x3;
    f16* y = (blockIdx.y == 0) ? y0 : (blockIdx.y == 1) ? y1
           : (blockIdx.y == 2) ? y2 : y3;
    float4 v = ((const float4*)x)[i];
    __half2 H0 = __floats2half2_rn(v.x, v.y);
    __half2 H1 = __floats2half2_rn(v.z, v.w);
    ((uint2*)y)[i] = make_uint2(*(uint32_t*)&H0, *(uint32_t*)&H1);
}

__global__ __launch_bounds__(256)
void mask_bits(const float* __restrict__ m, uint32_t* __restrict__ out, int nwords)
{
    int w = blockIdx.x * (blockDim.x >> 5) + (threadIdx.x >> 5);
    int lane = threadIdx.x & 31;
    if (w < nwords) {
        float v = m[(size_t)w * 32 + lane];
        uint32_t bits = __ballot_sync(0xffffffffu, v >= 0.5f);
        if (lane == 0) out[w] = bits;
    }
}

// ============================================================================
// GEMM: Y[m,n] = sum_k A[m,k]*B[n,k] + bias[n]  (single-pass fp16)
// CTA 128x128, BK=64, 3-stage cp.async, 2 CTAs/SM. 8 warps (4m x 2n).
// ============================================================================
#define GSTG 32768
#define GEMM_SMEM (3 * GSTG)
#define GNS (CC / 64)

__global__ __launch_bounds__(256, 2)
void gemm_f16(const f16* __restrict__ A, const f16* __restrict__ B,
              const float* __restrict__ bias,
              float* __restrict__ Yf, f16* __restrict__ Yh, float scale)
{
    extern __shared__ char sm[];
    const uint32_t sb = smem_u32(sm);

    const int tid  = threadIdx.x;
    const int wid  = tid >> 5;
    const int lane = tid & 31;
    const int wm = wid & 3;
    const int wn = wid >> 2;
    const int m0 = blockIdx.y * 128;
    const int n0 = blockIdx.x * 128;

    const int lrow = tid >> 1;
    const int lcb  = (tid & 1) * 4;

    const f16* Ap = A + (size_t)(m0 + lrow) * CC;
    const f16* Bp = B + (size_t)(n0 + lrow) * CC;

    float acc[2][8][4];
#pragma unroll
    for (int i = 0; i < 2; i++)
#pragma unroll
        for (int j = 0; j < 8; j++)
#pragma unroll
            for (int k = 0; k < 4; k++) acc[i][j][k] = 0.f;

    const int krow_in = ((lane >> 4) & 1) * 8 + (lane & 7);
    const int kc      = (lane >> 3) & 1;
    const int arow    = wm * 32 + (lane & 15);
    const int ac      = lane >> 4;

    auto issue = [&](int s) {
        const uint32_t stb = sb + (uint32_t)((s % 3) * GSTG);
        const int ko = s * 64;
#pragma unroll
        for (int c = 0; c < 4; c++) {
            const int ch = lcb + c;
            const uint32_t so = swz128(lrow, ch);
            cpa16(stb + so,         Ap + ko + ch * 8);
            cpa16(stb + 16384 + so, Bp + ko + ch * 8);
        }
    };

    issue(0); CP_COMMIT();
    issue(1); CP_COMMIT();

    for (int s = 0; s < GNS; s++) {
        CP_WAIT1();
        __syncthreads();
        if (s + 2 < GNS) issue(s + 2);
        CP_COMMIT();

        const uint32_t stb = sb + (uint32_t)((s % 3) * GSTG);
#pragma unroll
        for (int kt = 0; kt < 4; kt++) {
            uint32_t a_[2][4];
#pragma unroll
            for (int mt = 0; mt < 2; mt++)
                ldx4(a_[mt], stb + swz128(arow + mt * 16, 2 * kt + ac));
#pragma unroll
            for (int np = 0; np < 4; np++) {
                uint32_t b_[4];
                ldx4(b_, stb + 16384 +
                         swz128(wn * 64 + np * 16 + krow_in, 2 * kt + kc));
#pragma unroll
                for (int mt = 0; mt < 2; mt++) {
                    mma_f16(acc[mt][2 * np + 0], a_[mt], b_[0], b_[1]);
                    mma_f16(acc[mt][2 * np + 1], a_[mt], b_[2], b_[3]);
                }
            }
        }
    }

    // ---- epilogue ----
#pragma unroll
    for (int mt = 0; mt < 2; mt++) {
        const int r0 = m0 + wm * 32 + mt * 16 + (lane >> 2);
#pragma unroll
        for (int nt = 0; nt < 8; nt++) {
            const int c = n0 + wn * 64 + nt * 8 + (lane & 3) * 2;
            float2 bv = *(const float2*)(bias + c);
            float y00 = acc[mt][nt][0] + bv.x;
            float y01 = acc[mt][nt][1] + bv.y;
            float y10 = acc[mt][nt][2] + bv.x;
            float y11 = acc[mt][nt][3] + bv.y;
            if (Yf) {
                *(float2*)(Yf + (size_t)r0 * CC + c)       = make_float2(y00, y01);
                *(float2*)(Yf + (size_t)(r0 + 8) * CC + c) = make_float2(y10, y11);
            } else {
                y00 *= scale; y01 *= scale; y10 *= scale; y11 *= scale;
                *(uint32_t*)(Yh + (size_t)r0 * CC + c)       = packh_hi(y00, y01);
                *(uint32_t*)(Yh + (size_t)(r0 + 8) * CC + c) = packh_hi(y10, y11);
            }
        }
    }
}

// ============================================================================
// Flash attention: deferred-PV software pipelining. Single-pass fp16,
// base-2 softmax, bitmask, 5-stage cp.async KV ring (prefetch distance 3).
// At tile i: issue QK(i) MMAs, then PV(i-1) MMAs, THEN softmax(i) —
// softmax latency hides under PV tensor work. q-tile 128, kv 64, 8 warps.
// ============================================================================
#define KVSTG 32768
#define NSTG  5
#define FLASH_SMEM (NSTG * KVSTG)   // 163840
#define NKV (HW / 64)               // 64

__global__ __launch_bounds__(256, 1)
void flash_attn_tc6(const f16* __restrict__ Qh,
                    const f16* __restrict__ Kh, const f16* __restrict__ Vh,
                    const uint32_t* __restrict__ Mb, f16* __restrict__ Oh)
{
    extern __shared__ char sm[];
    const uint32_t sb = smem_u32(sm);

    const int tid  = threadIdx.x;
    const int wid  = tid >> 5;
    const int lane = tid & 31;
    const int q0 = blockIdx.x * 128;
    const int h  = blockIdx.y;
    const int b  = blockIdx.z;

    // ---- stage Q into stage-0 region, extract fragments ----
    {
        const int row = tid >> 1;
        const int cb  = (tid & 1) * 8;
        const f16* qsrc = Qh + (size_t)(b * NQ + q0 + row) * CC + h * DH;
#pragma unroll
        for (int c = 0; c < 8; c++) {
            const int ch = cb + c;
            cpa16(sb + swz(row, ch), qsrc + ch * 8);
        }
        CP_COMMIT();
        CP_WAIT0();
        __syncthreads();
    }

    uint32_t qhf[8][4];
    {
        const int qrow = 16 * wid + (lane & 15);
        const int qc   = lane >> 4;
#pragma unroll
        for (int kt = 0; kt < 8; kt++)
            ldx4(qhf[kt], sb + swz(qrow, 2 * kt + qc));
    }
    __syncthreads();

    const int krow_in = ((lane >> 4) & 1) * 8 + (lane & 7);
    const int kc      = (lane >> 3) & 1;
    const int vrow_in = (lane & 7) + ((lane >> 3) & 1) * 8;
    const int vc      = lane >> 4;

    const int kvrow = tid >> 2;
    const int kvcb  = (tid & 3) * 4;

    const f16* khb = Kh + (size_t)(b * HW + kvrow) * CC + h * DH;
    const f16* vhb = Vh + (size_t)(b * HW + kvrow) * CC + h * DH;

    const int r0l = 16 * wid + (lane >> 2);
    const int mc0 = 2 * (lane & 3);
    const uint32_t* mrow0 = Mb + (size_t)(b * NQ + q0 + r0l) * (HW / 32);
    const uint32_t* mrow1 = mrow0 + (size_t)8 * (HW / 32);

    auto issue = [&](int i) {
        const uint32_t stb = sb + (uint32_t)((i % NSTG) * KVSTG);
        const size_t koff = (size_t)(i * 64) * CC;
#pragma unroll
        for (int c = 0; c < 4; c++) {
            const int ch = kvcb + c;
            const uint32_t so = swz(kvrow, ch);
            cpa16(stb + so,         khb + koff + ch * 8);
            cpa16(stb + 16384 + so, vhb + koff + ch * 8);
        }
    };

    float m0r = -1e30f, m1r = -1e30f, l0r = 0.f, l1r = 0.f;
    float oc[16][4];
#pragma unroll
    for (int n = 0; n < 16; n++)
#pragma unroll
        for (int j = 0; j < 4; j++) oc[n][j] = 0.f;

    uint32_t pah[4][4];           // P_{i-1} fragments, carried across iters

    issue(0); CP_COMMIT();
    issue(1); CP_COMMIT();
    issue(2); CP_COMMIT();

    for (int i = 0; i < NKV; i++) {
        CP_WAIT2();               // completes group i (3 in flight)
        __syncthreads();          // all warps done reading stage i-2
        if (i + 3 < NKV) issue(i + 3);
        CP_COMMIT();

        const uint32_t stb  = sb + (uint32_t)((i % NSTG) * KVSTG);          // K_i
        const uint32_t stbp = sb + (uint32_t)(((i + NSTG - 1) % NSTG) * KVSTG); // V_{i-1}

        const uint2 w0 = *(const uint2*)(mrow0 + i * 2);
        const uint2 w1 = *(const uint2*)(mrow1 + i * 2);

        // ---- 1) S_i = Q K_i^T ----
        float sc[8][4];
#pragma unroll
        for (int n = 0; n < 8; n++)
#pragma unroll
            for (int j = 0; j < 4; j++) sc[n][j] = 0.f;

#pragma unroll
        for (int kt = 0; kt < 8; kt++) {
#pragma unroll
            for (int j = 0; j < 4; j++) {
                uint32_t kh_[4];
                ldx4(kh_, stb + swz(16 * j + krow_in, 2 * kt + kc));
                mma_f16(sc[2 * j + 0], qhf[kt], kh_[0], kh_[1]);
                mma_f16(sc[2 * j + 1], qhf[kt], kh_[2], kh_[3]);
            }
        }

        // ---- 2) O += P_{i-1} V_{i-1} (tensor work hiding softmax below) ----
        if (i > 0) {
#pragma unroll
            for (int kt = 0; kt < 4; kt++) {
#pragma unroll
                for (int np = 0; np < 8; np++) {
                    uint32_t v_[4];
                    ldx4t(v_, stbp + 16384 + swz(16 * kt + vrow_in, 2 * np + vc));
                    mma_f16(oc[2 * np + 0], pah[kt], v_[0], v_[1]);
                    mma_f16(oc[2 * np + 1], pah[kt], v_[2], v_[3]);
                }
            }
        }

        // ---- 3) mask + online softmax (base-2), hidden under PV ----
        float mx0 = m0r, mx1 = m1r;
#pragma unroll
        for (int n = 0; n < 8; n++) {
            const uint32_t wa = (n < 4) ? w0.x : w0.y;
            const uint32_t wb = (n < 4) ? w1.x : w1.y;
            const int pos = (n & 3) * 8 + mc0;
            sc[n][0] = ((wa >> pos) & 1u)       ? sc[n][0] : -1e30f;
            sc[n][1] = ((wa >> (pos + 1)) & 1u) ? sc[n][1] : -1e30f;
            sc[n][2] = ((wb >> pos) & 1u)       ? sc[n][2] : -1e30f;
            sc[n][3] = ((wb >> (pos + 1)) & 1u) ? sc[n][3] : -1e30f;
            mx0 = fmaxf(mx0, fmaxf(sc[n][0], sc[n][1]));
            mx1 = fmaxf(mx1, fmaxf(sc[n][2], sc[n][3]));
        }
        mx0 = fmaxf(mx0, __shfl_xor_sync(0xffffffffu, mx0, 1));
        mx0 = fmaxf(mx0, __shfl_xor_sync(0xffffffffu, mx0, 2));
        mx1 = fmaxf(mx1, __shfl_xor_sync(0xffffffffu, mx1, 1));
        mx1 = fmaxf(mx1, __shfl_xor_sync(0xffffffffu, mx1, 2));

        const float alpha0 = ex2f(m0r - mx0);
        const float alpha1 = ex2f(m1r - mx1);
        m0r = mx0; m1r = mx1;

        float rs0 = 0.f, rs1 = 0.f;
#pragma unroll
        for (int n = 0; n < 8; n++) {
            sc[n][0] = ex2f(sc[n][0] - mx0);
            sc[n][1] = ex2f(sc[n][1] - mx0);
            sc[n][2] = ex2f(sc[n][2] - mx1);
            sc[n][3] = ex2f(sc[n][3] - mx1);
            rs0 += sc[n][0] + sc[n][1];
            rs1 += sc[n][2] + sc[n][3];
        }
        rs0 += __shfl_xor_sync(0xffffffffu, rs0, 1);
        rs0 += __shfl_xor_sync(0xffffffffu, rs0, 2);
        rs1 += __shfl_xor_sync(0xffffffffu, rs1, 1);
        rs1 += __shfl_xor_sync(0xffffffffu, rs1, 2);
        l0r = l0r * alpha0 + rs0;
        l1r = l1r * alpha1 + rs1;

        // ---- 4) O *= alpha_i (after PV_{i-1} adds, program order) ----
#pragma unroll
        for (int n = 0; n < 16; n++) {
            oc[n][0] *= alpha0; oc[n][1] *= alpha0;
            oc[n][2] *= alpha1; oc[n][3] *= alpha1;
        }

        // ---- 5) pack P_i for next iteration ----
#pragma unroll
        for (int kt = 0; kt < 4; kt++) {
            pah[kt][0] = packh_hi(sc[2 * kt][0],     sc[2 * kt][1]);
            pah[kt][1] = packh_hi(sc[2 * kt][2],     sc[2 * kt][3]);
            pah[kt][2] = packh_hi(sc[2 * kt + 1][0], sc[2 * kt + 1][1]);
            pah[kt][3] = packh_hi(sc[2 * kt + 1][2], sc[2 * kt + 1][3]);
        }
    }

    // ---- tail: O += P_{last} V_{last} ----
    {
        const uint32_t stbl = sb + (uint32_t)(((NKV - 1) % NSTG) * KVSTG);
#pragma unroll
        for (int kt = 0; kt < 4; kt++) {
#pragma unroll
            for (int np = 0; np < 8; np++) {
                uint32_t v_[4];
                ldx4t(v_, stbl + 16384 + swz(16 * kt + vrow_in, 2 * np + vc));
                mma_f16(oc[2 * np + 0], pah[kt], v_[0], v_[1]);
                mma_f16(oc[2 * np + 1], pah[kt], v_[2], v_[3]);
            }
        }
    }

    // ---- normalize, write fp16 ----
    const float rl0 = 1.0f / l0r;
    const float rl1 = 1.0f / l1r;
    const size_t rbase0 = (size_t)(b * NQ + q0 + r0l) * CC + h * DH;
    const size_t rbase1 = rbase0 + (size_t)8 * CC;
#pragma unroll
    for (int n = 0; n < 16; n++) {
        const int c = n * 8 + mc0;
        *(uint32_t*)(Oh + rbase0 + c) = packh_hi(oc[n][0] * rl0, oc[n][1] * rl0);
        *(uint32_t*)(Oh + rbase1 + c) = packh_hi(oc[n][2] * rl1, oc[n][3] * rl1);
    }
}

// ---------------------------------------------------------------------------
extern "C" void kernel_launch(void* const* d_in, const int* in_sizes, int n_in,
                              void* d_out, int out_size)
{
    const float* query  = (const float*)d_in[0];
    const float* memory = (const float*)d_in[1];
    const float* mask   = (const float*)d_in[2];
    const float* Wq = (const float*)d_in[3];
    const float* bq = (const float*)d_in[4];
    const float* Wk = (const float*)d_in[5];
    const float* bk = (const float*)d_in[6];
    const float* Wv = (const float*)d_in[7];
    const float* bv = (const float*)d_in[8];
    const float* Wo = (const float*)d_in[9];
    const float* bo = (const float*)d_in[10];
    float* out = (float*)d_out;

    f16 *qin_h, *mem_h, *wq_h, *wk_h, *wv_h, *wo_h;
    f16 *q_h, *k_h, *v_h, *a_h;
    uint32_t* mb;
    cudaGetSymbolAddress((void**)&qin_h, s_qin_h);
    cudaGetSymbolAddress((void**)&mem_h, s_mem_h);
    cudaGetSymbolAddress((void**)&wq_h, s_wq_h);
    cudaGetSymbolAddress((void**)&wk_h, s_wk_h);
    cudaGetSymbolAddress((void**)&wv_h, s_wv_h);
    cudaGetSymbolAddress((void**)&wo_h, s_wo_h);
    cudaGetSymbolAddress((void**)&q_h, s_q_h);
    cudaGetSymbolAddress((void**)&k_h, s_k_h);
    cudaGetSymbolAddress((void**)&v_h, s_v_h);
    cudaGetSymbolAddress((void**)&a_h, s_a_h);
    cudaGetSymbolAddress((void**)&mb, s_mbits);

    cudaFuncSetAttribute(gemm_f16,
                         cudaFuncAttributeMaxDynamicSharedMemorySize, GEMM_SMEM);
    cudaFuncSetAttribute(flash_attn_tc6,
                         cudaFuncAttributeMaxDynamicSharedMemorySize, FLASH_SMEM);

    dim3 blk(256);
    const float scale = 0.08838834764831845f * 1.4426950408889634f;

    // ---- prep ----
    {
        int n4 = BB * NQ * CC / 4;
        round_f16<<<(n4 + 255) / 256, blk>>>(query, qin_h, n4);
        n4 = BB * HW * CC / 4;
        round_f16<<<(n4 + 255) / 256, blk>>>(memory, mem_h, n4);
        n4 = CC * CC / 4;
        round4_f16<<<dim3((n4 + 255) / 256, 4), blk>>>(
            Wq, wq_h, Wk, wk_h, Wv, wv_h, Wo, wo_h, n4);
        const int nwords = BB * NQ * HW / 32;
        mask_bits<<<nwords / 8, blk>>>(mask, mb, nwords);
    }

    // ---- projections ----
    gemm_f16<<<dim3(CC / 128, (BB * NQ) / 128), blk, GEMM_SMEM>>>(
        qin_h, wq_h, bq, nullptr, q_h, scale);
    gemm_f16<<<dim3(CC / 128, (BB * HW) / 128), blk, GEMM_SMEM>>>(
        mem_h, wk_h, bk, nullptr, k_h, 1.0f);
    gemm_f16<<<dim3(CC / 128, (BB * HW) / 128), blk, GEMM_SMEM>>>(
        mem_h, wv_h, bv, nullptr, v_h, 1.0f);

    // ---- attention ----
    flash_attn_tc6<<<dim3(NQ / 128, HH, BB), blk, FLASH_SMEM>>>(
        q_h, k_h, v_h, mb, a_h);

    // ---- output projection ----
    gemm_f16<<<dim3(CC / 128, (BB * NQ) / 128), blk, GEMM_SMEM>>>(
        a_h, wo_h, bo, out, nullptr, 1.0f);
}

// round 11
// speedup vs baseline: 7.4066x; 1.0431x over previous
#include <cuda_runtime.h>
#include <cuda_fp16.h>
#include <math.h>
#include <stdint.h>

#define BB 4
#define NQ 1024
#define HW 4096
#define CC 1024
#define HH 8
#define DH 128

typedef __half f16;

// ---------------- scratch (device globals; no allocations allowed) ----------
__device__ f16 s_qin_h[(size_t)BB * NQ * CC];
__device__ f16 s_mem_h[(size_t)BB * HW * CC];
__device__ f16 s_wq_h[(size_t)CC * CC];
__device__ f16 s_wk_h[(size_t)CC * CC];
__device__ f16 s_wv_h[(size_t)CC * CC];
__device__ f16 s_wo_h[(size_t)CC * CC];
__device__ f16 s_q_h[(size_t)BB * NQ * CC];
__device__ f16 s_k_h[(size_t)BB * HW * CC];
__device__ f16 s_v_h[(size_t)BB * HW * CC];
__device__ f16 s_a_h[(size_t)BB * NQ * CC];
__device__ uint32_t s_mbits[(size_t)BB * NQ * HW / 32];

// ============================ helpers =======================================
__device__ __forceinline__ uint32_t smem_u32(const void* p) {
    uint32_t a;
    asm("{ .reg .u64 t; cvta.to.shared.u64 t, %1; cvt.u32.u64 %0, t; }"
        : "=r"(a) : "l"(p));
    return a;
}

__device__ __forceinline__ void ldx4(uint32_t* r, uint32_t addr) {
    asm volatile("ldmatrix.sync.aligned.m8n8.x4.shared.b16 {%0,%1,%2,%3}, [%4];"
                 : "=r"(r[0]), "=r"(r[1]), "=r"(r[2]), "=r"(r[3]) : "r"(addr));
}

__device__ __forceinline__ void ldx4t(uint32_t* r, uint32_t addr) {
    asm volatile("ldmatrix.sync.aligned.m8n8.x4.trans.shared.b16 {%0,%1,%2,%3}, [%4];"
                 : "=r"(r[0]), "=r"(r[1]), "=r"(r[2]), "=r"(r[3]) : "r"(addr));
}

__device__ __forceinline__ void mma_f16(float* c, const uint32_t* a,
                                        uint32_t b0, uint32_t b1) {
    asm volatile(
        "mma.sync.aligned.m16n8k16.row.col.f32.f16.f16.f32 "
        "{%0,%1,%2,%3}, {%4,%5,%6,%7}, {%8,%9}, {%0,%1,%2,%3};"
        : "+f"(c[0]), "+f"(c[1]), "+f"(c[2]), "+f"(c[3])
        : "r"(a[0]), "r"(a[1]), "r"(a[2]), "r"(a[3]), "r"(b0), "r"(b1));
}

__device__ __forceinline__ void cpa16(uint32_t dst, const void* src) {
    asm volatile("cp.async.cg.shared.global [%0], [%1], 16;"
                 :: "r"(dst), "l"(src) : "memory");
}
#define CP_COMMIT() asm volatile("cp.async.commit_group;" ::: "memory")
#define CP_WAIT0()  asm volatile("cp.async.wait_group 0;" ::: "memory")
#define CP_WAIT1()  asm volatile("cp.async.wait_group 1;" ::: "memory")
#define CP_WAIT2()  asm volatile("cp.async.wait_group 2;" ::: "memory")

__device__ __forceinline__ uint32_t packh_hi(float x, float y) {
    __half2 h = __floats2half2_rn(x, y);
    return *(uint32_t*)&h;
}

__device__ __forceinline__ float ex2f(float x) {
    float y;
    asm("ex2.approx.ftz.f32 %0, %1;" : "=f"(y) : "f"(x));
    return y;
}

__device__ __forceinline__ uint32_t swz(int row, int chunk) {
    return (uint32_t)(row * 256 + ((chunk ^ (row & 7)) << 4));
}
__device__ __forceinline__ uint32_t swz128(int row, int chunk) {
    return (uint32_t)(row * 128 + ((chunk ^ (row & 7)) << 4));
}

// ============================================================================
// prep kernels
// ============================================================================
// 2x float4 per thread for higher MLP
__global__ __launch_bounds__(256)
void round_f16(const float* __restrict__ x, f16* __restrict__ hi, int n4)
{
    int i = (blockIdx.x * blockDim.x + threadIdx.x) * 2;
    if (i + 1 < n4) {
        float4 v0 = ((const float4*)x)[i];
        float4 v1 = ((const float4*)x)[i + 1];
        __half2 a0 = __floats2half2_rn(v0.x, v0.y);
        __half2 a1 = __floats2half2_rn(v0.z, v0.w);
        __half2 a2 = __floats2half2_rn(v1.x, v1.y);
        __half2 a3 = __floats2half2_rn(v1.z, v1.w);
        ((uint4*)hi)[i >> 1] = make_uint4(*(uint32_t*)&a0, *(uint32_t*)&a1,
                                          *(uint32_t*)&a2, *(uint32_t*)&a3);
    } else if (i < n4) {
        float4 v0 = ((const float4*)x)[i];
        __half2 a0 = __floats2half2_rn(v0.x, v0.y);
        __half2 a1 = __floats2half2_rn(v0.z, v0.w);
        ((uint2*)hi)[i] = make_uint2(*(uint32_t*)&a0, *(uint32_t*)&a1);
    }
}

// 4 weight tensors in one launch (blockIdx.y selects)
__global__ __launch_bounds__(256)
void round4_f16(const float* __restrict__ x0, f16* __restrict__ y0,
                const float* __restrict__ x1, f16* __restrict__ y1,
                const float* __restrict__ x2, f16* __restrict__ y2,
                const float* __restrict__ x3, f16* __restrict__ y3, int n4)
{
    int i = blockIdx.x * blockDim.x + threadIdx.x;
    if (i >= n4) return;
    const float* x = (blockIdx.y == 0) ? x0 : (blockIdx.y == 1) ? x1
                   : (blockIdx.y == 2) ? x2 : x3;
    f16* y = (blockIdx.y == 0) ? y0 : (blockIdx.y == 1) ? y1
           : (blockIdx.y == 2) ? y2 : y3;
    float4 v = ((const float4*)x)[i];
    __half2 H0 = __floats2half2_rn(v.x, v.y);
    __half2 H1 = __floats2half2_rn(v.z, v.w);
    ((uint2*)y)[i] = make_uint2(*(uint32_t*)&H0, *(uint32_t*)&H1);
}

// mask fp32 -> bitmap: one thread builds one 32-bit word (8x float4, MLP=8)
__global__ __launch_bounds__(256)
void mask_bits(const float* __restrict__ m, uint32_t* __restrict__ out, int nwords)
{
    int w = blockIdx.x * blockDim.x + threadIdx.x;
    if (w >= nwords) return;
    const float4* p = (const float4*)(m + (size_t)w * 32);
    float4 v[8];
#pragma unroll
    for (int j = 0; j < 8; j++) v[j] = p[j];
    uint32_t bits = 0;
#pragma unroll
    for (int j = 0; j < 8; j++) {
        bits |= (v[j].x >= 0.5f ? (1u << (j * 4 + 0)) : 0u);
        bits |= (v[j].y >= 0.5f ? (1u << (j * 4 + 1)) : 0u);
        bits |= (v[j].z >= 0.5f ? (1u << (j * 4 + 2)) : 0u);
        bits |= (v[j].w >= 0.5f ? (1u << (j * 4 + 3)) : 0u);
    }
    out[w] = bits;
}

// ============================================================================
// GEMM: Y[m,n] = sum_k A[m,k]*B[n,k] + bias[n]  (single-pass fp16)
// CTA 128x128, BK=64, 3-stage cp.async, 2 CTAs/SM. 8 warps (4m x 2n).
// ============================================================================
#define GSTG 32768
#define GEMM_SMEM (3 * GSTG)
#define GNS (CC / 64)

__global__ __launch_bounds__(256, 2)
void gemm_f16(const f16* __restrict__ A, const f16* __restrict__ B,
              const float* __restrict__ bias,
              float* __restrict__ Yf, f16* __restrict__ Yh, float scale)
{
    extern __shared__ char sm[];
    const uint32_t sb = smem_u32(sm);

    const int tid  = threadIdx.x;
    const int wid  = tid >> 5;
    const int lane = tid & 31;
    const int wm = wid & 3;
    const int wn = wid >> 2;
    const int m0 = blockIdx.y * 128;
    const int n0 = blockIdx.x * 128;

    const int lrow = tid >> 1;
    const int lcb  = (tid & 1) * 4;

    const f16* Ap = A + (size_t)(m0 + lrow) * CC;
    const f16* Bp = B + (size_t)(n0 + lrow) * CC;

    float acc[2][8][4];
#pragma unroll
    for (int i = 0; i < 2; i++)
#pragma unroll
        for (int j = 0; j < 8; j++)
#pragma unroll
            for (int k = 0; k < 4; k++) acc[i][j][k] = 0.f;

    const int krow_in = ((lane >> 4) & 1) * 8 + (lane & 7);
    const int kc      = (lane >> 3) & 1;
    const int arow    = wm * 32 + (lane & 15);
    const int ac      = lane >> 4;

    auto issue = [&](int s) {
        const uint32_t stb = sb + (uint32_t)((s % 3) * GSTG);
        const int ko = s * 64;
#pragma unroll
        for (int c = 0; c < 4; c++) {
            const int ch = lcb + c;
            const uint32_t so = swz128(lrow, ch);
            cpa16(stb + so,         Ap + ko + ch * 8);
            cpa16(stb + 16384 + so, Bp + ko + ch * 8);
        }
    };

    issue(0); CP_COMMIT();
    issue(1); CP_COMMIT();

    for (int s = 0; s < GNS; s++) {
        CP_WAIT1();
        __syncthreads();
        if (s + 2 < GNS) issue(s + 2);
        CP_COMMIT();

        const uint32_t stb = sb + (uint32_t)((s % 3) * GSTG);
#pragma unroll
        for (int kt = 0; kt < 4; kt++) {
            uint32_t a_[2][4];
#pragma unroll
            for (int mt = 0; mt < 2; mt++)
                ldx4(a_[mt], stb + swz128(arow + mt * 16, 2 * kt + ac));
#pragma unroll
            for (int np = 0; np < 4; np++) {
                uint32_t b_[4];
                ldx4(b_, stb + 16384 +
                         swz128(wn * 64 + np * 16 + krow_in, 2 * kt + kc));
#pragma unroll
                for (int mt = 0; mt < 2; mt++) {
                    mma_f16(acc[mt][2 * np + 0], a_[mt], b_[0], b_[1]);
                    mma_f16(acc[mt][2 * np + 1], a_[mt], b_[2], b_[3]);
                }
            }
        }
    }

    // ---- epilogue ----
#pragma unroll
    for (int mt = 0; mt < 2; mt++) {
        const int r0 = m0 + wm * 32 + mt * 16 + (lane >> 2);
#pragma unroll
        for (int nt = 0; nt < 8; nt++) {
            const int c = n0 + wn * 64 + nt * 8 + (lane & 3) * 2;
            float2 bv = *(const float2*)(bias + c);
            float y00 = acc[mt][nt][0] + bv.x;
            float y01 = acc[mt][nt][1] + bv.y;
            float y10 = acc[mt][nt][2] + bv.x;
            float y11 = acc[mt][nt][3] + bv.y;
            if (Yf) {
                *(float2*)(Yf + (size_t)r0 * CC + c)       = make_float2(y00, y01);
                *(float2*)(Yf + (size_t)(r0 + 8) * CC + c) = make_float2(y10, y11);
            } else {
                y00 *= scale; y01 *= scale; y10 *= scale; y11 *= scale;
                *(uint32_t*)(Yh + (size_t)r0 * CC + c)       = packh_hi(y00, y01);
                *(uint32_t*)(Yh + (size_t)(r0 + 8) * CC + c) = packh_hi(y10, y11);
            }
        }
    }
}

// ============================================================================
// Flash attention: deferred-PV software pipelining (unchanged from R10).
// ============================================================================
#define KVSTG 32768
#define NSTG  5
#define FLASH_SMEM (NSTG * KVSTG)   // 163840
#define NKV (HW / 64)               // 64

__global__ __launch_bounds__(256, 1)
void flash_attn_tc6(const f16* __restrict__ Qh,
                    const f16* __restrict__ Kh, const f16* __restrict__ Vh,
                    const uint32_t* __restrict__ Mb, f16* __restrict__ Oh)
{
    extern __shared__ char sm[];
    const uint32_t sb = smem_u32(sm);

    const int tid  = threadIdx.x;
    const int wid  = tid >> 5;
    const int lane = tid & 31;
    const int q0 = blockIdx.x * 128;
    const int h  = blockIdx.y;
    const int b  = blockIdx.z;

    // ---- stage Q, extract fragments ----
    {
        const int row = tid >> 1;
        const int cb  = (tid & 1) * 8;
        const f16* qsrc = Qh + (size_t)(b * NQ + q0 + row) * CC + h * DH;
#pragma unroll
        for (int c = 0; c < 8; c++) {
            const int ch = cb + c;
            cpa16(sb + swz(row, ch), qsrc + ch * 8);
        }
        CP_COMMIT();
        CP_WAIT0();
        __syncthreads();
    }

    uint32_t qhf[8][4];
    {
        const int qrow = 16 * wid + (lane & 15);
        const int qc   = lane >> 4;
#pragma unroll
        for (int kt = 0; kt < 8; kt++)
            ldx4(qhf[kt], sb + swz(qrow, 2 * kt + qc));
    }
    __syncthreads();

    const int krow_in = ((lane >> 4) & 1) * 8 + (lane & 7);
    const int kc      = (lane >> 3) & 1;
    const int vrow_in = (lane & 7) + ((lane >> 3) & 1) * 8;
    const int vc      = lane >> 4;

    const int kvrow = tid >> 2;
    const int kvcb  = (tid & 3) * 4;

    const f16* khb = Kh + (size_t)(b * HW + kvrow) * CC + h * DH;
    const f16* vhb = Vh + (size_t)(b * HW + kvrow) * CC + h * DH;

    const int r0l = 16 * wid + (lane >> 2);
    const int mc0 = 2 * (lane & 3);
    const uint32_t* mrow0 = Mb + (size_t)(b * NQ + q0 + r0l) * (HW / 32);
    const uint32_t* mrow1 = mrow0 + (size_t)8 * (HW / 32);

    auto issue = [&](int i) {
        const uint32_t stb = sb + (uint32_t)((i % NSTG) * KVSTG);
        const size_t koff = (size_t)(i * 64) * CC;
#pragma unroll
        for (int c = 0; c < 4; c++) {
            const int ch = kvcb + c;
            const uint32_t so = swz(kvrow, ch);
            cpa16(stb + so,         khb + koff + ch * 8);
            cpa16(stb + 16384 + so, vhb + koff + ch * 8);
        }
    };

    float m0r = -1e30f, m1r = -1e30f, l0r = 0.f, l1r = 0.f;
    float oc[16][4];
#pragma unroll
    for (int n = 0; n < 16; n++)
#pragma unroll
        for (int j = 0; j < 4; j++) oc[n][j] = 0.f;

    uint32_t pah[4][4];

    issue(0); CP_COMMIT();
    issue(1); CP_COMMIT();
    issue(2); CP_COMMIT();

    for (int i = 0; i < NKV; i++) {
        CP_WAIT2();
        __syncthreads();
        if (i + 3 < NKV) issue(i + 3);
        CP_COMMIT();

        const uint32_t stb  = sb + (uint32_t)((i % NSTG) * KVSTG);
        const uint32_t stbp = sb + (uint32_t)(((i + NSTG - 1) % NSTG) * KVSTG);

        const uint2 w0 = *(const uint2*)(mrow0 + i * 2);
        const uint2 w1 = *(const uint2*)(mrow1 + i * 2);

        // ---- 1) S_i = Q K_i^T ----
        float sc[8][4];
#pragma unroll
        for (int n = 0; n < 8; n++)
#pragma unroll
            for (int j = 0; j < 4; j++) sc[n][j] = 0.f;

#pragma unroll
        for (int kt = 0; kt < 8; kt++) {
#pragma unroll
            for (int j = 0; j < 4; j++) {
                uint32_t kh_[4];
                ldx4(kh_, stb + swz(16 * j + krow_in, 2 * kt + kc));
                mma_f16(sc[2 * j + 0], qhf[kt], kh_[0], kh_[1]);
                mma_f16(sc[2 * j + 1], qhf[kt], kh_[2], kh_[3]);
            }
        }

        // ---- 2) O += P_{i-1} V_{i-1} ----
        if (i > 0) {
#pragma unroll
            for (int kt = 0; kt < 4; kt++) {
#pragma unroll
                for (int np = 0; np < 8; np++) {
                    uint32_t v_[4];
                    ldx4t(v_, stbp + 16384 + swz(16 * kt + vrow_in, 2 * np + vc));
                    mma_f16(oc[2 * np + 0], pah[kt], v_[0], v_[1]);
                    mma_f16(oc[2 * np + 1], pah[kt], v_[2], v_[3]);
                }
            }
        }

        // ---- 3) mask + online softmax (base-2) ----
        float mx0 = m0r, mx1 = m1r;
#pragma unroll
        for (int n = 0; n < 8; n++) {
            const uint32_t wa = (n < 4) ? w0.x : w0.y;
            const uint32_t wb = (n < 4) ? w1.x : w1.y;
            const int pos = (n & 3) * 8 + mc0;
            sc[n][0] = ((wa >> pos) & 1u)       ? sc[n][0] : -1e30f;
            sc[n][1] = ((wa >> (pos + 1)) & 1u) ? sc[n][1] : -1e30f;
            sc[n][2] = ((wb >> pos) & 1u)       ? sc[n][2] : -1e30f;
            sc[n][3] = ((wb >> (pos + 1)) & 1u) ? sc[n][3] : -1e30f;
            mx0 = fmaxf(mx0, fmaxf(sc[n][0], sc[n][1]));
            mx1 = fmaxf(mx1, fmaxf(sc[n][2], sc[n][3]));
        }
        mx0 = fmaxf(mx0, __shfl_xor_sync(0xffffffffu, mx0, 1));
        mx0 = fmaxf(mx0, __shfl_xor_sync(0xffffffffu, mx0, 2));
        mx1 = fmaxf(mx1, __shfl_xor_sync(0xffffffffu, mx1, 1));
        mx1 = fmaxf(mx1, __shfl_xor_sync(0xffffffffu, mx1, 2));

        const float alpha0 = ex2f(m0r - mx0);
        const float alpha1 = ex2f(m1r - mx1);
        m0r = mx0; m1r = mx1;

        float rs0 = 0.f, rs1 = 0.f;
#pragma unroll
        for (int n = 0; n < 8; n++) {
            sc[n][0] = ex2f(sc[n][0] - mx0);
            sc[n][1] = ex2f(sc[n][1] - mx0);
            sc[n][2] = ex2f(sc[n][2] - mx1);
            sc[n][3] = ex2f(sc[n][3] - mx1);
            rs0 += sc[n][0] + sc[n][1];
            rs1 += sc[n][2] + sc[n][3];
        }
        rs0 += __shfl_xor_sync(0xffffffffu, rs0, 1);
        rs0 += __shfl_xor_sync(0xffffffffu, rs0, 2);
        rs1 += __shfl_xor_sync(0xffffffffu, rs1, 1);
        rs1 += __shfl_xor_sync(0xffffffffu, rs1, 2);
        l0r = l0r * alpha0 + rs0;
        l1r = l1r * alpha1 + rs1;

        // ---- 4) O *= alpha_i ----
#pragma unroll
        for (int n = 0; n < 16; n++) {
            oc[n][0] *= alpha0; oc[n][1] *= alpha0;
            oc[n][2] *= alpha1; oc[n][3] *= alpha1;
        }

        // ---- 5) pack P_i ----
#pragma unroll
        for (int kt = 0; kt < 4; kt++) {
            pah[kt][0] = packh_hi(sc[2 * kt][0],     sc[2 * kt][1]);
            pah[kt][1] = packh_hi(sc[2 * kt][2],     sc[2 * kt][3]);
            pah[kt][2] = packh_hi(sc[2 * kt + 1][0], sc[2 * kt + 1][1]);
            pah[kt][3] = packh_hi(sc[2 * kt + 1][2], sc[2 * kt + 1][3]);
        }
    }

    // ---- tail PV ----
    {
        const uint32_t stbl = sb + (uint32_t)(((NKV - 1) % NSTG) * KVSTG);
#pragma unroll
        for (int kt = 0; kt < 4; kt++) {
#pragma unroll
            for (int np = 0; np < 8; np++) {
                uint32_t v_[4];
                ldx4t(v_, stbl + 16384 + swz(16 * kt + vrow_in, 2 * np + vc));
                mma_f16(oc[2 * np + 0], pah[kt], v_[0], v_[1]);
                mma_f16(oc[2 * np + 1], pah[kt], v_[2], v_[3]);
            }
        }
    }

    // ---- normalize, write fp16 ----
    const float rl0 = 1.0f / l0r;
    const float rl1 = 1.0f / l1r;
    const size_t rbase0 = (size_t)(b * NQ + q0 + r0l) * CC + h * DH;
    const size_t rbase1 = rbase0 + (size_t)8 * CC;
#pragma unroll
    for (int n = 0; n < 16; n++) {
        const int c = n * 8 + mc0;
        *(uint32_t*)(Oh + rbase0 + c) = packh_hi(oc[n][0] * rl0, oc[n][1] * rl0);
        *(uint32_t*)(Oh + rbase1 + c) = packh_hi(oc[n][2] * rl1, oc[n][3] * rl1);
    }
}

// ---------------------------------------------------------------------------
extern "C" void kernel_launch(void* const* d_in, const int* in_sizes, int n_in,
                              void* d_out, int out_size)
{
    const float* query  = (const float*)d_in[0];
    const float* memory = (const float*)d_in[1];
    const float* mask   = (const float*)d_in[2];
    const float* Wq = (const float*)d_in[3];
    const float* bq = (const float*)d_in[4];
    const float* Wk = (const float*)d_in[5];
    const float* bk = (const float*)d_in[6];
    const float* Wv = (const float*)d_in[7];
    const float* bv = (const float*)d_in[8];
    const float* Wo = (const float*)d_in[9];
    const float* bo = (const float*)d_in[10];
    float* out = (float*)d_out;

    f16 *qin_h, *mem_h, *wq_h, *wk_h, *wv_h, *wo_h;
    f16 *q_h, *k_h, *v_h, *a_h;
    uint32_t* mb;
    cudaGetSymbolAddress((void**)&qin_h, s_qin_h);
    cudaGetSymbolAddress((void**)&mem_h, s_mem_h);
    cudaGetSymbolAddress((void**)&wq_h, s_wq_h);
    cudaGetSymbolAddress((void**)&wk_h, s_wk_h);
    cudaGetSymbolAddress((void**)&wv_h, s_wv_h);
    cudaGetSymbolAddress((void**)&wo_h, s_wo_h);
    cudaGetSymbolAddress((void**)&q_h, s_q_h);
    cudaGetSymbolAddress((void**)&k_h, s_k_h);
    cudaGetSymbolAddress((void**)&v_h, s_v_h);
    cudaGetSymbolAddress((void**)&a_h, s_a_h);
    cudaGetSymbolAddress((void**)&mb, s_mbits);

    cudaFuncSetAttribute(gemm_f16,
                         cudaFuncAttributeMaxDynamicSharedMemorySize, GEMM_SMEM);
    cudaFuncSetAttribute(flash_attn_tc6,
                         cudaFuncAttributeMaxDynamicSharedMemorySize, FLASH_SMEM);

    dim3 blk(256);
    const float scale = 0.08838834764831845f * 1.4426950408889634f;

    // ---- prep ----
    {
        int n4 = BB * NQ * CC / 4;
        round_f16<<<(n4 / 2 + 255) / 256, blk>>>(query, qin_h, n4);
        n4 = BB * HW * CC / 4;
        round_f16<<<(n4 / 2 + 255) / 256, blk>>>(memory, mem_h, n4);
        n4 = CC * CC / 4;
        round4_f16<<<dim3((n4 + 255) / 256, 4), blk>>>(
            Wq, wq_h, Wk, wk_h, Wv, wv_h, Wo, wo_h, n4);
        const int nwords = BB * NQ * HW / 32;
        mask_bits<<<(nwords + 255) / 256, blk>>>(mask, mb, nwords);
    }

    // ---- projections ----
    gemm_f16<<<dim3(CC / 128, (BB * NQ) / 128), blk, GEMM_SMEM>>>(
        qin_h, wq_h, bq, nullptr, q_h, scale);
    gemm_f16<<<dim3(CC / 128, (BB * HW) / 128), blk, GEMM_SMEM>>>(
        mem_h, wk_h, bk, nullptr, k_h, 1.0f);
    gemm_f16<<<dim3(CC / 128, (BB * HW) / 128), blk, GEMM_SMEM>>>(
        mem_h, wv_h, bv, nullptr, v_h, 1.0f);

    // ---- attention ----
    flash_attn_tc6<<<dim3(NQ / 128, HH, BB), blk, FLASH_SMEM>>>(
        q_h, k_h, v_h, mb, a_h);

    // ---- output projection ----
    gemm_f16<<<dim3(CC / 128, (BB * NQ) / 128), blk, GEMM_SMEM>>>(
        a_h, wo_h, bo, out, nullptr, 1.0f);
}

// round 12
// speedup vs baseline: 7.4766x; 1.0094x over previous
#include <cuda_runtime.h>
#include <cuda_fp16.h>
#include <math.h>
#include <stdint.h>

#define BB 4
#define NQ 1024
#define HW 4096
#define CC 1024
#define HH 8
#define DH 128

typedef __half f16;

// ---------------- scratch (device globals; no allocations allowed) ----------
__device__ f16 s_qin_h[(size_t)BB * NQ * CC];
__device__ f16 s_mem_h[(size_t)BB * HW * CC];
__device__ f16 s_wq_h[(size_t)CC * CC];
__device__ f16 s_wk_h[(size_t)CC * CC];
__device__ f16 s_wv_h[(size_t)CC * CC];
__device__ f16 s_wo_h[(size_t)CC * CC];
__device__ f16 s_q_h[(size_t)BB * NQ * CC];
__device__ f16 s_k_h[(size_t)BB * HW * CC];
__device__ f16 s_v_h[(size_t)BB * HW * CC];
__device__ f16 s_a_h[(size_t)BB * NQ * CC];
__device__ uint32_t s_mbits[(size_t)BB * NQ * HW / 32];

// ============================ helpers =======================================
__device__ __forceinline__ uint32_t smem_u32(const void* p) {
    uint32_t a;
    asm("{ .reg .u64 t; cvta.to.shared.u64 t, %1; cvt.u32.u64 %0, t; }"
        : "=r"(a) : "l"(p));
    return a;
}

__device__ __forceinline__ void ldx4(uint32_t* r, uint32_t addr) {
    asm volatile("ldmatrix.sync.aligned.m8n8.x4.shared.b16 {%0,%1,%2,%3}, [%4];"
                 : "=r"(r[0]), "=r"(r[1]), "=r"(r[2]), "=r"(r[3]) : "r"(addr));
}

__device__ __forceinline__ void ldx4t(uint32_t* r, uint32_t addr) {
    asm volatile("ldmatrix.sync.aligned.m8n8.x4.trans.shared.b16 {%0,%1,%2,%3}, [%4];"
                 : "=r"(r[0]), "=r"(r[1]), "=r"(r[2]), "=r"(r[3]) : "r"(addr));
}

__device__ __forceinline__ void mma_f16(float* c, const uint32_t* a,
                                        uint32_t b0, uint32_t b1) {
    asm volatile(
        "mma.sync.aligned.m16n8k16.row.col.f32.f16.f16.f32 "
        "{%0,%1,%2,%3}, {%4,%5,%6,%7}, {%8,%9}, {%0,%1,%2,%3};"
        : "+f"(c[0]), "+f"(c[1]), "+f"(c[2]), "+f"(c[3])
        : "r"(a[0]), "r"(a[1]), "r"(a[2]), "r"(a[3]), "r"(b0), "r"(b1));
}

__device__ __forceinline__ void cpa16(uint32_t dst, const void* src) {
    asm volatile("cp.async.cg.shared.global [%0], [%1], 16;"
                 :: "r"(dst), "l"(src) : "memory");
}
#define CP_COMMIT() asm volatile("cp.async.commit_group;" ::: "memory")
#define CP_WAIT0()  asm volatile("cp.async.wait_group 0;" ::: "memory")
#define CP_WAIT1()  asm volatile("cp.async.wait_group 1;" ::: "memory")

__device__ __forceinline__ uint32_t packh_hi(float x, float y) {
    __half2 h = __floats2half2_rn(x, y);
    return *(uint32_t*)&h;
}

__device__ __forceinline__ float ex2f(float x) {
    float y;
    asm("ex2.approx.ftz.f32 %0, %1;" : "=f"(y) : "f"(x));
    return y;
}

__device__ __forceinline__ uint32_t swz(int row, int chunk) {
    return (uint32_t)(row * 256 + ((chunk ^ (row & 7)) << 4));
}
__device__ __forceinline__ uint32_t swz128(int row, int chunk) {
    return (uint32_t)(row * 128 + ((chunk ^ (row & 7)) << 4));
}

// ============================================================================
// prep kernels (unchanged from R11)
// ============================================================================
__global__ __launch_bounds__(256)
void round_f16(const float* __restrict__ x, f16* __restrict__ hi, int n4)
{
    int i = (blockIdx.x * blockDim.x + threadIdx.x) * 2;
    if (i + 1 < n4) {
        float4 v0 = ((const float4*)x)[i];
        float4 v1 = ((const float4*)x)[i + 1];
        __half2 a0 = __floats2half2_rn(v0.x, v0.y);
        __half2 a1 = __floats2half2_rn(v0.z, v0.w);
        __half2 a2 = __floats2half2_rn(v1.x, v1.y);
        __half2 a3 = __floats2half2_rn(v1.z, v1.w);
        ((uint4*)hi)[i >> 1] = make_uint4(*(uint32_t*)&a0, *(uint32_t*)&a1,
                                          *(uint32_t*)&a2, *(uint32_t*)&a3);
    } else if (i < n4) {
        float4 v0 = ((const float4*)x)[i];
        __half2 a0 = __floats2half2_rn(v0.x, v0.y);
        __half2 a1 = __floats2half2_rn(v0.z, v0.w);
        ((uint2*)hi)[i] = make_uint2(*(uint32_t*)&a0, *(uint32_t*)&a1);
    }
}

__global__ __launch_bounds__(256)
void round4_f16(const float* __restrict__ x0, f16* __restrict__ y0,
                const float* __restrict__ x1, f16* __restrict__ y1,
                const float* __restrict__ x2, f16* __restrict__ y2,
                const float* __restrict__ x3, f16* __restrict__ y3, int n4)
{
    int i = blockIdx.x * blockDim.x + threadIdx.x;
    if (i >= n4) return;
    const float* x = (blockIdx.y == 0) ? x0 : (blockIdx.y == 1) ? x1
                   : (blockIdx.y == 2) ? x2 : x3;
    f16* y = (blockIdx.y == 0) ? y0 : (blockIdx.y == 1) ? y1
           : (blockIdx.y == 2) ? y2 : y3;
    float4 v = ((const float4*)x)[i];
    __half2 H0 = __floats2half2_rn(v.x, v.y);
    __half2 H1 = __floats2half2_rn(v.z, v.w);
    ((uint2*)y)[i] = make_uint2(*(uint32_t*)&H0, *(uint32_t*)&H1);
}

__global__ __launch_bounds__(256)
void mask_bits(const float* __restrict__ m, uint32_t* __restrict__ out, int nwords)
{
    int w = blockIdx.x * blockDim.x + threadIdx.x;
    if (w >= nwords) return;
    const float4* p = (const float4*)(m + (size_t)w * 32);
    float4 v[8];
#pragma unroll
    for (int j = 0; j < 8; j++) v[j] = p[j];
    uint32_t bits = 0;
#pragma unroll
    for (int j = 0; j < 8; j++) {
        bits |= (v[j].x >= 0.5f ? (1u << (j * 4 + 0)) : 0u);
        bits |= (v[j].y >= 0.5f ? (1u << (j * 4 + 1)) : 0u);
        bits |= (v[j].z >= 0.5f ? (1u << (j * 4 + 2)) : 0u);
        bits |= (v[j].w >= 0.5f ? (1u << (j * 4 + 3)) : 0u);
    }
    out[w] = bits;
}

// ============================================================================
// GEMM (unchanged from R11)
// ============================================================================
#define GSTG 32768
#define GEMM_SMEM (3 * GSTG)
#define GNS (CC / 64)

__global__ __launch_bounds__(256, 2)
void gemm_f16(const f16* __restrict__ A, const f16* __restrict__ B,
              const float* __restrict__ bias,
              float* __restrict__ Yf, f16* __restrict__ Yh, float scale)
{
    extern __shared__ char sm[];
    const uint32_t sb = smem_u32(sm);

    const int tid  = threadIdx.x;
    const int wid  = tid >> 5;
    const int lane = tid & 31;
    const int wm = wid & 3;
    const int wn = wid >> 2;
    const int m0 = blockIdx.y * 128;
    const int n0 = blockIdx.x * 128;

    const int lrow = tid >> 1;
    const int lcb  = (tid & 1) * 4;

    const f16* Ap = A + (size_t)(m0 + lrow) * CC;
    const f16* Bp = B + (size_t)(n0 + lrow) * CC;

    float acc[2][8][4];
#pragma unroll
    for (int i = 0; i < 2; i++)
#pragma unroll
        for (int j = 0; j < 8; j++)
#pragma unroll
            for (int k = 0; k < 4; k++) acc[i][j][k] = 0.f;

    const int krow_in = ((lane >> 4) & 1) * 8 + (lane & 7);
    const int kc      = (lane >> 3) & 1;
    const int arow    = wm * 32 + (lane & 15);
    const int ac      = lane >> 4;

    auto issue = [&](int s) {
        const uint32_t stb = sb + (uint32_t)((s % 3) * GSTG);
        const int ko = s * 64;
#pragma unroll
        for (int c = 0; c < 4; c++) {
            const int ch = lcb + c;
            const uint32_t so = swz128(lrow, ch);
            cpa16(stb + so,         Ap + ko + ch * 8);
            cpa16(stb + 16384 + so, Bp + ko + ch * 8);
        }
    };

    issue(0); CP_COMMIT();
    issue(1); CP_COMMIT();

    for (int s = 0; s < GNS; s++) {
        CP_WAIT1();
        __syncthreads();
        if (s + 2 < GNS) issue(s + 2);
        CP_COMMIT();

        const uint32_t stb = sb + (uint32_t)((s % 3) * GSTG);
#pragma unroll
        for (int kt = 0; kt < 4; kt++) {
            uint32_t a_[2][4];
#pragma unroll
            for (int mt = 0; mt < 2; mt++)
                ldx4(a_[mt], stb + swz128(arow + mt * 16, 2 * kt + ac));
#pragma unroll
            for (int np = 0; np < 4; np++) {
                uint32_t b_[4];
                ldx4(b_, stb + 16384 +
                         swz128(wn * 64 + np * 16 + krow_in, 2 * kt + kc));
#pragma unroll
                for (int mt = 0; mt < 2; mt++) {
                    mma_f16(acc[mt][2 * np + 0], a_[mt], b_[0], b_[1]);
                    mma_f16(acc[mt][2 * np + 1], a_[mt], b_[2], b_[3]);
                }
            }
        }
    }

#pragma unroll
    for (int mt = 0; mt < 2; mt++) {
        const int r0 = m0 + wm * 32 + mt * 16 + (lane >> 2);
#pragma unroll
        for (int nt = 0; nt < 8; nt++) {
            const int c = n0 + wn * 64 + nt * 8 + (lane & 3) * 2;
            float2 bv = *(const float2*)(bias + c);
            float y00 = acc[mt][nt][0] + bv.x;
            float y01 = acc[mt][nt][1] + bv.y;
            float y10 = acc[mt][nt][2] + bv.x;
            float y11 = acc[mt][nt][3] + bv.y;
            if (Yf) {
                *(float2*)(Yf + (size_t)r0 * CC + c)       = make_float2(y00, y01);
                *(float2*)(Yf + (size_t)(r0 + 8) * CC + c) = make_float2(y10, y11);
            } else {
                y00 *= scale; y01 *= scale; y10 *= scale; y11 *= scale;
                *(uint32_t*)(Yh + (size_t)r0 * CC + c)       = packh_hi(y00, y01);
                *(uint32_t*)(Yh + (size_t)(r0 + 8) * CC + c) = packh_hi(y10, y11);
            }
        }
    }
}

// ============================================================================
// Flash attention v7: 2 CTAs/SM (single wave over 256 CTAs).
// Resident Q smem region (32KB) + 2-stage KV ring (2x32KB) = 96KB/CTA.
// Q re-ldmatrix'd per tile (no register residency); in-order softmax->PV;
// cross-CTA overlap hides softmax + load latency. Regs capped at 128.
// ============================================================================
#define KVSTG 32768
#define QRGN  32768
#define FLASH_SMEM (QRGN + 2 * KVSTG)   // 98304
#define NKV (HW / 64)                   // 64

__global__ __launch_bounds__(256, 2)
void flash_attn_tc7(const f16* __restrict__ Qh,
                    const f16* __restrict__ Kh, const f16* __restrict__ Vh,
                    const uint32_t* __restrict__ Mb, f16* __restrict__ Oh)
{
    extern __shared__ char sm[];
    const uint32_t sb = smem_u32(sm);

    const int tid  = threadIdx.x;
    const int wid  = tid >> 5;
    const int lane = tid & 31;
    const int q0 = blockIdx.x * 128;
    const int h  = blockIdx.y;
    const int b  = blockIdx.z;

    // ---- stage Q into resident region [0, 32KB) ----
    {
        const int row = tid >> 1;
        const int cb  = (tid & 1) * 8;
        const f16* qsrc = Qh + (size_t)(b * NQ + q0 + row) * CC + h * DH;
#pragma unroll
        for (int c = 0; c < 8; c++) {
            const int ch = cb + c;
            cpa16(sb + swz(row, ch), qsrc + ch * 8);
        }
        CP_COMMIT();
    }

    const int qrow = 16 * wid + (lane & 15);
    const int qc   = lane >> 4;

    const int krow_in = ((lane >> 4) & 1) * 8 + (lane & 7);
    const int kc      = (lane >> 3) & 1;
    const int vrow_in = (lane & 7) + ((lane >> 3) & 1) * 8;
    const int vc      = lane >> 4;

    const int kvrow = tid >> 2;
    const int kvcb  = (tid & 3) * 4;

    const f16* khb = Kh + (size_t)(b * HW + kvrow) * CC + h * DH;
    const f16* vhb = Vh + (size_t)(b * HW + kvrow) * CC + h * DH;

    const int r0l = 16 * wid + (lane >> 2);
    const int mc0 = 2 * (lane & 3);
    const uint32_t* mrow0 = Mb + (size_t)(b * NQ + q0 + r0l) * (HW / 32);
    const uint32_t* mrow1 = mrow0 + (size_t)8 * (HW / 32);

    auto issue = [&](int i) {
        const uint32_t stb = sb + QRGN + (uint32_t)((i & 1) * KVSTG);
        const size_t koff = (size_t)(i * 64) * CC;
#pragma unroll
        for (int c = 0; c < 4; c++) {
            const int ch = kvcb + c;
            const uint32_t so = swz(kvrow, ch);
            cpa16(stb + so,         khb + koff + ch * 8);
            cpa16(stb + 16384 + so, vhb + koff + ch * 8);
        }
    };

    float m0r = -1e30f, m1r = -1e30f, l0r = 0.f, l1r = 0.f;
    float oc[16][4];
#pragma unroll
    for (int n = 0; n < 16; n++)
#pragma unroll
        for (int j = 0; j < 4; j++) oc[n][j] = 0.f;

    issue(0); CP_COMMIT();   // group 1 = Q (group 0) then KV0

    for (int i = 0; i < NKV; i++) {
        CP_WAIT0();               // Q + all issued KV complete
        __syncthreads();          // stage (i+1)&1 readers (iter i-1) done
        if (i + 1 < NKV) issue(i + 1);
        CP_COMMIT();

        const uint32_t stb = sb + QRGN + (uint32_t)((i & 1) * KVSTG);

        const uint2 w0 = *(const uint2*)(mrow0 + i * 2);
        const uint2 w1 = *(const uint2*)(mrow1 + i * 2);

        // ---- S = Q K^T (Q from resident smem) ----
        float sc[8][4];
#pragma unroll
        for (int n = 0; n < 8; n++)
#pragma unroll
            for (int j = 0; j < 4; j++) sc[n][j] = 0.f;

#pragma unroll
        for (int kt = 0; kt < 8; kt++) {
            uint32_t qh_[4];
            ldx4(qh_, sb + swz(qrow, 2 * kt + qc));
#pragma unroll
            for (int j = 0; j < 4; j++) {
                uint32_t kh_[4];
                ldx4(kh_, stb + swz(16 * j + krow_in, 2 * kt + kc));
                mma_f16(sc[2 * j + 0], qh_, kh_[0], kh_[1]);
                mma_f16(sc[2 * j + 1], qh_, kh_[2], kh_[3]);
            }
        }

        // ---- mask + online softmax (base-2) ----
        float mx0 = m0r, mx1 = m1r;
#pragma unroll
        for (int n = 0; n < 8; n++) {
            const uint32_t wa = (n < 4) ? w0.x : w0.y;
            const uint32_t wb = (n < 4) ? w1.x : w1.y;
            const int pos = (n & 3) * 8 + mc0;
            sc[n][0] = ((wa >> pos) & 1u)       ? sc[n][0] : -1e30f;
            sc[n][1] = ((wa >> (pos + 1)) & 1u) ? sc[n][1] : -1e30f;
            sc[n][2] = ((wb >> pos) & 1u)       ? sc[n][2] : -1e30f;
            sc[n][3] = ((wb >> (pos + 1)) & 1u) ? sc[n][3] : -1e30f;
            mx0 = fmaxf(mx0, fmaxf(sc[n][0], sc[n][1]));
            mx1 = fmaxf(mx1, fmaxf(sc[n][2], sc[n][3]));
        }
        mx0 = fmaxf(mx0, __shfl_xor_sync(0xffffffffu, mx0, 1));
        mx0 = fmaxf(mx0, __shfl_xor_sync(0xffffffffu, mx0, 2));
        mx1 = fmaxf(mx1, __shfl_xor_sync(0xffffffffu, mx1, 1));
        mx1 = fmaxf(mx1, __shfl_xor_sync(0xffffffffu, mx1, 2));

        const float alpha0 = ex2f(m0r - mx0);
        const float alpha1 = ex2f(m1r - mx1);
        m0r = mx0; m1r = mx1;

        float rs0 = 0.f, rs1 = 0.f;
#pragma unroll
        for (int n = 0; n < 8; n++) {
            sc[n][0] = ex2f(sc[n][0] - mx0);
            sc[n][1] = ex2f(sc[n][1] - mx0);
            sc[n][2] = ex2f(sc[n][2] - mx1);
            sc[n][3] = ex2f(sc[n][3] - mx1);
            rs0 += sc[n][0] + sc[n][1];
            rs1 += sc[n][2] + sc[n][3];
        }
        rs0 += __shfl_xor_sync(0xffffffffu, rs0, 1);
        rs0 += __shfl_xor_sync(0xffffffffu, rs0, 2);
        rs1 += __shfl_xor_sync(0xffffffffu, rs1, 1);
        rs1 += __shfl_xor_sync(0xffffffffu, rs1, 2);
        l0r = l0r * alpha0 + rs0;
        l1r = l1r * alpha1 + rs1;

        // ---- pack P; rescale O ----
        uint32_t pah[4][4];
#pragma unroll
        for (int kt = 0; kt < 4; kt++) {
            pah[kt][0] = packh_hi(sc[2 * kt][0],     sc[2 * kt][1]);
            pah[kt][1] = packh_hi(sc[2 * kt][2],     sc[2 * kt][3]);
            pah[kt][2] = packh_hi(sc[2 * kt + 1][0], sc[2 * kt + 1][1]);
            pah[kt][3] = packh_hi(sc[2 * kt + 1][2], sc[2 * kt + 1][3]);
        }
#pragma unroll
        for (int n = 0; n < 16; n++) {
            oc[n][0] *= alpha0; oc[n][1] *= alpha0;
            oc[n][2] *= alpha1; oc[n][3] *= alpha1;
        }

        // ---- O += P @ V ----
#pragma unroll
        for (int kt = 0; kt < 4; kt++) {
#pragma unroll
            for (int np = 0; np < 8; np++) {
                uint32_t v_[4];
                ldx4t(v_, stb + 16384 + swz(16 * kt + vrow_in, 2 * np + vc));
                mma_f16(oc[2 * np + 0], pah[kt], v_[0], v_[1]);
                mma_f16(oc[2 * np + 1], pah[kt], v_[2], v_[3]);
            }
        }
    }

    // ---- normalize, write fp16 ----
    const float rl0 = 1.0f / l0r;
    const float rl1 = 1.0f / l1r;
    const size_t rbase0 = (size_t)(b * NQ + q0 + r0l) * CC + h * DH;
    const size_t rbase1 = rbase0 + (size_t)8 * CC;
#pragma unroll
    for (int n = 0; n < 16; n++) {
        const int c = n * 8 + mc0;
        *(uint32_t*)(Oh + rbase0 + c) = packh_hi(oc[n][0] * rl0, oc[n][1] * rl0);
        *(uint32_t*)(Oh + rbase1 + c) = packh_hi(oc[n][2] * rl1, oc[n][3] * rl1);
    }
}

// ---------------------------------------------------------------------------
extern "C" void kernel_launch(void* const* d_in, const int* in_sizes, int n_in,
                              void* d_out, int out_size)
{
    const float* query  = (const float*)d_in[0];
    const float* memory = (const float*)d_in[1];
    const float* mask   = (const float*)d_in[2];
    const float* Wq = (const float*)d_in[3];
    const float* bq = (const float*)d_in[4];
    const float* Wk = (const float*)d_in[5];
    const float* bk = (const float*)d_in[6];
    const float* Wv = (const float*)d_in[7];
    const float* bv = (const float*)d_in[8];
    const float* Wo = (const float*)d_in[9];
    const float* bo = (const float*)d_in[10];
    float* out = (float*)d_out;

    f16 *qin_h, *mem_h, *wq_h, *wk_h, *wv_h, *wo_h;
    f16 *q_h, *k_h, *v_h, *a_h;
    uint32_t* mb;
    cudaGetSymbolAddress((void**)&qin_h, s_qin_h);
    cudaGetSymbolAddress((void**)&mem_h, s_mem_h);
    cudaGetSymbolAddress((void**)&wq_h, s_wq_h);
    cudaGetSymbolAddress((void**)&wk_h, s_wk_h);
    cudaGetSymbolAddress((void**)&wv_h, s_wv_h);
    cudaGetSymbolAddress((void**)&wo_h, s_wo_h);
    cudaGetSymbolAddress((void**)&q_h, s_q_h);
    cudaGetSymbolAddress((void**)&k_h, s_k_h);
    cudaGetSymbolAddress((void**)&v_h, s_v_h);
    cudaGetSymbolAddress((void**)&a_h, s_a_h);
    cudaGetSymbolAddress((void**)&mb, s_mbits);

    cudaFuncSetAttribute(gemm_f16,
                         cudaFuncAttributeMaxDynamicSharedMemorySize, GEMM_SMEM);
    cudaFuncSetAttribute(flash_attn_tc7,
                         cudaFuncAttributeMaxDynamicSharedMemorySize, FLASH_SMEM);

    dim3 blk(256);
    const float scale = 0.08838834764831845f * 1.4426950408889634f;

    // ---- prep ----
    {
        int n4 = BB * NQ * CC / 4;
        round_f16<<<(n4 / 2 + 255) / 256, blk>>>(query, qin_h, n4);
        n4 = BB * HW * CC / 4;
        round_f16<<<(n4 / 2 + 255) / 256, blk>>>(memory, mem_h, n4);
        n4 = CC * CC / 4;
        round4_f16<<<dim3((n4 + 255) / 256, 4), blk>>>(
            Wq, wq_h, Wk, wk_h, Wv, wv_h, Wo, wo_h, n4);
        const int nwords = BB * NQ * HW / 32;
        mask_bits<<<(nwords + 255) / 256, blk>>>(mask, mb, nwords);
    }

    // ---- projections ----
    gemm_f16<<<dim3(CC / 128, (BB * NQ) / 128), blk, GEMM_SMEM>>>(
        qin_h, wq_h, bq, nullptr, q_h, scale);
    gemm_f16<<<dim3(CC / 128, (BB * HW) / 128), blk, GEMM_SMEM>>>(
        mem_h, wk_h, bk, nullptr, k_h, 1.0f);
    gemm_f16<<<dim3(CC / 128, (BB * HW) / 128), blk, GEMM_SMEM>>>(
        mem_h, wv_h, bv, nullptr, v_h, 1.0f);

    // ---- attention (2 CTAs/SM, single wave) ----
    flash_attn_tc7<<<dim3(NQ / 128, HH, BB), blk, FLASH_SMEM>>>(
        q_h, k_h, v_h, mb, a_h);

    // ---- output projection ----
    gemm_f16<<<dim3(CC / 128, (BB * NQ) / 128), blk, GEMM_SMEM>>>(
        a_h, wo_h, bo, out, nullptr, 1.0f);
}

// round 13
// speedup vs baseline: 7.5988x; 1.0163x over previous
#include <cuda_runtime.h>
#include <cuda_fp16.h>
#include <math.h>
#include <stdint.h>

#define BB 4
#define NQ 1024
#define HW 4096
#define CC 1024
#define HH 8
#define DH 128

typedef __half f16;

// ---------------- scratch (device globals; no allocations allowed) ----------
__device__ f16 s_qin_h[(size_t)BB * NQ * CC];
__device__ f16 s_mem_h[(size_t)BB * HW * CC];
__device__ f16 s_wq_h[(size_t)CC * CC];
__device__ f16 s_wk_h[(size_t)CC * CC];
__device__ f16 s_wv_h[(size_t)CC * CC];
__device__ f16 s_wo_h[(size_t)CC * CC];
__device__ f16 s_q_h[(size_t)BB * NQ * CC];
__device__ f16 s_k_h[(size_t)BB * HW * CC];
__device__ f16 s_v_h[(size_t)BB * HW * CC];
__device__ f16 s_a_h[(size_t)BB * NQ * CC];
__device__ uint32_t s_mbits[(size_t)BB * NQ * HW / 32];

// ============================ helpers =======================================
__device__ __forceinline__ uint32_t smem_u32(const void* p) {
    uint32_t a;
    asm("{ .reg .u64 t; cvta.to.shared.u64 t, %1; cvt.u32.u64 %0, t; }"
        : "=r"(a) : "l"(p));
    return a;
}

__device__ __forceinline__ void ldx4(uint32_t* r, uint32_t addr) {
    asm volatile("ldmatrix.sync.aligned.m8n8.x4.shared.b16 {%0,%1,%2,%3}, [%4];"
                 : "=r"(r[0]), "=r"(r[1]), "=r"(r[2]), "=r"(r[3]) : "r"(addr));
}

__device__ __forceinline__ void ldx4t(uint32_t* r, uint32_t addr) {
    asm volatile("ldmatrix.sync.aligned.m8n8.x4.trans.shared.b16 {%0,%1,%2,%3}, [%4];"
                 : "=r"(r[0]), "=r"(r[1]), "=r"(r[2]), "=r"(r[3]) : "r"(addr));
}

__device__ __forceinline__ void mma_f16(float* c, const uint32_t* a,
                                        uint32_t b0, uint32_t b1) {
    asm volatile(
        "mma.sync.aligned.m16n8k16.row.col.f32.f16.f16.f32 "
        "{%0,%1,%2,%3}, {%4,%5,%6,%7}, {%8,%9}, {%0,%1,%2,%3};"
        : "+f"(c[0]), "+f"(c[1]), "+f"(c[2]), "+f"(c[3])
        : "r"(a[0]), "r"(a[1]), "r"(a[2]), "r"(a[3]), "r"(b0), "r"(b1));
}

__device__ __forceinline__ void cpa16(uint32_t dst, const void* src) {
    asm volatile("cp.async.cg.shared.global [%0], [%1], 16;"
                 :: "r"(dst), "l"(src) : "memory");
}
#define CP_COMMIT() asm volatile("cp.async.commit_group;" ::: "memory")
#define CP_WAIT0()  asm volatile("cp.async.wait_group 0;" ::: "memory")
#define CP_WAIT1()  asm volatile("cp.async.wait_group 1;" ::: "memory")

__device__ __forceinline__ uint32_t packh_hi(float x, float y) {
    __half2 h = __floats2half2_rn(x, y);
    return *(uint32_t*)&h;
}

__device__ __forceinline__ float ex2f(float x) {
    float y;
    asm("ex2.approx.ftz.f32 %0, %1;" : "=f"(y) : "f"(x));
    return y;
}

__device__ __forceinline__ uint32_t swz(int row, int chunk) {
    return (uint32_t)(row * 256 + ((chunk ^ (row & 7)) << 4));
}
__device__ __forceinline__ uint32_t swz128(int row, int chunk) {
    return (uint32_t)(row * 128 + ((chunk ^ (row & 7)) << 4));
}

// ============================================================================
// prep kernels
// ============================================================================
// All six fp32->fp16 rounds in ONE launch. Segment map is compile-time.
// Units: one thread handles 2 float4 (8 floats) -> one uint4 store.
#define N4P_Q (BB * NQ * CC / 8)      // 524288 pairs
#define N4P_M (BB * HW * CC / 8)      // 2097152
#define N4P_W (CC * CC / 8)           // 131072
#define N4P_TOTAL (N4P_Q + N4P_M + 4 * N4P_W)   // 3145728

__global__ __launch_bounds__(256)
void round_all(const float* __restrict__ q,  f16* __restrict__ qo,
               const float* __restrict__ m,  f16* __restrict__ mo,
               const float* __restrict__ w0, f16* __restrict__ o0,
               const float* __restrict__ w1, f16* __restrict__ o1,
               const float* __restrict__ w2, f16* __restrict__ o2,
               const float* __restrict__ w3, f16* __restrict__ o3)
{
    size_t p = (size_t)blockIdx.x * blockDim.x + threadIdx.x;
    if (p >= (size_t)N4P_TOTAL) return;
    const float* x;
    f16* y;
    size_t off;
    if (p < N4P_Q) {
        x = q; y = qo; off = p;
    } else if (p < (size_t)N4P_Q + N4P_M) {
        x = m; y = mo; off = p - N4P_Q;
    } else {
        size_t r = p - N4P_Q - N4P_M;
        int ws = (int)(r / N4P_W);
        off = r % N4P_W;
        x = (ws == 0) ? w0 : (ws == 1) ? w1 : (ws == 2) ? w2 : w3;
        y = (ws == 0) ? o0 : (ws == 1) ? o1 : (ws == 2) ? o2 : o3;
    }
    const size_t i = off * 2;
    float4 v0 = ((const float4*)x)[i];
    float4 v1 = ((const float4*)x)[i + 1];
    __half2 a0 = __floats2half2_rn(v0.x, v0.y);
    __half2 a1 = __floats2half2_rn(v0.z, v0.w);
    __half2 a2 = __floats2half2_rn(v1.x, v1.y);
    __half2 a3 = __floats2half2_rn(v1.z, v1.w);
    ((uint4*)y)[off] = make_uint4(*(uint32_t*)&a0, *(uint32_t*)&a1,
                                  *(uint32_t*)&a2, *(uint32_t*)&a3);
}

// mask fp32 -> bitmap: one thread builds one 32-bit word (8x float4, MLP=8)
__global__ __launch_bounds__(256)
void mask_bits(const float* __restrict__ m, uint32_t* __restrict__ out, int nwords)
{
    int w = blockIdx.x * blockDim.x + threadIdx.x;
    if (w >= nwords) return;
    const float4* p = (const float4*)(m + (size_t)w * 32);
    float4 v[8];
#pragma unroll
    for (int j = 0; j < 8; j++) v[j] = p[j];
    uint32_t bits = 0;
#pragma unroll
    for (int j = 0; j < 8; j++) {
        bits |= (v[j].x >= 0.5f ? (1u << (j * 4 + 0)) : 0u);
        bits |= (v[j].y >= 0.5f ? (1u << (j * 4 + 1)) : 0u);
        bits |= (v[j].z >= 0.5f ? (1u << (j * 4 + 2)) : 0u);
        bits |= (v[j].w >= 0.5f ? (1u << (j * 4 + 3)) : 0u);
    }
    out[w] = bits;
}

// ============================================================================
// GEMM (unchanged from R11/R12)
// ============================================================================
#define GSTG 32768
#define GEMM_SMEM (3 * GSTG)
#define GNS (CC / 64)

__global__ __launch_bounds__(256, 2)
void gemm_f16(const f16* __restrict__ A, const f16* __restrict__ B,
              const float* __restrict__ bias,
              float* __restrict__ Yf, f16* __restrict__ Yh, float scale)
{
    extern __shared__ char sm[];
    const uint32_t sb = smem_u32(sm);

    const int tid  = threadIdx.x;
    const int wid  = tid >> 5;
    const int lane = tid & 31;
    const int wm = wid & 3;
    const int wn = wid >> 2;
    const int m0 = blockIdx.y * 128;
    const int n0 = blockIdx.x * 128;

    const int lrow = tid >> 1;
    const int lcb  = (tid & 1) * 4;

    const f16* Ap = A + (size_t)(m0 + lrow) * CC;
    const f16* Bp = B + (size_t)(n0 + lrow) * CC;

    float acc[2][8][4];
#pragma unroll
    for (int i = 0; i < 2; i++)
#pragma unroll
        for (int j = 0; j < 8; j++)
#pragma unroll
            for (int k = 0; k < 4; k++) acc[i][j][k] = 0.f;

    const int krow_in = ((lane >> 4) & 1) * 8 + (lane & 7);
    const int kc      = (lane >> 3) & 1;
    const int arow    = wm * 32 + (lane & 15);
    const int ac      = lane >> 4;

    auto issue = [&](int s) {
        const uint32_t stb = sb + (uint32_t)((s % 3) * GSTG);
        const int ko = s * 64;
#pragma unroll
        for (int c = 0; c < 4; c++) {
            const int ch = lcb + c;
            const uint32_t so = swz128(lrow, ch);
            cpa16(stb + so,         Ap + ko + ch * 8);
            cpa16(stb + 16384 + so, Bp + ko + ch * 8);
        }
    };

    issue(0); CP_COMMIT();
    issue(1); CP_COMMIT();

    for (int s = 0; s < GNS; s++) {
        CP_WAIT1();
        __syncthreads();
        if (s + 2 < GNS) issue(s + 2);
        CP_COMMIT();

        const uint32_t stb = sb + (uint32_t)((s % 3) * GSTG);
#pragma unroll
        for (int kt = 0; kt < 4; kt++) {
            uint32_t a_[2][4];
#pragma unroll
            for (int mt = 0; mt < 2; mt++)
                ldx4(a_[mt], stb + swz128(arow + mt * 16, 2 * kt + ac));
#pragma unroll
            for (int np = 0; np < 4; np++) {
                uint32_t b_[4];
                ldx4(b_, stb + 16384 +
                         swz128(wn * 64 + np * 16 + krow_in, 2 * kt + kc));
#pragma unroll
                for (int mt = 0; mt < 2; mt++) {
                    mma_f16(acc[mt][2 * np + 0], a_[mt], b_[0], b_[1]);
                    mma_f16(acc[mt][2 * np + 1], a_[mt], b_[2], b_[3]);
                }
            }
        }
    }

#pragma unroll
    for (int mt = 0; mt < 2; mt++) {
        const int r0 = m0 + wm * 32 + mt * 16 + (lane >> 2);
#pragma unroll
        for (int nt = 0; nt < 8; nt++) {
            const int c = n0 + wn * 64 + nt * 8 + (lane & 3) * 2;
            float2 bv = *(const float2*)(bias + c);
            float y00 = acc[mt][nt][0] + bv.x;
            float y01 = acc[mt][nt][1] + bv.y;
            float y10 = acc[mt][nt][2] + bv.x;
            float y11 = acc[mt][nt][3] + bv.y;
            if (Yf) {
                *(float2*)(Yf + (size_t)r0 * CC + c)       = make_float2(y00, y01);
                *(float2*)(Yf + (size_t)(r0 + 8) * CC + c) = make_float2(y10, y11);
            } else {
                y00 *= scale; y01 *= scale; y10 *= scale; y11 *= scale;
                *(uint32_t*)(Yh + (size_t)r0 * CC + c)       = packh_hi(y00, y01);
                *(uint32_t*)(Yh + (size_t)(r0 + 8) * CC + c) = packh_hi(y10, y11);
            }
        }
    }
}

// ============================================================================
// Flash attention v7 (unchanged from R12): 2 CTAs/SM, resident Q smem,
// 2-stage KV ring, in-order softmax->PV, base-2 softmax, bitmask mask.
// ============================================================================
#define KVSTG 32768
#define QRGN  32768
#define FLASH_SMEM (QRGN + 2 * KVSTG)   // 98304
#define NKV (HW / 64)                   // 64

__global__ __launch_bounds__(256, 2)
void flash_attn_tc7(const f16* __restrict__ Qh,
                    const f16* __restrict__ Kh, const f16* __restrict__ Vh,
                    const uint32_t* __restrict__ Mb, f16* __restrict__ Oh)
{
    extern __shared__ char sm[];
    const uint32_t sb = smem_u32(sm);

    const int tid  = threadIdx.x;
    const int wid  = tid >> 5;
    const int lane = tid & 31;
    const int q0 = blockIdx.x * 128;
    const int h  = blockIdx.y;
    const int b  = blockIdx.z;

    // ---- stage Q into resident region [0, 32KB) ----
    {
        const int row = tid >> 1;
        const int cb  = (tid & 1) * 8;
        const f16* qsrc = Qh + (size_t)(b * NQ + q0 + row) * CC + h * DH;
#pragma unroll
        for (int c = 0; c < 8; c++) {
            const int ch = cb + c;
            cpa16(sb + swz(row, ch), qsrc + ch * 8);
        }
        CP_COMMIT();
    }

    const int qrow = 16 * wid + (lane & 15);
    const int qc   = lane >> 4;

    const int krow_in = ((lane >> 4) & 1) * 8 + (lane & 7);
    const int kc      = (lane >> 3) & 1;
    const int vrow_in = (lane & 7) + ((lane >> 3) & 1) * 8;
    const int vc      = lane >> 4;

    const int kvrow = tid >> 2;
    const int kvcb  = (tid & 3) * 4;

    const f16* khb = Kh + (size_t)(b * HW + kvrow) * CC + h * DH;
    const f16* vhb = Vh + (size_t)(b * HW + kvrow) * CC + h * DH;

    const int r0l = 16 * wid + (lane >> 2);
    const int mc0 = 2 * (lane & 3);
    const uint32_t* mrow0 = Mb + (size_t)(b * NQ + q0 + r0l) * (HW / 32);
    const uint32_t* mrow1 = mrow0 + (size_t)8 * (HW / 32);

    auto issue = [&](int i) {
        const uint32_t stb = sb + QRGN + (uint32_t)((i & 1) * KVSTG);
        const size_t koff = (size_t)(i * 64) * CC;
#pragma unroll
        for (int c = 0; c < 4; c++) {
            const int ch = kvcb + c;
            const uint32_t so = swz(kvrow, ch);
            cpa16(stb + so,         khb + koff + ch * 8);
            cpa16(stb + 16384 + so, vhb + koff + ch * 8);
        }
    };

    float m0r = -1e30f, m1r = -1e30f, l0r = 0.f, l1r = 0.f;
    float oc[16][4];
#pragma unroll
    for (int n = 0; n < 16; n++)
#pragma unroll
        for (int j = 0; j < 4; j++) oc[n][j] = 0.f;

    issue(0); CP_COMMIT();

    for (int i = 0; i < NKV; i++) {
        CP_WAIT0();
        __syncthreads();
        if (i + 1 < NKV) issue(i + 1);
        CP_COMMIT();

        const uint32_t stb = sb + QRGN + (uint32_t)((i & 1) * KVSTG);

        const uint2 w0 = *(const uint2*)(mrow0 + i * 2);
        const uint2 w1 = *(const uint2*)(mrow1 + i * 2);

        // ---- S = Q K^T (Q from resident smem) ----
        float sc[8][4];
#pragma unroll
        for (int n = 0; n < 8; n++)
#pragma unroll
            for (int j = 0; j < 4; j++) sc[n][j] = 0.f;

#pragma unroll
        for (int kt = 0; kt < 8; kt++) {
            uint32_t qh_[4];
            ldx4(qh_, sb + swz(qrow, 2 * kt + qc));
#pragma unroll
            for (int j = 0; j < 4; j++) {
                uint32_t kh_[4];
                ldx4(kh_, stb + swz(16 * j + krow_in, 2 * kt + kc));
                mma_f16(sc[2 * j + 0], qh_, kh_[0], kh_[1]);
                mma_f16(sc[2 * j + 1], qh_, kh_[2], kh_[3]);
            }
        }

        // ---- mask + online softmax (base-2) ----
        float mx0 = m0r, mx1 = m1r;
#pragma unroll
        for (int n = 0; n < 8; n++) {
            const uint32_t wa = (n < 4) ? w0.x : w0.y;
            const uint32_t wb = (n < 4) ? w1.x : w1.y;
            const int pos = (n & 3) * 8 + mc0;
            sc[n][0] = ((wa >> pos) & 1u)       ? sc[n][0] : -1e30f;
            sc[n][1] = ((wa >> (pos + 1)) & 1u) ? sc[n][1] : -1e30f;
            sc[n][2] = ((wb >> pos) & 1u)       ? sc[n][2] : -1e30f;
            sc[n][3] = ((wb >> (pos + 1)) & 1u) ? sc[n][3] : -1e30f;
            mx0 = fmaxf(mx0, fmaxf(sc[n][0], sc[n][1]));
            mx1 = fmaxf(mx1, fmaxf(sc[n][2], sc[n][3]));
        }
        mx0 = fmaxf(mx0, __shfl_xor_sync(0xffffffffu, mx0, 1));
        mx0 = fmaxf(mx0, __shfl_xor_sync(0xffffffffu, mx0, 2));
        mx1 = fmaxf(mx1, __shfl_xor_sync(0xffffffffu, mx1, 1));
        mx1 = fmaxf(mx1, __shfl_xor_sync(0xffffffffu, mx1, 2));

        const float alpha0 = ex2f(m0r - mx0);
        const float alpha1 = ex2f(m1r - mx1);
        m0r = mx0; m1r = mx1;

        float rs0 = 0.f, rs1 = 0.f;
#pragma unroll
        for (int n = 0; n < 8; n++) {
            sc[n][0] = ex2f(sc[n][0] - mx0);
            sc[n][1] = ex2f(sc[n][1] - mx0);
            sc[n][2] = ex2f(sc[n][2] - mx1);
            sc[n][3] = ex2f(sc[n][3] - mx1);
            rs0 += sc[n][0] + sc[n][1];
            rs1 += sc[n][2] + sc[n][3];
        }
        rs0 += __shfl_xor_sync(0xffffffffu, rs0, 1);
        rs0 += __shfl_xor_sync(0xffffffffu, rs0, 2);
        rs1 += __shfl_xor_sync(0xffffffffu, rs1, 1);
        rs1 += __shfl_xor_sync(0xffffffffu, rs1, 2);
        l0r = l0r * alpha0 + rs0;
        l1r = l1r * alpha1 + rs1;

        // ---- pack P; rescale O ----
        uint32_t pah[4][4];
#pragma unroll
        for (int kt = 0; kt < 4; kt++) {
            pah[kt][0] = packh_hi(sc[2 * kt][0],     sc[2 * kt][1]);
            pah[kt][1] = packh_hi(sc[2 * kt][2],     sc[2 * kt][3]);
            pah[kt][2] = packh_hi(sc[2 * kt + 1][0], sc[2 * kt + 1][1]);
            pah[kt][3] = packh_hi(sc[2 * kt + 1][2], sc[2 * kt + 1][3]);
        }
#pragma unroll
        for (int n = 0; n < 16; n++) {
            oc[n][0] *= alpha0; oc[n][1] *= alpha0;
            oc[n][2] *= alpha1; oc[n][3] *= alpha1;
        }

        // ---- O += P @ V ----
#pragma unroll
        for (int kt = 0; kt < 4; kt++) {
#pragma unroll
            for (int np = 0; np < 8; np++) {
                uint32_t v_[4];
                ldx4t(v_, stb + 16384 + swz(16 * kt + vrow_in, 2 * np + vc));
                mma_f16(oc[2 * np + 0], pah[kt], v_[0], v_[1]);
                mma_f16(oc[2 * np + 1], pah[kt], v_[2], v_[3]);
            }
        }
    }

    // ---- normalize, write fp16 ----
    const float rl0 = 1.0f / l0r;
    const float rl1 = 1.0f / l1r;
    const size_t rbase0 = (size_t)(b * NQ + q0 + r0l) * CC + h * DH;
    const size_t rbase1 = rbase0 + (size_t)8 * CC;
#pragma unroll
    for (int n = 0; n < 16; n++) {
        const int c = n * 8 + mc0;
        *(uint32_t*)(Oh + rbase0 + c) = packh_hi(oc[n][0] * rl0, oc[n][1] * rl0);
        *(uint32_t*)(Oh + rbase1 + c) = packh_hi(oc[n][2] * rl1, oc[n][3] * rl1);
    }
}

// ---------------------------------------------------------------------------
extern "C" void kernel_launch(void* const* d_in, const int* in_sizes, int n_in,
                              void* d_out, int out_size)
{
    const float* query  = (const float*)d_in[0];
    const float* memory = (const float*)d_in[1];
    const float* mask   = (const float*)d_in[2];
    const float* Wq = (const float*)d_in[3];
    const float* bq = (const float*)d_in[4];
    const float* Wk = (const float*)d_in[5];
    const float* bk = (const float*)d_in[6];
    const float* Wv = (const float*)d_in[7];
    const float* bv = (const float*)d_in[8];
    const float* Wo = (const float*)d_in[9];
    const float* bo = (const float*)d_in[10];
    float* out = (float*)d_out;

    f16 *qin_h, *mem_h, *wq_h, *wk_h, *wv_h, *wo_h;
    f16 *q_h, *k_h, *v_h, *a_h;
    uint32_t* mb;
    cudaGetSymbolAddress((void**)&qin_h, s_qin_h);
    cudaGetSymbolAddress((void**)&mem_h, s_mem_h);
    cudaGetSymbolAddress((void**)&wq_h, s_wq_h);
    cudaGetSymbolAddress((void**)&wk_h, s_wk_h);
    cudaGetSymbolAddress((void**)&wv_h, s_wv_h);
    cudaGetSymbolAddress((void**)&wo_h, s_wo_h);
    cudaGetSymbolAddress((void**)&q_h, s_q_h);
    cudaGetSymbolAddress((void**)&k_h, s_k_h);
    cudaGetSymbolAddress((void**)&v_h, s_v_h);
    cudaGetSymbolAddress((void**)&a_h, s_a_h);
    cudaGetSymbolAddress((void**)&mb, s_mbits);

    cudaFuncSetAttribute(gemm_f16,
                         cudaFuncAttributeMaxDynamicSharedMemorySize, GEMM_SMEM);
    cudaFuncSetAttribute(flash_attn_tc7,
                         cudaFuncAttributeMaxDynamicSharedMemorySize, FLASH_SMEM);

    // side stream + fork/join events (created once; identical captured work
    // every call — only the handles persist)
    static cudaStream_t s2 = nullptr;
    static cudaEvent_t ev_fork = nullptr, ev_join = nullptr;
    if (!s2) {
        cudaStreamCreateWithFlags(&s2, cudaStreamNonBlocking);
        cudaEventCreateWithFlags(&ev_fork, cudaEventDisableTiming);
        cudaEventCreateWithFlags(&ev_join, cudaEventDisableTiming);
    }

    dim3 blk(256);
    const float scale = 0.08838834764831845f * 1.4426950408889634f;

    // ---- fork: mask_bits on side stream (DRAM-bound; overlaps GEMMs) ----
    cudaEventRecord(ev_fork, 0);
    cudaStreamWaitEvent(s2, ev_fork, 0);
    {
        const int nwords = BB * NQ * HW / 32;
        mask_bits<<<(nwords + 255) / 256, blk, 0, s2>>>(mask, mb, nwords);
    }
    cudaEventRecord(ev_join, s2);

    // ---- fused rounds (main stream) ----
    round_all<<<(N4P_TOTAL + 255) / 256, blk>>>(
        query, qin_h, memory, mem_h,
        Wq, wq_h, Wk, wk_h, Wv, wv_h, Wo, wo_h);

    // ---- projections ----
    gemm_f16<<<dim3(CC / 128, (BB * NQ) / 128), blk, GEMM_SMEM>>>(
        qin_h, wq_h, bq, nullptr, q_h, scale);
    gemm_f16<<<dim3(CC / 128, (BB * HW) / 128), blk, GEMM_SMEM>>>(
        mem_h, wk_h, bk, nullptr, k_h, 1.0f);
    gemm_f16<<<dim3(CC / 128, (BB * HW) / 128), blk, GEMM_SMEM>>>(
        mem_h, wv_h, bv, nullptr, v_h, 1.0f);

    // ---- join: mask bitmap must be ready before flash ----
    cudaStreamWaitEvent(0, ev_join, 0);

    // ---- attention ----
    flash_attn_tc7<<<dim3(NQ / 128, HH, BB), blk, FLASH_SMEM>>>(
        q_h, k_h, v_h, mb, a_h);

    // ---- output projection ----
    gemm_f16<<<dim3(CC / 128, (BB * NQ) / 128), blk, GEMM_SMEM>>>(
        a_h, wo_h, bo, out, nullptr, 1.0f);
}

// round 14
// speedup vs baseline: 7.7202x; 1.0160x over previous
#include <cuda_runtime.h>
#include <cuda_fp16.h>
#include <math.h>
#include <stdint.h>

#define BB 4
#define NQ 1024
#define HW 4096
#define CC 1024
#define HH 8
#define DH 128

typedef __half f16;

// ---------------- scratch (device globals; no allocations allowed) ----------
__device__ f16 s_qin_h[(size_t)BB * NQ * CC];
__device__ f16 s_mem_h[(size_t)BB * HW * CC];
__device__ f16 s_wq_h[(size_t)CC * CC];
__device__ f16 s_wk_h[(size_t)CC * CC];
__device__ f16 s_wv_h[(size_t)CC * CC];
__device__ f16 s_wo_h[(size_t)CC * CC];
__device__ f16 s_q_h[(size_t)BB * NQ * CC];
__device__ f16 s_k_h[(size_t)BB * HW * CC];
__device__ f16 s_v_h[(size_t)BB * HW * CC];
__device__ f16 s_a_h[(size_t)BB * NQ * CC];
__device__ uint32_t s_mbits[(size_t)BB * NQ * HW / 32];

// ============================ helpers =======================================
__device__ __forceinline__ uint32_t smem_u32(const void* p) {
    uint32_t a;
    asm("{ .reg .u64 t; cvta.to.shared.u64 t, %1; cvt.u32.u64 %0, t; }"
        : "=r"(a) : "l"(p));
    return a;
}

__device__ __forceinline__ void ldx4(uint32_t* r, uint32_t addr) {
    asm volatile("ldmatrix.sync.aligned.m8n8.x4.shared.b16 {%0,%1,%2,%3}, [%4];"
                 : "=r"(r[0]), "=r"(r[1]), "=r"(r[2]), "=r"(r[3]) : "r"(addr));
}

__device__ __forceinline__ void ldx4t(uint32_t* r, uint32_t addr) {
    asm volatile("ldmatrix.sync.aligned.m8n8.x4.trans.shared.b16 {%0,%1,%2,%3}, [%4];"
                 : "=r"(r[0]), "=r"(r[1]), "=r"(r[2]), "=r"(r[3]) : "r"(addr));
}

__device__ __forceinline__ void mma_f16(float* c, const uint32_t* a,
                                        uint32_t b0, uint32_t b1) {
    asm volatile(
        "mma.sync.aligned.m16n8k16.row.col.f32.f16.f16.f32 "
        "{%0,%1,%2,%3}, {%4,%5,%6,%7}, {%8,%9}, {%0,%1,%2,%3};"
        : "+f"(c[0]), "+f"(c[1]), "+f"(c[2]), "+f"(c[3])
        : "r"(a[0]), "r"(a[1]), "r"(a[2]), "r"(a[3]), "r"(b0), "r"(b1));
}

__device__ __forceinline__ void cpa16(uint32_t dst, const void* src) {
    asm volatile("cp.async.cg.shared.global [%0], [%1], 16;"
                 :: "r"(dst), "l"(src) : "memory");
}
#define CP_COMMIT() asm volatile("cp.async.commit_group;" ::: "memory")
#define CP_WAIT0()  asm volatile("cp.async.wait_group 0;" ::: "memory")
#define CP_WAIT1()  asm volatile("cp.async.wait_group 1;" ::: "memory")

__device__ __forceinline__ uint32_t packh_hi(float x, float y) {
    __half2 h = __floats2half2_rn(x, y);
    return *(uint32_t*)&h;
}

__device__ __forceinline__ float ex2f(float x) {
    float y;
    asm("ex2.approx.ftz.f32 %0, %1;" : "=f"(y) : "f"(x));
    return y;
}

__device__ __forceinline__ uint32_t swz(int row, int chunk) {
    return (uint32_t)(row * 256 + ((chunk ^ (row & 7)) << 4));
}
__device__ __forceinline__ uint32_t swz128(int row, int chunk) {
    return (uint32_t)(row * 128 + ((chunk ^ (row & 7)) << 4));
}

// ============================================================================
// prep kernels (unchanged from R13)
// ============================================================================
#define N4P_Q (BB * NQ * CC / 8)
#define N4P_M (BB * HW * CC / 8)
#define N4P_W (CC * CC / 8)
#define N4P_TOTAL (N4P_Q + N4P_M + 4 * N4P_W)

__global__ __launch_bounds__(256)
void round_all(const float* __restrict__ q,  f16* __restrict__ qo,
               const float* __restrict__ m,  f16* __restrict__ mo,
               const float* __restrict__ w0, f16* __restrict__ o0,
               const float* __restrict__ w1, f16* __restrict__ o1,
               const float* __restrict__ w2, f16* __restrict__ o2,
               const float* __restrict__ w3, f16* __restrict__ o3)
{
    size_t p = (size_t)blockIdx.x * blockDim.x + threadIdx.x;
    if (p >= (size_t)N4P_TOTAL) return;
    const float* x;
    f16* y;
    size_t off;
    if (p < N4P_Q) {
        x = q; y = qo; off = p;
    } else if (p < (size_t)N4P_Q + N4P_M) {
        x = m; y = mo; off = p - N4P_Q;
    } else {
        size_t r = p - N4P_Q - N4P_M;
        int ws = (int)(r / N4P_W);
        off = r % N4P_W;
        x = (ws == 0) ? w0 : (ws == 1) ? w1 : (ws == 2) ? w2 : w3;
        y = (ws == 0) ? o0 : (ws == 1) ? o1 : (ws == 2) ? o2 : o3;
    }
    const size_t i = off * 2;
    float4 v0 = ((const float4*)x)[i];
    float4 v1 = ((const float4*)x)[i + 1];
    __half2 a0 = __floats2half2_rn(v0.x, v0.y);
    __half2 a1 = __floats2half2_rn(v0.z, v0.w);
    __half2 a2 = __floats2half2_rn(v1.x, v1.y);
    __half2 a3 = __floats2half2_rn(v1.z, v1.w);
    ((uint4*)y)[off] = make_uint4(*(uint32_t*)&a0, *(uint32_t*)&a1,
                                  *(uint32_t*)&a2, *(uint32_t*)&a3);
}

__global__ __launch_bounds__(256)
void mask_bits(const float* __restrict__ m, uint32_t* __restrict__ out, int nwords)
{
    int w = blockIdx.x * blockDim.x + threadIdx.x;
    if (w >= nwords) return;
    const float4* p = (const float4*)(m + (size_t)w * 32);
    float4 v[8];
#pragma unroll
    for (int j = 0; j < 8; j++) v[j] = p[j];
    uint32_t bits = 0;
#pragma unroll
    for (int j = 0; j < 8; j++) {
        bits |= (v[j].x >= 0.5f ? (1u << (j * 4 + 0)) : 0u);
        bits |= (v[j].y >= 0.5f ? (1u << (j * 4 + 1)) : 0u);
        bits |= (v[j].z >= 0.5f ? (1u << (j * 4 + 2)) : 0u);
        bits |= (v[j].w >= 0.5f ? (1u << (j * 4 + 3)) : 0u);
    }
    out[w] = bits;
}

// ============================================================================
// GEMM v3: 512 threads, 16 warps (4m x 4n), warp tile 32x32.
// CTA 128x128, BK=64, 3-stage cp.async, 2 CTAs/SM (8 warps/SMSP).
// acc = 32 regs/thread -> ptxas has room to hoist LDSMs; latency hidden by
// 8-deep warp rotation. Same K-order per accumulator: bitwise-identical output.
// ============================================================================
#define GSTG 32768
#define GEMM_SMEM (3 * GSTG)
#define GNS (CC / 64)

__global__ __launch_bounds__(512, 2)
void gemm_f16(const f16* __restrict__ A, const f16* __restrict__ B,
              const float* __restrict__ bias,
              float* __restrict__ Yf, f16* __restrict__ Yh, float scale)
{
    extern __shared__ char sm[];
    const uint32_t sb = smem_u32(sm);

    const int tid  = threadIdx.x;
    const int wid  = tid >> 5;
    const int lane = tid & 31;
    const int wm = wid & 3;          // warp m (x32)
    const int wn = wid >> 2;         // warp n (x32)
    const int m0 = blockIdx.y * 128;
    const int n0 = blockIdx.x * 128;

    // loader: 512 threads, 2 chunks A + 2 chunks B each per stage
    const int lrow = tid >> 2;           // 0..127
    const int lcb  = (tid & 3) * 2;      // chunk base 0,2,4,6

    const f16* Ap = A + (size_t)(m0 + lrow) * CC;
    const f16* Bp = B + (size_t)(n0 + lrow) * CC;

    float acc[2][4][4];
#pragma unroll
    for (int i = 0; i < 2; i++)
#pragma unroll
        for (int j = 0; j < 4; j++)
#pragma unroll
            for (int k = 0; k < 4; k++) acc[i][j][k] = 0.f;

    const int krow_in = ((lane >> 4) & 1) * 8 + (lane & 7);
    const int kc      = (lane >> 3) & 1;
    const int arow    = wm * 32 + (lane & 15);
    const int ac      = lane >> 4;

    auto issue = [&](int s) {
        const uint32_t stb = sb + (uint32_t)((s % 3) * GSTG);
        const int ko = s * 64;
#pragma unroll
        for (int c = 0; c < 2; c++) {
            const int ch = lcb + c;
            const uint32_t so = swz128(lrow, ch);
            cpa16(stb + so,         Ap + ko + ch * 8);
            cpa16(stb + 16384 + so, Bp + ko + ch * 8);
        }
    };

    issue(0); CP_COMMIT();
    issue(1); CP_COMMIT();

    for (int s = 0; s < GNS; s++) {
        CP_WAIT1();
        __syncthreads();
        if (s + 2 < GNS) issue(s + 2);
        CP_COMMIT();

        const uint32_t stb = sb + (uint32_t)((s % 3) * GSTG);
#pragma unroll
        for (int kt = 0; kt < 4; kt++) {
            uint32_t a_[2][4];
#pragma unroll
            for (int mt = 0; mt < 2; mt++)
                ldx4(a_[mt], stb + swz128(arow + mt * 16, 2 * kt + ac));
            uint32_t b_[2][4];
#pragma unroll
            for (int nh = 0; nh < 2; nh++)
                ldx4(b_[nh], stb + 16384 +
                             swz128(wn * 32 + nh * 16 + krow_in, 2 * kt + kc));
#pragma unroll
            for (int mt = 0; mt < 2; mt++) {
#pragma unroll
                for (int nh = 0; nh < 2; nh++) {
                    mma_f16(acc[mt][2 * nh + 0], a_[mt], b_[nh][0], b_[nh][1]);
                    mma_f16(acc[mt][2 * nh + 1], a_[mt], b_[nh][2], b_[nh][3]);
                }
            }
        }
    }

    // ---- epilogue ----
#pragma unroll
    for (int mt = 0; mt < 2; mt++) {
        const int r0 = m0 + wm * 32 + mt * 16 + (lane >> 2);
#pragma unroll
        for (int nt = 0; nt < 4; nt++) {
            const int c = n0 + wn * 32 + nt * 8 + (lane & 3) * 2;
            float2 bv = *(const float2*)(bias + c);
            float y00 = acc[mt][nt][0] + bv.x;
            float y01 = acc[mt][nt][1] + bv.y;
            float y10 = acc[mt][nt][2] + bv.x;
            float y11 = acc[mt][nt][3] + bv.y;
            if (Yf) {
                *(float2*)(Yf + (size_t)r0 * CC + c)       = make_float2(y00, y01);
                *(float2*)(Yf + (size_t)(r0 + 8) * CC + c) = make_float2(y10, y11);
            } else {
                y00 *= scale; y01 *= scale; y10 *= scale; y11 *= scale;
                *(uint32_t*)(Yh + (size_t)r0 * CC + c)       = packh_hi(y00, y01);
                *(uint32_t*)(Yh + (size_t)(r0 + 8) * CC + c) = packh_hi(y10, y11);
            }
        }
    }
}

// ============================================================================
// Flash attention v7 (unchanged from R12/R13)
// ============================================================================
#define KVSTG 32768
#define QRGN  32768
#define FLASH_SMEM (QRGN + 2 * KVSTG)
#define NKV (HW / 64)

__global__ __launch_bounds__(256, 2)
void flash_attn_tc7(const f16* __restrict__ Qh,
                    const f16* __restrict__ Kh, const f16* __restrict__ Vh,
                    const uint32_t* __restrict__ Mb, f16* __restrict__ Oh)
{
    extern __shared__ char sm[];
    const uint32_t sb = smem_u32(sm);

    const int tid  = threadIdx.x;
    const int wid  = tid >> 5;
    const int lane = tid & 31;
    const int q0 = blockIdx.x * 128;
    const int h  = blockIdx.y;
    const int b  = blockIdx.z;

    {
        const int row = tid >> 1;
        const int cb  = (tid & 1) * 8;
        const f16* qsrc = Qh + (size_t)(b * NQ + q0 + row) * CC + h * DH;
#pragma unroll
        for (int c = 0; c < 8; c++) {
            const int ch = cb + c;
            cpa16(sb + swz(row, ch), qsrc + ch * 8);
        }
        CP_COMMIT();
    }

    const int qrow = 16 * wid + (lane & 15);
    const int qc   = lane >> 4;

    const int krow_in = ((lane >> 4) & 1) * 8 + (lane & 7);
    const int kc      = (lane >> 3) & 1;
    const int vrow_in = (lane & 7) + ((lane >> 3) & 1) * 8;
    const int vc      = lane >> 4;

    const int kvrow = tid >> 2;
    const int kvcb  = (tid & 3) * 4;

    const f16* khb = Kh + (size_t)(b * HW + kvrow) * CC + h * DH;
    const f16* vhb = Vh + (size_t)(b * HW + kvrow) * CC + h * DH;

    const int r0l = 16 * wid + (lane >> 2);
    const int mc0 = 2 * (lane & 3);
    const uint32_t* mrow0 = Mb + (size_t)(b * NQ + q0 + r0l) * (HW / 32);
    const uint32_t* mrow1 = mrow0 + (size_t)8 * (HW / 32);

    auto issue = [&](int i) {
        const uint32_t stb = sb + QRGN + (uint32_t)((i & 1) * KVSTG);
        const size_t koff = (size_t)(i * 64) * CC;
#pragma unroll
        for (int c = 0; c < 4; c++) {
            const int ch = kvcb + c;
            const uint32_t so = swz(kvrow, ch);
            cpa16(stb + so,         khb + koff + ch * 8);
            cpa16(stb + 16384 + so, vhb + koff + ch * 8);
        }
    };

    float m0r = -1e30f, m1r = -1e30f, l0r = 0.f, l1r = 0.f;
    float oc[16][4];
#pragma unroll
    for (int n = 0; n < 16; n++)
#pragma unroll
        for (int j = 0; j < 4; j++) oc[n][j] = 0.f;

    issue(0); CP_COMMIT();

    for (int i = 0; i < NKV; i++) {
        CP_WAIT0();
        __syncthreads();
        if (i + 1 < NKV) issue(i + 1);
        CP_COMMIT();

        const uint32_t stb = sb + QRGN + (uint32_t)((i & 1) * KVSTG);

        const uint2 w0 = *(const uint2*)(mrow0 + i * 2);
        const uint2 w1 = *(const uint2*)(mrow1 + i * 2);

        float sc[8][4];
#pragma unroll
        for (int n = 0; n < 8; n++)
#pragma unroll
            for (int j = 0; j < 4; j++) sc[n][j] = 0.f;

#pragma unroll
        for (int kt = 0; kt < 8; kt++) {
            uint32_t qh_[4];
            ldx4(qh_, sb + swz(qrow, 2 * kt + qc));
#pragma unroll
            for (int j = 0; j < 4; j++) {
                uint32_t kh_[4];
                ldx4(kh_, stb + swz(16 * j + krow_in, 2 * kt + kc));
                mma_f16(sc[2 * j + 0], qh_, kh_[0], kh_[1]);
                mma_f16(sc[2 * j + 1], qh_, kh_[2], kh_[3]);
            }
        }

        float mx0 = m0r, mx1 = m1r;
#pragma unroll
        for (int n = 0; n < 8; n++) {
            const uint32_t wa = (n < 4) ? w0.x : w0.y;
            const uint32_t wb = (n < 4) ? w1.x : w1.y;
            const int pos = (n & 3) * 8 + mc0;
            sc[n][0] = ((wa >> pos) & 1u)       ? sc[n][0] : -1e30f;
            sc[n][1] = ((wa >> (pos + 1)) & 1u) ? sc[n][1] : -1e30f;
            sc[n][2] = ((wb >> pos) & 1u)       ? sc[n][2] : -1e30f;
            sc[n][3] = ((wb >> (pos + 1)) & 1u) ? sc[n][3] : -1e30f;
            mx0 = fmaxf(mx0, fmaxf(sc[n][0], sc[n][1]));
            mx1 = fmaxf(mx1, fmaxf(sc[n][2], sc[n][3]));
        }
        mx0 = fmaxf(mx0, __shfl_xor_sync(0xffffffffu, mx0, 1));
        mx0 = fmaxf(mx0, __shfl_xor_sync(0xffffffffu, mx0, 2));
        mx1 = fmaxf(mx1, __shfl_xor_sync(0xffffffffu, mx1, 1));
        mx1 = fmaxf(mx1, __shfl_xor_sync(0xffffffffu, mx1, 2));

        const float alpha0 = ex2f(m0r - mx0);
        const float alpha1 = ex2f(m1r - mx1);
        m0r = mx0; m1r = mx1;

        float rs0 = 0.f, rs1 = 0.f;
#pragma unroll
        for (int n = 0; n < 8; n++) {
            sc[n][0] = ex2f(sc[n][0] - mx0);
            sc[n][1] = ex2f(sc[n][1] - mx0);
            sc[n][2] = ex2f(sc[n][2] - mx1);
            sc[n][3] = ex2f(sc[n][3] - mx1);
            rs0 += sc[n][0] + sc[n][1];
            rs1 += sc[n][2] + sc[n][3];
        }
        rs0 += __shfl_xor_sync(0xffffffffu, rs0, 1);
        rs0 += __shfl_xor_sync(0xffffffffu, rs0, 2);
        rs1 += __shfl_xor_sync(0xffffffffu, rs1, 1);
        rs1 += __shfl_xor_sync(0xffffffffu, rs1, 2);
        l0r = l0r * alpha0 + rs0;
        l1r = l1r * alpha1 + rs1;

        uint32_t pah[4][4];
#pragma unroll
        for (int kt = 0; kt < 4; kt++) {
            pah[kt][0] = packh_hi(sc[2 * kt][0],     sc[2 * kt][1]);
            pah[kt][1] = packh_hi(sc[2 * kt][2],     sc[2 * kt][3]);
            pah[kt][2] = packh_hi(sc[2 * kt + 1][0], sc[2 * kt + 1][1]);
            pah[kt][3] = packh_hi(sc[2 * kt + 1][2], sc[2 * kt + 1][3]);
        }
#pragma unroll
        for (int n = 0; n < 16; n++) {
            oc[n][0] *= alpha0; oc[n][1] *= alpha0;
            oc[n][2] *= alpha1; oc[n][3] *= alpha1;
        }

#pragma unroll
        for (int kt = 0; kt < 4; kt++) {
#pragma unroll
            for (int np = 0; np < 8; np++) {
                uint32_t v_[4];
                ldx4t(v_, stb + 16384 + swz(16 * kt + vrow_in, 2 * np + vc));
                mma_f16(oc[2 * np + 0], pah[kt], v_[0], v_[1]);
                mma_f16(oc[2 * np + 1], pah[kt], v_[2], v_[3]);
            }
        }
    }

    const float rl0 = 1.0f / l0r;
    const float rl1 = 1.0f / l1r;
    const size_t rbase0 = (size_t)(b * NQ + q0 + r0l) * CC + h * DH;
    const size_t rbase1 = rbase0 + (size_t)8 * CC;
#pragma unroll
    for (int n = 0; n < 16; n++) {
        const int c = n * 8 + mc0;
        *(uint32_t*)(Oh + rbase0 + c) = packh_hi(oc[n][0] * rl0, oc[n][1] * rl0);
        *(uint32_t*)(Oh + rbase1 + c) = packh_hi(oc[n][2] * rl1, oc[n][3] * rl1);
    }
}

// ---------------------------------------------------------------------------
extern "C" void kernel_launch(void* const* d_in, const int* in_sizes, int n_in,
                              void* d_out, int out_size)
{
    const float* query  = (const float*)d_in[0];
    const float* memory = (const float*)d_in[1];
    const float* mask   = (const float*)d_in[2];
    const float* Wq = (const float*)d_in[3];
    const float* bq = (const float*)d_in[4];
    const float* Wk = (const float*)d_in[5];
    const float* bk = (const float*)d_in[6];
    const float* Wv = (const float*)d_in[7];
    const float* bv = (const float*)d_in[8];
    const float* Wo = (const float*)d_in[9];
    const float* bo = (const float*)d_in[10];
    float* out = (float*)d_out;

    f16 *qin_h, *mem_h, *wq_h, *wk_h, *wv_h, *wo_h;
    f16 *q_h, *k_h, *v_h, *a_h;
    uint32_t* mb;
    cudaGetSymbolAddress((void**)&qin_h, s_qin_h);
    cudaGetSymbolAddress((void**)&mem_h, s_mem_h);
    cudaGetSymbolAddress((void**)&wq_h, s_wq_h);
    cudaGetSymbolAddress((void**)&wk_h, s_wk_h);
    cudaGetSymbolAddress((void**)&wv_h, s_wv_h);
    cudaGetSymbolAddress((void**)&wo_h, s_wo_h);
    cudaGetSymbolAddress((void**)&q_h, s_q_h);
    cudaGetSymbolAddress((void**)&k_h, s_k_h);
    cudaGetSymbolAddress((void**)&v_h, s_v_h);
    cudaGetSymbolAddress((void**)&a_h, s_a_h);
    cudaGetSymbolAddress((void**)&mb, s_mbits);

    cudaFuncSetAttribute(gemm_f16,
                         cudaFuncAttributeMaxDynamicSharedMemorySize, GEMM_SMEM);
    cudaFuncSetAttribute(flash_attn_tc7,
                         cudaFuncAttributeMaxDynamicSharedMemorySize, FLASH_SMEM);

    static cudaStream_t s2 = nullptr;
    static cudaEvent_t ev_fork = nullptr, ev_join = nullptr;
    if (!s2) {
        cudaStreamCreateWithFlags(&s2, cudaStreamNonBlocking);
        cudaEventCreateWithFlags(&ev_fork, cudaEventDisableTiming);
        cudaEventCreateWithFlags(&ev_join, cudaEventDisableTiming);
    }

    dim3 blk(256);
    dim3 blk512(512);
    const float scale = 0.08838834764831845f * 1.4426950408889634f;

    // ---- fork: mask_bits on side stream ----
    cudaEventRecord(ev_fork, 0);
    cudaStreamWaitEvent(s2, ev_fork, 0);
    {
        const int nwords = BB * NQ * HW / 32;
        mask_bits<<<(nwords + 255) / 256, blk, 0, s2>>>(mask, mb, nwords);
    }
    cudaEventRecord(ev_join, s2);

    // ---- fused rounds ----
    round_all<<<(N4P_TOTAL + 255) / 256, blk>>>(
        query, qin_h, memory, mem_h,
        Wq, wq_h, Wk, wk_h, Wv, wv_h, Wo, wo_h);

    // ---- projections (512-thread GEMM v3) ----
    gemm_f16<<<dim3(CC / 128, (BB * NQ) / 128), blk512, GEMM_SMEM>>>(
        qin_h, wq_h, bq, nullptr, q_h, scale);
    gemm_f16<<<dim3(CC / 128, (BB * HW) / 128), blk512, GEMM_SMEM>>>(
        mem_h, wk_h, bk, nullptr, k_h, 1.0f);
    gemm_f16<<<dim3(CC / 128, (BB * HW) / 128), blk512, GEMM_SMEM>>>(
        mem_h, wv_h, bv, nullptr, v_h, 1.0f);

    // ---- join: mask bitmap ready before flash ----
    cudaStreamWaitEvent(0, ev_join, 0);

    // ---- attention ----
    flash_attn_tc7<<<dim3(NQ / 128, HH, BB), blk, FLASH_SMEM>>>(
        q_h, k_h, v_h, mb, a_h);

    // ---- output projection ----
    gemm_f16<<<dim3(CC / 128, (BB * NQ) / 128), blk512, GEMM_SMEM>>>(
        a_h, wo_h, bo, out, nullptr, 1.0f);
}